// round 3
// baseline (speedup 1.0000x reference)
#include <cuda_runtime.h>
#include <math.h>

#define B_    8
#define T_    512
#define F_    229
#define C1_   48
#define C3_   96
#define FP1_  114
#define FP2_  57
#define DC_   768
#define FCIN_ 5472
#define G4_   3072
#define K1P_  1024
#define K2_   1536
#define NP_   88
#define MALL_ 4096
#define NBLK_ 148

// ---------------- device scratch (no allocations allowed) ----------------
__device__ float g_conv1[B_*C1_*T_*F_];
__device__ float g_conv2[B_*C1_*T_*FP1_];
__device__ float g_Amat[MALL_*FCIN_];
__device__ float g_ac[MALL_*DC_];
__device__ float g_pre[MALL_*G4_];
__device__ float g_W1r[G4_*K1P_];
__device__ float g_W2r[G4_*K2_];
__device__ float g_Wpre[G4_*DC_];
__device__ float g_bpre[G4_];
__device__ float g_b2v[G4_];
__device__ float g_wf1[C1_*9],      g_bf1[C1_];
__device__ float g_wf2[C1_*C1_*9],  g_bf2[C1_];
__device__ float g_wf3[C3_*C1_*9],  g_bf3[C3_];
__device__ float g_h1[2][B_][DC_], g_h2[2][B_][DC_];
__device__ float g_c1[B_][DC_],    g_c2[B_][DC_];
__device__ int   g_prev[B_][NP_];
__device__ unsigned g_bar_count;
__device__ volatile unsigned g_bar_gen;

// ---------------- prep: fold BN, reorder LSTM weights, zero state ----------------
__global__ void prep_kernel(
    const float* __restrict__ c1w, const float* __restrict__ c1b,
    const float* __restrict__ b1g, const float* __restrict__ b1b,
    const float* __restrict__ b1m, const float* __restrict__ b1v,
    const float* __restrict__ c2w, const float* __restrict__ c2b,
    const float* __restrict__ b2g, const float* __restrict__ b2b,
    const float* __restrict__ b2m, const float* __restrict__ b2v,
    const float* __restrict__ c3w, const float* __restrict__ c3b,
    const float* __restrict__ b3g, const float* __restrict__ b3b,
    const float* __restrict__ b3m, const float* __restrict__ b3v,
    const float* __restrict__ wih1, const float* __restrict__ whh1,
    const float* __restrict__ bih1, const float* __restrict__ bhh1,
    const float* __restrict__ wih2, const float* __restrict__ whh2,
    const float* __restrict__ bih2, const float* __restrict__ bhh2)
{
    const int st = gridDim.x * blockDim.x;
    const int t0 = blockIdx.x * blockDim.x + threadIdx.x;
    const float eps = 1e-5f;

    for (int i = t0; i < C1_*9; i += st) { int c = i/9;        g_wf1[i] = c1w[i] * (b1g[c]*rsqrtf(b1v[c]+eps)); }
    for (int i = t0; i < C1_;  i += st)  g_bf1[i] = (c1b[i]-b1m[i])*(b1g[i]*rsqrtf(b1v[i]+eps)) + b1b[i];
    for (int i = t0; i < C1_*C1_*9; i += st) { int c = i/(C1_*9); g_wf2[i] = c2w[i] * (b2g[c]*rsqrtf(b2v[c]+eps)); }
    for (int i = t0; i < C1_;  i += st)  g_bf2[i] = (c2b[i]-b2m[i])*(b2g[i]*rsqrtf(b2v[i]+eps)) + b2b[i];
    for (int i = t0; i < C3_*C1_*9; i += st) { int c = i/(C1_*9); g_wf3[i] = c3w[i] * (b3g[c]*rsqrtf(b3v[c]+eps)); }
    for (int i = t0; i < C3_;  i += st)  g_bf3[i] = (c3b[i]-b3m[i])*(b3g[i]*rsqrtf(b3v[i]+eps)) + b3b[i];

    // W1r: rows n = cell*4+g  <-  orig row g*768+cell ; cols [0,176)=wih1 emb part, [176,944)=whh1, [944,1024)=0
    for (int i = t0; i < G4_*K1P_; i += st) {
        int n = i >> 10, k = i & (K1P_-1);
        int m = n >> 2, g = n & 3, orig = g*DC_ + m;
        float v = 0.f;
        if (k < 176)       v = wih1[orig*944 + 768 + k];
        else if (k < 944)  v = whh1[orig*DC_ + (k - 176)];
        g_W1r[i] = v;
    }
    // W2r: cols [0,768)=wih2, [768,1536)=whh2
    for (int i = t0; i < G4_*K2_; i += st) {
        int n = i / K2_, k = i - n*K2_;
        int m = n >> 2, g = n & 3, orig = g*DC_ + m;
        g_W2r[i] = (k < DC_) ? wih2[orig*DC_ + k] : whh2[orig*DC_ + (k - DC_)];
    }
    // Wpre: acoustic part of wih1, reordered rows
    for (int i = t0; i < G4_*DC_; i += st) {
        int n = i / DC_, k = i - n*DC_;
        int m = n >> 2, g = n & 3, orig = g*DC_ + m;
        g_Wpre[i] = wih1[orig*944 + k];
    }
    for (int i = t0; i < G4_; i += st) {
        int m = i >> 2, g = i & 3, orig = g*DC_ + m;
        g_bpre[i] = bih1[orig] + bhh1[orig];
        g_b2v[i]  = bih2[orig] + bhh2[orig];
    }
    // zero AR state (buffers [0]; [1] is written before first read)
    for (int i = t0; i < B_*DC_; i += st) {
        (&g_h1[0][0][0])[i] = 0.f;
        (&g_h2[0][0][0])[i] = 0.f;
        (&g_c1[0][0])[i]    = 0.f;
        (&g_c2[0][0])[i]    = 0.f;
    }
    for (int i = t0; i < B_*NP_; i += st) (&g_prev[0][0])[i] = 0;
}

// ---------------- conv1: 1 -> 48, 3x3 SAME, BN folded, ReLU ----------------
__global__ void conv1_kernel(const float* __restrict__ mel)
{
    int t = blockIdx.x, b = blockIdx.y, f = threadIdx.x;
    __shared__ float ws[C1_*9];
    __shared__ float bs[C1_];
    for (int i = threadIdx.x; i < C1_*9; i += 256) ws[i] = g_wf1[i];
    for (int i = threadIdx.x; i < C1_;  i += 256) bs[i] = g_bf1[i];
    __syncthreads();
    if (f >= F_) return;

    float x[9];
#pragma unroll
    for (int dt = 0; dt < 3; dt++)
#pragma unroll
        for (int df = 0; df < 3; df++) {
            int tt = t - 1 + dt, ff = f - 1 + df;
            x[dt*3+df] = (tt >= 0 && tt < T_ && ff >= 0 && ff < F_)
                         ? mel[(b*T_ + tt)*F_ + ff] : 0.f;
        }
    for (int c = 0; c < C1_; c++) {
        float a = bs[c];
#pragma unroll
        for (int k = 0; k < 9; k++) a += ws[c*9+k] * x[k];
        g_conv1[((b*C1_ + c)*T_ + t)*F_ + f] = fmaxf(a, 0.f);
    }
}

// ---------------- conv2: 48 -> 48, 3x3 SAME, ReLU, maxpool F/2 ----------------
__global__ __launch_bounds__(256) void conv2_kernel()
{
    int t0 = blockIdx.x * 4, b = blockIdx.y, ch = blockIdx.z;
    int f = threadIdx.x;
    __shared__ float ws[8*C1_*9];
    __shared__ float ys[4][232];
    for (int i = threadIdx.x; i < 8*C1_*9; i += 256) ws[i] = g_wf2[ch*8*C1_*9 + i];
    __syncthreads();

    float acc[8][4];
#pragma unroll
    for (int cc = 0; cc < 8; cc++) {
        float bv = g_bf2[ch*8 + cc];
#pragma unroll
        for (int tt = 0; tt < 4; tt++) acc[cc][tt] = bv;
    }
    if (f < F_) {
        for (int ci = 0; ci < C1_; ci++) {
            const float* base = g_conv1 + ((b*C1_ + ci)*T_)*F_;
            float xr[6][3];
#pragma unroll
            for (int j = 0; j < 6; j++) {
                int tt = t0 - 1 + j;
#pragma unroll
                for (int d = 0; d < 3; d++) {
                    int ff = f - 1 + d;
                    xr[j][d] = (tt >= 0 && tt < T_ && ff >= 0 && ff < F_)
                               ? base[tt*F_ + ff] : 0.f;
                }
            }
#pragma unroll
            for (int cc = 0; cc < 8; cc++) {
                const float* w = &ws[(cc*C1_ + ci)*9];
                float w0=w[0],w1=w[1],w2=w[2],w3=w[3],w4=w[4],w5=w[5],w6=w[6],w7=w[7],w8=w[8];
#pragma unroll
                for (int tt = 0; tt < 4; tt++) {
                    acc[cc][tt] += w0*xr[tt  ][0] + w1*xr[tt  ][1] + w2*xr[tt  ][2]
                                 + w3*xr[tt+1][0] + w4*xr[tt+1][1] + w5*xr[tt+1][2]
                                 + w6*xr[tt+2][0] + w7*xr[tt+2][1] + w8*xr[tt+2][2];
                }
            }
        }
    }
    for (int cc = 0; cc < 8; cc++) {
        __syncthreads();
        if (f < F_) {
#pragma unroll
            for (int tt = 0; tt < 4; tt++) ys[tt][f] = fmaxf(acc[cc][tt], 0.f);
        }
        __syncthreads();
        if (f < FP1_) {
            int c = ch*8 + cc;
#pragma unroll
            for (int tt = 0; tt < 4; tt++)
                g_conv2[((b*C1_ + c)*T_ + t0 + tt)*FP1_ + f] =
                    fmaxf(ys[tt][2*f], ys[tt][2*f+1]);
        }
    }
}

// ---------------- conv3: 48 -> 96, 3x3 SAME, ReLU, maxpool, write A matrix ----------------
__global__ __launch_bounds__(128) void conv3_kernel()
{
    int t0 = blockIdx.x * 4, b = blockIdx.y, ch = blockIdx.z;
    int f = threadIdx.x;
    __shared__ float ws[8*C1_*9];
    __shared__ float ys[4][116];
    for (int i = threadIdx.x; i < 8*C1_*9; i += 128) ws[i] = g_wf3[ch*8*C1_*9 + i];
    __syncthreads();

    float acc[8][4];
#pragma unroll
    for (int cc = 0; cc < 8; cc++) {
        float bv = g_bf3[ch*8 + cc];
#pragma unroll
        for (int tt = 0; tt < 4; tt++) acc[cc][tt] = bv;
    }
    if (f < FP1_) {
        for (int ci = 0; ci < C1_; ci++) {
            const float* base = g_conv2 + ((b*C1_ + ci)*T_)*FP1_;
            float xr[6][3];
#pragma unroll
            for (int j = 0; j < 6; j++) {
                int tt = t0 - 1 + j;
#pragma unroll
                for (int d = 0; d < 3; d++) {
                    int ff = f - 1 + d;
                    xr[j][d] = (tt >= 0 && tt < T_ && ff >= 0 && ff < FP1_)
                               ? base[tt*FP1_ + ff] : 0.f;
                }
            }
#pragma unroll
            for (int cc = 0; cc < 8; cc++) {
                const float* w = &ws[(cc*C1_ + ci)*9];
                float w0=w[0],w1=w[1],w2=w[2],w3=w[3],w4=w[4],w5=w[5],w6=w[6],w7=w[7],w8=w[8];
#pragma unroll
                for (int tt = 0; tt < 4; tt++) {
                    acc[cc][tt] += w0*xr[tt  ][0] + w1*xr[tt  ][1] + w2*xr[tt  ][2]
                                 + w3*xr[tt+1][0] + w4*xr[tt+1][1] + w5*xr[tt+1][2]
                                 + w6*xr[tt+2][0] + w7*xr[tt+2][1] + w8*xr[tt+2][2];
                }
            }
        }
    }
    for (int cc = 0; cc < 8; cc++) {
        __syncthreads();
        if (f < FP1_) {
#pragma unroll
            for (int tt = 0; tt < 4; tt++) ys[tt][f] = fmaxf(acc[cc][tt], 0.f);
        }
        __syncthreads();
        if (f < FP2_) {
            int c = ch*8 + cc;
#pragma unroll
            for (int tt = 0; tt < 4; tt++)
                g_Amat[(b*T_ + t0 + tt)*FCIN_ + c*FP2_ + f] =
                    fmaxf(ys[tt][2*f], ys[tt][2*f+1]);
        }
    }
}

// ---------------- GEMM: C[M,N] = A[M,K] * B[N,K]^T + bias[N]  (all row-major) ----------------
__global__ __launch_bounds__(256) void gemm_tn(
    const float* __restrict__ A, const float* __restrict__ Bm,
    const float* __restrict__ bias, float* __restrict__ C,
    int M, int N, int K)
{
    __shared__ float As[16][68];
    __shared__ float Bs[16][68];
    int tid = threadIdx.x;
    int tx = tid & 15, ty = tid >> 4;
    int m0 = blockIdx.y * 64, n0 = blockIdx.x * 64;
    int lr = tid >> 2, lk = (tid & 3) * 4;
    float acc[4][4] = {};

    const float* Ap = A + (size_t)(m0 + lr)*K + lk;
    const float* Bp = Bm + (size_t)(n0 + lr)*K + lk;

    for (int k0 = 0; k0 < K; k0 += 16) {
        float4 a  = *(const float4*)(Ap + k0);
        float4 bb = *(const float4*)(Bp + k0);
        As[lk  ][lr] = a.x;  As[lk+1][lr] = a.y;  As[lk+2][lr] = a.z;  As[lk+3][lr] = a.w;
        Bs[lk  ][lr] = bb.x; Bs[lk+1][lr] = bb.y; Bs[lk+2][lr] = bb.z; Bs[lk+3][lr] = bb.w;
        __syncthreads();
#pragma unroll
        for (int kk = 0; kk < 16; kk++) {
            float4 av = *(const float4*)&As[kk][ty*4];
            float4 bv = *(const float4*)&Bs[kk][tx*4];
            float aa[4] = {av.x, av.y, av.z, av.w};
            float bbv[4] = {bv.x, bv.y, bv.z, bv.w};
#pragma unroll
            for (int i = 0; i < 4; i++)
#pragma unroll
                for (int j = 0; j < 4; j++)
                    acc[i][j] += aa[i] * bbv[j];
        }
        __syncthreads();
    }
#pragma unroll
    for (int i = 0; i < 4; i++)
#pragma unroll
        for (int j = 0; j < 4; j++)
            C[(size_t)(m0 + ty*4 + i)*N + n0 + tx*4 + j] = acc[i][j] + bias[n0 + tx*4 + j];
}

// ---------------- AR persistent kernel ----------------
__device__ __forceinline__ float warp_sum(float s)
{
    s += __shfl_xor_sync(0xffffffffu, s, 16);
    s += __shfl_xor_sync(0xffffffffu, s, 8);
    s += __shfl_xor_sync(0xffffffffu, s, 4);
    s += __shfl_xor_sync(0xffffffffu, s, 2);
    s += __shfl_xor_sync(0xffffffffu, s, 1);
    return s;
}
__device__ __forceinline__ float sigm(float x) { return 1.f / (1.f + expf(-x)); }

__device__ __forceinline__ void grid_bar()
{
    __syncthreads();
    if (threadIdx.x == 0) {
        __threadfence();
        unsigned gen = g_bar_gen;
        if (atomicAdd(&g_bar_count, 1u) == gridDim.x - 1) {
            g_bar_count = 0;
            __threadfence();
            g_bar_gen = gen + 1;
        } else {
            while (g_bar_gen == gen) __nanosleep(64);
        }
        __threadfence();
    }
    __syncthreads();
}

template <int KP>
__device__ __forceinline__ void lstm_phase(
    const float* __restrict__ W, const float* xs,
    int gw, int lane, int t,
    const float* __restrict__ preb, bool per_sample,
    float (*cst)[DC_], float* hout)
{
    for (int cell = gw; cell < DC_; cell += NBLK_*8) {
        const float* Wb = W + (size_t)cell * 4 * KP;
        float acc[4][8];
#pragma unroll
        for (int r = 0; r < 4; r++)
#pragma unroll
            for (int b = 0; b < 8; b++) acc[r][b] = 0.f;

#pragma unroll 2
        for (int kb = 0; kb < KP; kb += 128) {
            float4 w0 = *(const float4*)(Wb          + kb + lane*4);
            float4 w1 = *(const float4*)(Wb +   KP   + kb + lane*4);
            float4 w2 = *(const float4*)(Wb + 2*KP   + kb + lane*4);
            float4 w3 = *(const float4*)(Wb + 3*KP   + kb + lane*4);
#pragma unroll
            for (int b = 0; b < 8; b++) {
                float4 x = *(const float4*)(xs + b*K2_ + kb + lane*4);
                acc[0][b] += w0.x*x.x + w0.y*x.y + w0.z*x.z + w0.w*x.w;
                acc[1][b] += w1.x*x.x + w1.y*x.y + w1.z*x.z + w1.w*x.w;
                acc[2][b] += w2.x*x.x + w2.y*x.y + w2.z*x.z + w2.w*x.w;
                acc[3][b] += w3.x*x.x + w3.y*x.y + w3.z*x.z + w3.w*x.w;
            }
        }
        float z[4];
#pragma unroll
        for (int r = 0; r < 4; r++)
#pragma unroll
            for (int b = 0; b < 8; b++) {
                float s = warp_sum(acc[r][b]);
                if (lane == b) z[r] = s;
            }
        if (lane < 8) {
            int b = lane;
#pragma unroll
            for (int r = 0; r < 4; r++)
                z[r] += per_sample ? preb[(size_t)(b*T_ + t)*G4_ + cell*4 + r]
                                   : preb[cell*4 + r];
            float co = cst[b][cell];
            float ig = sigm(z[0]), fg = sigm(z[1]);
            float gg = tanhf(z[2]), og = sigm(z[3]);
            float cn = fg*co + ig*gg;
            cst[b][cell] = cn;
            hout[b*DC_ + cell] = og * tanhf(cn);
        }
    }
}

__global__ __launch_bounds__(256, 1) void ar_kernel(
    const float* __restrict__ postw, const float* __restrict__ postb,
    const float* __restrict__ embw, float* __restrict__ out)
{
    extern __shared__ float xs[];      // 8 * 1536 floats
    int tid = threadIdx.x, lane = tid & 31, warp = tid >> 5;
    int gw = blockIdx.x * 8 + warp;

    for (int t = 0; t < T_; t++) {
        int rd = t & 1, wr = rd ^ 1;

        // ---- fill xs for LSTM1: [emb(176) | h1_old(768) | 0-pad(80)] ----
        for (int i = tid; i < B_*K1P_; i += 256) {
            int b = i >> 10, k = i & (K1P_-1);
            float v = 0.f;
            if (k < 176)       v = embw[__ldcg(&g_prev[b][k >> 1]) * 2 + (k & 1)];
            else if (k < 944)  v = __ldcg(&g_h1[rd][b][k - 176]);
            xs[b*K2_ + k] = v;
        }
        __syncthreads();
        lstm_phase<K1P_>(g_W1r, xs, gw, lane, t, g_pre, true, g_c1, &g_h1[wr][0][0]);
        grid_bar();

        // ---- fill xs for LSTM2: [h1_new(768) | h2_old(768)] ----
        for (int i = tid; i < B_*K2_; i += 256) {
            int b = i / K2_, k = i - b*K2_;
            xs[i] = (k < DC_) ? __ldcg(&g_h1[wr][b][k]) : __ldcg(&g_h2[rd][b][k - DC_]);
        }
        __syncthreads();
        lstm_phase<K2_>(g_W2r, xs, gw, lane, t, g_b2v, false, g_c2, &g_h2[wr][0][0]);
        grid_bar();

        // ---- fill xs for post: h2_new(768) ----
        for (int i = tid; i < B_*DC_; i += 256) {
            int b = i / DC_, k = i - b*DC_;
            xs[b*K2_ + k] = __ldcg(&g_h2[wr][b][k]);
        }
        __syncthreads();
        // post GEMV + argmax; warp task = (pitch, batch)
        for (int task = gw; task < NP_*B_; task += NBLK_*8) {
            int p = task >> 3, b = task & 7;
            const float* xb = xs + b*K2_;
            const float* Wp = postw + (size_t)p*5*DC_;
            float acc[5] = {0.f, 0.f, 0.f, 0.f, 0.f};
#pragma unroll 2
            for (int kb = 0; kb < DC_; kb += 128) {
                float4 x = *(const float4*)(xb + kb + lane*4);
#pragma unroll
                for (int s = 0; s < 5; s++) {
                    float4 w = *(const float4*)(Wp + s*DC_ + kb + lane*4);
                    acc[s] += w.x*x.x + w.y*x.y + w.z*x.z + w.w*x.w;
                }
            }
#pragma unroll
            for (int s = 0; s < 5; s++) acc[s] = warp_sum(acc[s]);
            if (lane == 0) {
                float* o = out + (size_t)(b*T_ + t)*440 + p*5;
                float best = -1e30f; int bi = 0;
#pragma unroll
                for (int s = 0; s < 5; s++) {
                    float v = acc[s] + postb[p*5 + s];
                    o[s] = v;
                    if (v > best) { best = v; bi = s; }
                }
                g_prev[b][p] = bi;
            }
        }
        grid_bar();
    }
}

// ---------------- launch ----------------
extern "C" void kernel_launch(void* const* d_in, const int* in_sizes, int n_in,
                              void* d_out, int out_size)
{
    const float* mel    = (const float*)d_in[0];
    const float* c1w    = (const float*)d_in[1];
    const float* c1b    = (const float*)d_in[2];
    const float* b1g    = (const float*)d_in[3];
    const float* b1b    = (const float*)d_in[4];
    const float* b1m    = (const float*)d_in[5];
    const float* b1v    = (const float*)d_in[6];
    const float* c2w    = (const float*)d_in[7];
    const float* c2b    = (const float*)d_in[8];
    const float* b2g    = (const float*)d_in[9];
    const float* b2b    = (const float*)d_in[10];
    const float* b2m    = (const float*)d_in[11];
    const float* b2v    = (const float*)d_in[12];
    const float* c3w    = (const float*)d_in[13];
    const float* c3b    = (const float*)d_in[14];
    const float* b3g    = (const float*)d_in[15];
    const float* b3b    = (const float*)d_in[16];
    const float* b3m    = (const float*)d_in[17];
    const float* b3v    = (const float*)d_in[18];
    const float* fc_w   = (const float*)d_in[19];
    const float* fc_b   = (const float*)d_in[20];
    const float* wih1   = (const float*)d_in[21];
    const float* whh1   = (const float*)d_in[22];
    const float* bih1   = (const float*)d_in[23];
    const float* bhh1   = (const float*)d_in[24];
    const float* wih2   = (const float*)d_in[25];
    const float* whh2   = (const float*)d_in[26];
    const float* bih2   = (const float*)d_in[27];
    const float* bhh2   = (const float*)d_in[28];
    const float* post_w = (const float*)d_in[29];
    const float* post_b = (const float*)d_in[30];
    const float* emb_w  = (const float*)d_in[31];

    prep_kernel<<<2048, 256>>>(c1w, c1b, b1g, b1b, b1m, b1v,
                               c2w, c2b, b2g, b2b, b2m, b2v,
                               c3w, c3b, b3g, b3b, b3m, b3v,
                               wih1, whh1, bih1, bhh1,
                               wih2, whh2, bih2, bhh2);

    conv1_kernel<<<dim3(T_, B_), 256>>>(mel);
    conv2_kernel<<<dim3(T_/4, B_, C1_/8), 256>>>();
    conv3_kernel<<<dim3(T_/4, B_, C3_/8), 128>>>();

    float *pA, *pAc, *pPre, *pWpre, *pBpre;
    cudaGetSymbolAddress((void**)&pA,    g_Amat);
    cudaGetSymbolAddress((void**)&pAc,   g_ac);
    cudaGetSymbolAddress((void**)&pPre,  g_pre);
    cudaGetSymbolAddress((void**)&pWpre, g_Wpre);
    cudaGetSymbolAddress((void**)&pBpre, g_bpre);

    // acoustic = A * fc_w^T + fc_b              (4096 x 768, K=5472)
    gemm_tn<<<dim3(DC_/64, MALL_/64), 256>>>(pA, fc_w, fc_b, pAc, MALL_, DC_, FCIN_);
    // pre = acoustic * Wpre^T + (bih1+bhh1)     (4096 x 3072, K=768)
    gemm_tn<<<dim3(G4_/64, MALL_/64), 256>>>(pAc, pWpre, pBpre, pPre, MALL_, G4_, DC_);

    ar_kernel<<<NBLK_, 256, B_*K2_*sizeof(float)>>>(post_w, post_b, emb_w, (float*)d_out);
}

// round 4
// speedup vs baseline: 1.0259x; 1.0259x over previous
#include <cuda_runtime.h>
#include <math.h>

#define B_    8
#define T_    512
#define F_    229
#define C1_   48
#define C3_   96
#define FP1_  114
#define FP2_  57
#define DC_   768
#define FCIN_ 5472
#define G4_   3072
#define K1P_  1024
#define K2_   1536
#define NP_   88
#define MALL_ 4096
#define NBLK_ 148

// ---------------- device scratch (no allocations allowed) ----------------
__device__ float g_conv1[B_*C1_*T_*F_];
__device__ float g_conv2[B_*C1_*T_*FP1_];
__device__ float g_Amat[MALL_*FCIN_];
__device__ float g_ac[MALL_*DC_];
__device__ float g_pre[MALL_*G4_];
__device__ float g_W1r[G4_*K1P_];
__device__ float g_W2r[G4_*K2_];
__device__ float g_Wpre[G4_*DC_];
__device__ float g_bpre[G4_];
__device__ float g_b2v[G4_];
__device__ float g_wf1[C1_*9],      g_bf1[C1_];
__device__ float g_wf2[C1_*C1_*9],  g_bf2[C1_];
__device__ float g_wf3[C3_*C1_*9],  g_bf3[C3_];
__device__ float g_h1[2][B_][DC_], g_h2[2][B_][DC_];
__device__ float g_c1[B_][DC_],    g_c2[B_][DC_];
__device__ int   g_prev[B_][NP_];
__device__ unsigned g_bar_count;
__device__ volatile unsigned g_bar_gen;

// ---------------- prep: fold BN, reorder LSTM weights, zero state ----------------
__global__ void prep_kernel(
    const float* __restrict__ c1w, const float* __restrict__ c1b,
    const float* __restrict__ b1g, const float* __restrict__ b1b,
    const float* __restrict__ b1m, const float* __restrict__ b1v,
    const float* __restrict__ c2w, const float* __restrict__ c2b,
    const float* __restrict__ b2g, const float* __restrict__ b2b,
    const float* __restrict__ b2m, const float* __restrict__ b2v,
    const float* __restrict__ c3w, const float* __restrict__ c3b,
    const float* __restrict__ b3g, const float* __restrict__ b3b,
    const float* __restrict__ b3m, const float* __restrict__ b3v,
    const float* __restrict__ wih1, const float* __restrict__ whh1,
    const float* __restrict__ bih1, const float* __restrict__ bhh1,
    const float* __restrict__ wih2, const float* __restrict__ whh2,
    const float* __restrict__ bih2, const float* __restrict__ bhh2)
{
    const int st = gridDim.x * blockDim.x;
    const int t0 = blockIdx.x * blockDim.x + threadIdx.x;
    const float eps = 1e-5f;

    for (int i = t0; i < C1_*9; i += st) { int c = i/9;        g_wf1[i] = c1w[i] * (b1g[c]*rsqrtf(b1v[c]+eps)); }
    for (int i = t0; i < C1_;  i += st)  g_bf1[i] = (c1b[i]-b1m[i])*(b1g[i]*rsqrtf(b1v[i]+eps)) + b1b[i];
    for (int i = t0; i < C1_*C1_*9; i += st) { int c = i/(C1_*9); g_wf2[i] = c2w[i] * (b2g[c]*rsqrtf(b2v[c]+eps)); }
    for (int i = t0; i < C1_;  i += st)  g_bf2[i] = (c2b[i]-b2m[i])*(b2g[i]*rsqrtf(b2v[i]+eps)) + b2b[i];
    for (int i = t0; i < C3_*C1_*9; i += st) { int c = i/(C1_*9); g_wf3[i] = c3w[i] * (b3g[c]*rsqrtf(b3v[c]+eps)); }
    for (int i = t0; i < C3_;  i += st)  g_bf3[i] = (c3b[i]-b3m[i])*(b3g[i]*rsqrtf(b3v[i]+eps)) + b3b[i];

    // W1r: rows n = cell*4+g  <-  orig row g*768+cell ; cols [0,176)=wih1 emb part, [176,944)=whh1, [944,1024)=0
    for (int i = t0; i < G4_*K1P_; i += st) {
        int n = i >> 10, k = i & (K1P_-1);
        int m = n >> 2, g = n & 3, orig = g*DC_ + m;
        float v = 0.f;
        if (k < 176)       v = wih1[orig*944 + 768 + k];
        else if (k < 944)  v = whh1[orig*DC_ + (k - 176)];
        g_W1r[i] = v;
    }
    // W2r: cols [0,768)=wih2, [768,1536)=whh2
    for (int i = t0; i < G4_*K2_; i += st) {
        int n = i / K2_, k = i - n*K2_;
        int m = n >> 2, g = n & 3, orig = g*DC_ + m;
        g_W2r[i] = (k < DC_) ? wih2[orig*DC_ + k] : whh2[orig*DC_ + (k - DC_)];
    }
    // Wpre: acoustic part of wih1, reordered rows
    for (int i = t0; i < G4_*DC_; i += st) {
        int n = i / DC_, k = i - n*DC_;
        int m = n >> 2, g = n & 3, orig = g*DC_ + m;
        g_Wpre[i] = wih1[orig*944 + k];
    }
    for (int i = t0; i < G4_; i += st) {
        int m = i >> 2, g = i & 3, orig = g*DC_ + m;
        g_bpre[i] = bih1[orig] + bhh1[orig];
        g_b2v[i]  = bih2[orig] + bhh2[orig];
    }
    // zero AR state (buffers [0]; [1] is written before first read)
    for (int i = t0; i < B_*DC_; i += st) {
        (&g_h1[0][0][0])[i] = 0.f;
        (&g_h2[0][0][0])[i] = 0.f;
        (&g_c1[0][0])[i]    = 0.f;
        (&g_c2[0][0])[i]    = 0.f;
    }
    for (int i = t0; i < B_*NP_; i += st) (&g_prev[0][0])[i] = 0;
}

// ---------------- conv1: 1 -> 48, 3x3 SAME, BN folded, ReLU ----------------
__global__ void conv1_kernel(const float* __restrict__ mel)
{
    int t = blockIdx.x, b = blockIdx.y, f = threadIdx.x;
    __shared__ float ws[C1_*9];
    __shared__ float bs[C1_];
    for (int i = threadIdx.x; i < C1_*9; i += 256) ws[i] = g_wf1[i];
    for (int i = threadIdx.x; i < C1_;  i += 256) bs[i] = g_bf1[i];
    __syncthreads();
    if (f >= F_) return;

    float x[9];
#pragma unroll
    for (int dt = 0; dt < 3; dt++)
#pragma unroll
        for (int df = 0; df < 3; df++) {
            int tt = t - 1 + dt, ff = f - 1 + df;
            x[dt*3+df] = (tt >= 0 && tt < T_ && ff >= 0 && ff < F_)
                         ? mel[(b*T_ + tt)*F_ + ff] : 0.f;
        }
    for (int c = 0; c < C1_; c++) {
        float a = bs[c];
#pragma unroll
        for (int k = 0; k < 9; k++) a += ws[c*9+k] * x[k];
        g_conv1[((b*C1_ + c)*T_ + t)*F_ + f] = fmaxf(a, 0.f);
    }
}

// ---------------- conv2: 48 -> 48, 3x3 SAME, ReLU, maxpool F/2 ----------------
__global__ __launch_bounds__(256) void conv2_kernel()
{
    int t0 = blockIdx.x * 4, b = blockIdx.y, ch = blockIdx.z;
    int f = threadIdx.x;
    __shared__ float ws[8*C1_*9];
    __shared__ float ys[4][232];
    for (int i = threadIdx.x; i < 8*C1_*9; i += 256) ws[i] = g_wf2[ch*8*C1_*9 + i];
    __syncthreads();

    float acc[8][4];
#pragma unroll
    for (int cc = 0; cc < 8; cc++) {
        float bv = g_bf2[ch*8 + cc];
#pragma unroll
        for (int tt = 0; tt < 4; tt++) acc[cc][tt] = bv;
    }
    if (f < F_) {
        for (int ci = 0; ci < C1_; ci++) {
            const float* base = g_conv1 + ((b*C1_ + ci)*T_)*F_;
            float xr[6][3];
#pragma unroll
            for (int j = 0; j < 6; j++) {
                int tt = t0 - 1 + j;
#pragma unroll
                for (int d = 0; d < 3; d++) {
                    int ff = f - 1 + d;
                    xr[j][d] = (tt >= 0 && tt < T_ && ff >= 0 && ff < F_)
                               ? base[tt*F_ + ff] : 0.f;
                }
            }
#pragma unroll
            for (int cc = 0; cc < 8; cc++) {
                const float* w = &ws[(cc*C1_ + ci)*9];
                float w0=w[0],w1=w[1],w2=w[2],w3=w[3],w4=w[4],w5=w[5],w6=w[6],w7=w[7],w8=w[8];
#pragma unroll
                for (int tt = 0; tt < 4; tt++) {
                    acc[cc][tt] += w0*xr[tt  ][0] + w1*xr[tt  ][1] + w2*xr[tt  ][2]
                                 + w3*xr[tt+1][0] + w4*xr[tt+1][1] + w5*xr[tt+1][2]
                                 + w6*xr[tt+2][0] + w7*xr[tt+2][1] + w8*xr[tt+2][2];
                }
            }
        }
    }
    for (int cc = 0; cc < 8; cc++) {
        __syncthreads();
        if (f < F_) {
#pragma unroll
            for (int tt = 0; tt < 4; tt++) ys[tt][f] = fmaxf(acc[cc][tt], 0.f);
        }
        __syncthreads();
        if (f < FP1_) {
            int c = ch*8 + cc;
#pragma unroll
            for (int tt = 0; tt < 4; tt++)
                g_conv2[((b*C1_ + c)*T_ + t0 + tt)*FP1_ + f] =
                    fmaxf(ys[tt][2*f], ys[tt][2*f+1]);
        }
    }
}

// ---------------- conv3: 48 -> 96, 3x3 SAME, ReLU, maxpool, write A matrix ----------------
__global__ __launch_bounds__(128) void conv3_kernel()
{
    int t0 = blockIdx.x * 4, b = blockIdx.y, ch = blockIdx.z;
    int f = threadIdx.x;
    __shared__ float ws[8*C1_*9];
    __shared__ float ys[4][116];
    for (int i = threadIdx.x; i < 8*C1_*9; i += 128) ws[i] = g_wf3[ch*8*C1_*9 + i];
    __syncthreads();

    float acc[8][4];
#pragma unroll
    for (int cc = 0; cc < 8; cc++) {
        float bv = g_bf3[ch*8 + cc];
#pragma unroll
        for (int tt = 0; tt < 4; tt++) acc[cc][tt] = bv;
    }
    if (f < FP1_) {
        for (int ci = 0; ci < C1_; ci++) {
            const float* base = g_conv2 + ((b*C1_ + ci)*T_)*FP1_;
            float xr[6][3];
#pragma unroll
            for (int j = 0; j < 6; j++) {
                int tt = t0 - 1 + j;
#pragma unroll
                for (int d = 0; d < 3; d++) {
                    int ff = f - 1 + d;
                    xr[j][d] = (tt >= 0 && tt < T_ && ff >= 0 && ff < FP1_)
                               ? base[tt*FP1_ + ff] : 0.f;
                }
            }
#pragma unroll
            for (int cc = 0; cc < 8; cc++) {
                const float* w = &ws[(cc*C1_ + ci)*9];
                float w0=w[0],w1=w[1],w2=w[2],w3=w[3],w4=w[4],w5=w[5],w6=w[6],w7=w[7],w8=w[8];
#pragma unroll
                for (int tt = 0; tt < 4; tt++) {
                    acc[cc][tt] += w0*xr[tt  ][0] + w1*xr[tt  ][1] + w2*xr[tt  ][2]
                                 + w3*xr[tt+1][0] + w4*xr[tt+1][1] + w5*xr[tt+1][2]
                                 + w6*xr[tt+2][0] + w7*xr[tt+2][1] + w8*xr[tt+2][2];
                }
            }
        }
    }
    for (int cc = 0; cc < 8; cc++) {
        __syncthreads();
        if (f < FP1_) {
#pragma unroll
            for (int tt = 0; tt < 4; tt++) ys[tt][f] = fmaxf(acc[cc][tt], 0.f);
        }
        __syncthreads();
        if (f < FP2_) {
            int c = ch*8 + cc;
#pragma unroll
            for (int tt = 0; tt < 4; tt++)
                g_Amat[(b*T_ + t0 + tt)*FCIN_ + c*FP2_ + f] =
                    fmaxf(ys[tt][2*f], ys[tt][2*f+1]);
        }
    }
}

// ---------------- GEMM: C[M,N] = A[M,K] * B[N,K]^T + bias[N] ----------------
// 128x128x16 tile, 256 threads, 8x8 micro-tile, double-buffered smem.
#define BM_ 128
#define BN_ 128
#define BK_ 16

__global__ __launch_bounds__(256) void gemm_tn(
    const float* __restrict__ A, const float* __restrict__ Bm,
    const float* __restrict__ bias, float* __restrict__ C,
    int M, int N, int K)
{
    __shared__ float As[2][BK_][BM_];
    __shared__ float Bs[2][BK_][BN_];

    const int tid = threadIdx.x;
    const int m0 = blockIdx.y * BM_, n0 = blockIdx.x * BN_;

    // load mapping: 64 rows x 4 k-quads per pass, two row-passes (r, r+64)
    const int lr = tid >> 2;
    const int lk = (tid & 3) * 4;
    const float* Ap = A + (size_t)(m0 + lr) * K + lk;
    const float* Bp = Bm + (size_t)(n0 + lr) * K + lk;
    const size_t rowK = (size_t)64 * K;

    // compute mapping: warps 4(M) x 2(N); lanes 4(M) x 8(N); 8x8 per thread
    const int warp = tid >> 5, lane = tid & 31;
    const int wm = warp & 3, wn = warp >> 2;
    const int lm = lane >> 3, ln = lane & 7;
    const int row0 = wm * 32 + lm * 8;
    const int col0 = wn * 64 + ln * 8;

    float acc[8][8];
#pragma unroll
    for (int i = 0; i < 8; i++)
#pragma unroll
        for (int j = 0; j < 8; j++) acc[i][j] = 0.f;

    // preload tile 0 into buffer 0
    {
        float4 a0 = *(const float4*)(Ap);
        float4 a1 = *(const float4*)(Ap + rowK);
        float4 b0 = *(const float4*)(Bp);
        float4 b1 = *(const float4*)(Bp + rowK);
        As[0][lk+0][lr] = a0.x; As[0][lk+1][lr] = a0.y; As[0][lk+2][lr] = a0.z; As[0][lk+3][lr] = a0.w;
        As[0][lk+0][lr+64] = a1.x; As[0][lk+1][lr+64] = a1.y; As[0][lk+2][lr+64] = a1.z; As[0][lk+3][lr+64] = a1.w;
        Bs[0][lk+0][lr] = b0.x; Bs[0][lk+1][lr] = b0.y; Bs[0][lk+2][lr] = b0.z; Bs[0][lk+3][lr] = b0.w;
        Bs[0][lk+0][lr+64] = b1.x; Bs[0][lk+1][lr+64] = b1.y; Bs[0][lk+2][lr+64] = b1.z; Bs[0][lk+3][lr+64] = b1.w;
    }
    __syncthreads();

    const int nkt = K >> 4;
    int cur = 0;
    for (int kt = 0; kt < nkt; kt++) {
        float4 pa0, pa1, pb0, pb1;
        const bool has = (kt + 1 < nkt);
        if (has) {
            int ko = (kt + 1) << 4;
            pa0 = *(const float4*)(Ap + ko);
            pa1 = *(const float4*)(Ap + rowK + ko);
            pb0 = *(const float4*)(Bp + ko);
            pb1 = *(const float4*)(Bp + rowK + ko);
        }
#pragma unroll
        for (int kk = 0; kk < BK_; kk++) {
            float4 av0 = *(const float4*)&As[cur][kk][row0];
            float4 av1 = *(const float4*)&As[cur][kk][row0 + 4];
            float4 bv0 = *(const float4*)&Bs[cur][kk][col0];
            float4 bv1 = *(const float4*)&Bs[cur][kk][col0 + 4];
            float a[8] = {av0.x, av0.y, av0.z, av0.w, av1.x, av1.y, av1.z, av1.w};
            float b[8] = {bv0.x, bv0.y, bv0.z, bv0.w, bv1.x, bv1.y, bv1.z, bv1.w};
#pragma unroll
            for (int i = 0; i < 8; i++)
#pragma unroll
                for (int j = 0; j < 8; j++)
                    acc[i][j] += a[i] * b[j];
        }
        if (has) {
            int nb = cur ^ 1;
            As[nb][lk+0][lr] = pa0.x; As[nb][lk+1][lr] = pa0.y; As[nb][lk+2][lr] = pa0.z; As[nb][lk+3][lr] = pa0.w;
            As[nb][lk+0][lr+64] = pa1.x; As[nb][lk+1][lr+64] = pa1.y; As[nb][lk+2][lr+64] = pa1.z; As[nb][lk+3][lr+64] = pa1.w;
            Bs[nb][lk+0][lr] = pb0.x; Bs[nb][lk+1][lr] = pb0.y; Bs[nb][lk+2][lr] = pb0.z; Bs[nb][lk+3][lr] = pb0.w;
            Bs[nb][lk+0][lr+64] = pb1.x; Bs[nb][lk+1][lr+64] = pb1.y; Bs[nb][lk+2][lr+64] = pb1.z; Bs[nb][lk+3][lr+64] = pb1.w;
        }
        __syncthreads();
        cur ^= 1;
    }

    float bv[8];
#pragma unroll
    for (int j = 0; j < 8; j++) bv[j] = bias[n0 + col0 + j];
#pragma unroll
    for (int i = 0; i < 8; i++) {
        float* Cp = C + (size_t)(m0 + row0 + i) * N + n0 + col0;
        float4 o0 = make_float4(acc[i][0]+bv[0], acc[i][1]+bv[1], acc[i][2]+bv[2], acc[i][3]+bv[3]);
        float4 o1 = make_float4(acc[i][4]+bv[4], acc[i][5]+bv[5], acc[i][6]+bv[6], acc[i][7]+bv[7]);
        *(float4*)(Cp)     = o0;
        *(float4*)(Cp + 4) = o1;
    }
}

// ---------------- AR persistent kernel ----------------
__device__ __forceinline__ float warp_sum(float s)
{
    s += __shfl_xor_sync(0xffffffffu, s, 16);
    s += __shfl_xor_sync(0xffffffffu, s, 8);
    s += __shfl_xor_sync(0xffffffffu, s, 4);
    s += __shfl_xor_sync(0xffffffffu, s, 2);
    s += __shfl_xor_sync(0xffffffffu, s, 1);
    return s;
}
__device__ __forceinline__ float sigm(float x) { return 1.f / (1.f + expf(-x)); }

__device__ __forceinline__ void grid_bar()
{
    __syncthreads();
    if (threadIdx.x == 0) {
        __threadfence();
        unsigned gen = g_bar_gen;
        if (atomicAdd(&g_bar_count, 1u) == gridDim.x - 1) {
            g_bar_count = 0;
            __threadfence();
            g_bar_gen = gen + 1;
        } else {
            while (g_bar_gen == gen) __nanosleep(32);
        }
        __threadfence();
    }
    __syncthreads();
}

template <int KP>
__device__ __forceinline__ void lstm_phase(
    const float* __restrict__ W, const float* xs,
    int gw, int lane, int t,
    const float* __restrict__ preb, bool per_sample,
    float (*cst)[DC_], float* hout)
{
    for (int cell = gw; cell < DC_; cell += NBLK_*8) {
        const float* Wb = W + (size_t)cell * 4 * KP;
        float acc[4][8];
#pragma unroll
        for (int r = 0; r < 4; r++)
#pragma unroll
            for (int b = 0; b < 8; b++) acc[r][b] = 0.f;

#pragma unroll 2
        for (int kb = 0; kb < KP; kb += 128) {
            float4 w0 = *(const float4*)(Wb          + kb + lane*4);
            float4 w1 = *(const float4*)(Wb +   KP   + kb + lane*4);
            float4 w2 = *(const float4*)(Wb + 2*KP   + kb + lane*4);
            float4 w3 = *(const float4*)(Wb + 3*KP   + kb + lane*4);
#pragma unroll
            for (int b = 0; b < 8; b++) {
                float4 x = *(const float4*)(xs + b*K2_ + kb + lane*4);
                acc[0][b] += w0.x*x.x + w0.y*x.y + w0.z*x.z + w0.w*x.w;
                acc[1][b] += w1.x*x.x + w1.y*x.y + w1.z*x.z + w1.w*x.w;
                acc[2][b] += w2.x*x.x + w2.y*x.y + w2.z*x.z + w2.w*x.w;
                acc[3][b] += w3.x*x.x + w3.y*x.y + w3.z*x.z + w3.w*x.w;
            }
        }
        float z[4];
#pragma unroll
        for (int r = 0; r < 4; r++)
#pragma unroll
            for (int b = 0; b < 8; b++) {
                float s = warp_sum(acc[r][b]);
                if (lane == b) z[r] = s;
            }
        if (lane < 8) {
            int b = lane;
#pragma unroll
            for (int r = 0; r < 4; r++)
                z[r] += per_sample ? preb[(size_t)(b*T_ + t)*G4_ + cell*4 + r]
                                   : preb[cell*4 + r];
            float co = cst[b][cell];
            float ig = sigm(z[0]), fg = sigm(z[1]);
            float gg = tanhf(z[2]), og = sigm(z[3]);
            float cn = fg*co + ig*gg;
            cst[b][cell] = cn;
            hout[b*DC_ + cell] = og * tanhf(cn);
        }
    }
}

__global__ __launch_bounds__(256, 1) void ar_kernel(
    const float* __restrict__ postw, const float* __restrict__ postb,
    const float* __restrict__ embw, float* __restrict__ out)
{
    extern __shared__ float xs[];      // 8 * 1536 floats
    int tid = threadIdx.x, lane = tid & 31, warp = tid >> 5;
    int gw = blockIdx.x * 8 + warp;

    for (int t = 0; t < T_; t++) {
        int rd = t & 1, wr = rd ^ 1;

        // ---- fill xs for LSTM1: [emb(176) | h1_old(768) | 0-pad(80)] ----
        for (int i = tid; i < B_*K1P_; i += 256) {
            int b = i >> 10, k = i & (K1P_-1);
            float v = 0.f;
            if (k < 176)       v = embw[__ldcg(&g_prev[b][k >> 1]) * 2 + (k & 1)];
            else if (k < 944)  v = __ldcg(&g_h1[rd][b][k - 176]);
            xs[b*K2_ + k] = v;
        }
        __syncthreads();
        lstm_phase<K1P_>(g_W1r, xs, gw, lane, t, g_pre, true, g_c1, &g_h1[wr][0][0]);
        grid_bar();

        // ---- fill xs for LSTM2: [h1_new(768) | h2_old(768)] ----
        for (int i = tid; i < B_*K2_; i += 256) {
            int b = i / K2_, k = i - b*K2_;
            xs[i] = (k < DC_) ? __ldcg(&g_h1[wr][b][k]) : __ldcg(&g_h2[rd][b][k - DC_]);
        }
        __syncthreads();
        lstm_phase<K2_>(g_W2r, xs, gw, lane, t, g_b2v, false, g_c2, &g_h2[wr][0][0]);
        grid_bar();

        // ---- fill xs for post: h2_new(768) ----
        for (int i = tid; i < B_*DC_; i += 256) {
            int b = i / DC_, k = i - b*DC_;
            xs[b*K2_ + k] = __ldcg(&g_h2[wr][b][k]);
        }
        __syncthreads();
        // post GEMV + argmax; warp task = (pitch, batch-half): 4 batches per warp
        for (int task = gw; task < NP_*2; task += NBLK_*8) {
            int p = task >> 1, bh = (task & 1) * 4;
            const float* Wp = postw + (size_t)p*5*DC_;
            float acc[5][4];
#pragma unroll
            for (int s = 0; s < 5; s++)
#pragma unroll
                for (int b = 0; b < 4; b++) acc[s][b] = 0.f;
#pragma unroll 2
            for (int kb = 0; kb < DC_; kb += 128) {
                float4 w[5];
#pragma unroll
                for (int s = 0; s < 5; s++)
                    w[s] = *(const float4*)(Wp + s*DC_ + kb + lane*4);
#pragma unroll
                for (int b = 0; b < 4; b++) {
                    float4 x = *(const float4*)(xs + (bh + b)*K2_ + kb + lane*4);
#pragma unroll
                    for (int s = 0; s < 5; s++)
                        acc[s][b] += w[s].x*x.x + w[s].y*x.y + w[s].z*x.z + w[s].w*x.w;
                }
            }
#pragma unroll
            for (int s = 0; s < 5; s++)
#pragma unroll
                for (int b = 0; b < 4; b++)
                    acc[s][b] = warp_sum(acc[s][b]);
            if (lane < 4) {
                int b = bh + lane;
                float* o = out + (size_t)(b*T_ + t)*440 + p*5;
                float best = -1e30f; int bi = 0;
#pragma unroll
                for (int s = 0; s < 5; s++) {
                    float v0 = (lane & 1) ? acc[s][1] : acc[s][0];
                    float v1 = (lane & 1) ? acc[s][3] : acc[s][2];
                    float v  = ((lane & 2) ? v1 : v0) + postb[p*5 + s];
                    o[s] = v;
                    if (v > best) { best = v; bi = s; }
                }
                g_prev[b][p] = bi;
            }
        }
        grid_bar();
    }
}

// ---------------- launch ----------------
extern "C" void kernel_launch(void* const* d_in, const int* in_sizes, int n_in,
                              void* d_out, int out_size)
{
    const float* mel    = (const float*)d_in[0];
    const float* c1w    = (const float*)d_in[1];
    const float* c1b    = (const float*)d_in[2];
    const float* b1g    = (const float*)d_in[3];
    const float* b1b    = (const float*)d_in[4];
    const float* b1m    = (const float*)d_in[5];
    const float* b1v    = (const float*)d_in[6];
    const float* c2w    = (const float*)d_in[7];
    const float* c2b    = (const float*)d_in[8];
    const float* b2g    = (const float*)d_in[9];
    const float* b2b    = (const float*)d_in[10];
    const float* b2m    = (const float*)d_in[11];
    const float* b2v    = (const float*)d_in[12];
    const float* c3w    = (const float*)d_in[13];
    const float* c3b    = (const float*)d_in[14];
    const float* b3g    = (const float*)d_in[15];
    const float* b3b    = (const float*)d_in[16];
    const float* b3m    = (const float*)d_in[17];
    const float* b3v    = (const float*)d_in[18];
    const float* fc_w   = (const float*)d_in[19];
    const float* fc_b   = (const float*)d_in[20];
    const float* wih1   = (const float*)d_in[21];
    const float* whh1   = (const float*)d_in[22];
    const float* bih1   = (const float*)d_in[23];
    const float* bhh1   = (const float*)d_in[24];
    const float* wih2   = (const float*)d_in[25];
    const float* whh2   = (const float*)d_in[26];
    const float* bih2   = (const float*)d_in[27];
    const float* bhh2   = (const float*)d_in[28];
    const float* post_w = (const float*)d_in[29];
    const float* post_b = (const float*)d_in[30];
    const float* emb_w  = (const float*)d_in[31];

    prep_kernel<<<2048, 256>>>(c1w, c1b, b1g, b1b, b1m, b1v,
                               c2w, c2b, b2g, b2b, b2m, b2v,
                               c3w, c3b, b3g, b3b, b3m, b3v,
                               wih1, whh1, bih1, bhh1,
                               wih2, whh2, bih2, bhh2);

    conv1_kernel<<<dim3(T_, B_), 256>>>(mel);
    conv2_kernel<<<dim3(T_/4, B_, C1_/8), 256>>>();
    conv3_kernel<<<dim3(T_/4, B_, C3_/8), 128>>>();

    float *pA, *pAc, *pPre, *pWpre, *pBpre;
    cudaGetSymbolAddress((void**)&pA,    g_Amat);
    cudaGetSymbolAddress((void**)&pAc,   g_ac);
    cudaGetSymbolAddress((void**)&pPre,  g_pre);
    cudaGetSymbolAddress((void**)&pWpre, g_Wpre);
    cudaGetSymbolAddress((void**)&pBpre, g_bpre);

    // acoustic = A * fc_w^T + fc_b              (4096 x 768, K=5472)
    gemm_tn<<<dim3(DC_/BN_, MALL_/BM_), 256>>>(pA, fc_w, fc_b, pAc, MALL_, DC_, FCIN_);
    // pre = acoustic * Wpre^T + (bih1+bhh1)     (4096 x 3072, K=768)
    gemm_tn<<<dim3(G4_/BN_, MALL_/BM_), 256>>>(pAc, pWpre, pBpre, pPre, MALL_, G4_, DC_);

    ar_kernel<<<NBLK_, 256, B_*K2_*sizeof(float)>>>(post_w, post_b, emb_w, (float*)d_out);
}

// round 5
// speedup vs baseline: 1.1970x; 1.1667x over previous
#include <cuda_runtime.h>
#include <math.h>

#define B_    8
#define T_    512
#define F_    229
#define C1_   48
#define C3_   96
#define FP1_  114
#define FP2_  57
#define DC_   768
#define FCIN_ 5472
#define G4_   3072
#define K1P_  1024
#define K2_   1536
#define NP_   88
#define MALL_ 4096
#define NB_AR 128

typedef unsigned long long u64t;

// ---------------- f32x2 helpers ----------------
__device__ __forceinline__ void fma2(u64t &acc, u64t a, u64t b) {
    asm("fma.rn.f32x2 %0, %1, %2, %0;" : "+l"(acc) : "l"(a), "l"(b));
}
__device__ __forceinline__ u64t pk2(float lo, float hi) {
    u64t r;
    asm("mov.b64 %0, {%1, %2};" : "=l"(r) : "r"(__float_as_uint(lo)), "r"(__float_as_uint(hi)));
    return r;
}
__device__ __forceinline__ float2 upk2(u64t v) {
    unsigned lo, hi;
    asm("mov.b64 {%0, %1}, %2;" : "=r"(lo), "=r"(hi) : "l"(v));
    return make_float2(__uint_as_float(lo), __uint_as_float(hi));
}
__device__ __forceinline__ float psum(u64t v) {
    float2 f = upk2(v);
    return f.x + f.y;
}

// ---------------- device scratch (no allocations allowed) ----------------
__device__ float g_conv1[B_*C1_*T_*F_];
__device__ float g_conv2[B_*C1_*T_*FP1_];
__device__ float g_Amat[MALL_*FCIN_];
__device__ float g_ac[MALL_*DC_];
__device__ float g_pre[MALL_*G4_];
__device__ float g_W1r[G4_*K1P_];
__device__ float g_W2r[G4_*K2_];
__device__ float g_Wpre[G4_*DC_];
__device__ float g_bpre[G4_];
__device__ float g_b2v[G4_];
__device__ float g_wf1[C1_*9],      g_bf1[C1_];
__device__ float g_wf2[C1_*C1_*9],  g_bf2[C1_];
__device__ float g_wf3[C3_*C1_*9],  g_bf3[C3_];
__device__ float g_h1[2][B_][DC_], g_h2[2][B_][DC_];
__device__ int   g_prev[B_][NP_];
__device__ volatile unsigned g_arr[NB_AR*32];
__device__ volatile unsigned g_rel;

// ---------------- prep: fold BN, reorder LSTM weights, zero state ----------------
__global__ void prep_kernel(
    const float* __restrict__ c1w, const float* __restrict__ c1b,
    const float* __restrict__ b1g, const float* __restrict__ b1b,
    const float* __restrict__ b1m, const float* __restrict__ b1v,
    const float* __restrict__ c2w, const float* __restrict__ c2b,
    const float* __restrict__ b2g, const float* __restrict__ b2b,
    const float* __restrict__ b2m, const float* __restrict__ b2v,
    const float* __restrict__ c3w, const float* __restrict__ c3b,
    const float* __restrict__ b3g, const float* __restrict__ b3b,
    const float* __restrict__ b3m, const float* __restrict__ b3v,
    const float* __restrict__ wih1, const float* __restrict__ whh1,
    const float* __restrict__ bih1, const float* __restrict__ bhh1,
    const float* __restrict__ wih2, const float* __restrict__ whh2,
    const float* __restrict__ bih2, const float* __restrict__ bhh2)
{
    const int st = gridDim.x * blockDim.x;
    const int t0 = blockIdx.x * blockDim.x + threadIdx.x;
    const float eps = 1e-5f;

    for (int i = t0; i < C1_*9; i += st) { int c = i/9;        g_wf1[i] = c1w[i] * (b1g[c]*rsqrtf(b1v[c]+eps)); }
    for (int i = t0; i < C1_;  i += st)  g_bf1[i] = (c1b[i]-b1m[i])*(b1g[i]*rsqrtf(b1v[i]+eps)) + b1b[i];
    for (int i = t0; i < C1_*C1_*9; i += st) { int c = i/(C1_*9); g_wf2[i] = c2w[i] * (b2g[c]*rsqrtf(b2v[c]+eps)); }
    for (int i = t0; i < C1_;  i += st)  g_bf2[i] = (c2b[i]-b2m[i])*(b2g[i]*rsqrtf(b2v[i]+eps)) + b2b[i];
    for (int i = t0; i < C3_*C1_*9; i += st) { int c = i/(C1_*9); g_wf3[i] = c3w[i] * (b3g[c]*rsqrtf(b3v[c]+eps)); }
    for (int i = t0; i < C3_;  i += st)  g_bf3[i] = (c3b[i]-b3m[i])*(b3g[i]*rsqrtf(b3v[i]+eps)) + b3b[i];

    // W1r: rows n = cell*4+g  <-  orig row g*768+cell ; cols [0,176)=wih1 emb part, [176,944)=whh1, [944,1024)=0
    for (int i = t0; i < G4_*K1P_; i += st) {
        int n = i >> 10, k = i & (K1P_-1);
        int m = n >> 2, g = n & 3, orig = g*DC_ + m;
        float v = 0.f;
        if (k < 176)       v = wih1[orig*944 + 768 + k];
        else if (k < 944)  v = whh1[orig*DC_ + (k - 176)];
        g_W1r[i] = v;
    }
    // W2r: cols [0,768)=wih2, [768,1536)=whh2
    for (int i = t0; i < G4_*K2_; i += st) {
        int n = i / K2_, k = i - n*K2_;
        int m = n >> 2, g = n & 3, orig = g*DC_ + m;
        g_W2r[i] = (k < DC_) ? wih2[orig*DC_ + k] : whh2[orig*DC_ + (k - DC_)];
    }
    // Wpre: acoustic part of wih1, reordered rows
    for (int i = t0; i < G4_*DC_; i += st) {
        int n = i / DC_, k = i - n*DC_;
        int m = n >> 2, g = n & 3, orig = g*DC_ + m;
        g_Wpre[i] = wih1[orig*944 + k];
    }
    for (int i = t0; i < G4_; i += st) {
        int m = i >> 2, g = i & 3, orig = g*DC_ + m;
        g_bpre[i] = bih1[orig] + bhh1[orig];
        g_b2v[i]  = bih2[orig] + bhh2[orig];
    }
    // zero AR state
    for (int i = t0; i < B_*DC_; i += st) {
        (&g_h1[0][0][0])[i] = 0.f;
        (&g_h2[0][0][0])[i] = 0.f;
    }
    for (int i = t0; i < B_*NP_; i += st) (&g_prev[0][0])[i] = 0;
    for (int i = t0; i < NB_AR; i += st) g_arr[i*32] = 0u;
    if (t0 == 0) g_rel = 0u;
}

// ---------------- conv1: 1 -> 48, 3x3 SAME, BN folded, ReLU ----------------
__global__ void conv1_kernel(const float* __restrict__ mel)
{
    int t = blockIdx.x, b = blockIdx.y, f = threadIdx.x;
    __shared__ float ws[C1_*9];
    __shared__ float bs[C1_];
    for (int i = threadIdx.x; i < C1_*9; i += 256) ws[i] = g_wf1[i];
    for (int i = threadIdx.x; i < C1_;  i += 256) bs[i] = g_bf1[i];
    __syncthreads();
    if (f >= F_) return;

    float x[9];
#pragma unroll
    for (int dt = 0; dt < 3; dt++)
#pragma unroll
        for (int df = 0; df < 3; df++) {
            int tt = t - 1 + dt, ff = f - 1 + df;
            x[dt*3+df] = (tt >= 0 && tt < T_ && ff >= 0 && ff < F_)
                         ? mel[(b*T_ + tt)*F_ + ff] : 0.f;
        }
    for (int c = 0; c < C1_; c++) {
        float a = bs[c];
#pragma unroll
        for (int k = 0; k < 9; k++) a += ws[c*9+k] * x[k];
        g_conv1[((b*C1_ + c)*T_ + t)*F_ + f] = fmaxf(a, 0.f);
    }
}

// ---------------- conv2: 48 -> 48, 3x3 SAME, ReLU, maxpool F/2 ----------------
__global__ __launch_bounds__(256) void conv2_kernel()
{
    int t0 = blockIdx.x * 4, b = blockIdx.y, ch = blockIdx.z;
    int f = threadIdx.x;
    __shared__ float ws[8*C1_*9];
    __shared__ float ys[4][232];
    for (int i = threadIdx.x; i < 8*C1_*9; i += 256) ws[i] = g_wf2[ch*8*C1_*9 + i];
    __syncthreads();

    float acc[8][4];
#pragma unroll
    for (int cc = 0; cc < 8; cc++) {
        float bv = g_bf2[ch*8 + cc];
#pragma unroll
        for (int tt = 0; tt < 4; tt++) acc[cc][tt] = bv;
    }
    if (f < F_) {
        for (int ci = 0; ci < C1_; ci++) {
            const float* base = g_conv1 + ((b*C1_ + ci)*T_)*F_;
            float xr[6][3];
#pragma unroll
            for (int j = 0; j < 6; j++) {
                int tt = t0 - 1 + j;
#pragma unroll
                for (int d = 0; d < 3; d++) {
                    int ff = f - 1 + d;
                    xr[j][d] = (tt >= 0 && tt < T_ && ff >= 0 && ff < F_)
                               ? base[tt*F_ + ff] : 0.f;
                }
            }
#pragma unroll
            for (int cc = 0; cc < 8; cc++) {
                const float* w = &ws[(cc*C1_ + ci)*9];
                float w0=w[0],w1=w[1],w2=w[2],w3=w[3],w4=w[4],w5=w[5],w6=w[6],w7=w[7],w8=w[8];
#pragma unroll
                for (int tt = 0; tt < 4; tt++) {
                    acc[cc][tt] += w0*xr[tt  ][0] + w1*xr[tt  ][1] + w2*xr[tt  ][2]
                                 + w3*xr[tt+1][0] + w4*xr[tt+1][1] + w5*xr[tt+1][2]
                                 + w6*xr[tt+2][0] + w7*xr[tt+2][1] + w8*xr[tt+2][2];
                }
            }
        }
    }
    for (int cc = 0; cc < 8; cc++) {
        __syncthreads();
        if (f < F_) {
#pragma unroll
            for (int tt = 0; tt < 4; tt++) ys[tt][f] = fmaxf(acc[cc][tt], 0.f);
        }
        __syncthreads();
        if (f < FP1_) {
            int c = ch*8 + cc;
#pragma unroll
            for (int tt = 0; tt < 4; tt++)
                g_conv2[((b*C1_ + c)*T_ + t0 + tt)*FP1_ + f] =
                    fmaxf(ys[tt][2*f], ys[tt][2*f+1]);
        }
    }
}

// ---------------- conv3: 48 -> 96, 3x3 SAME, ReLU, maxpool, write A matrix ----------------
__global__ __launch_bounds__(128) void conv3_kernel()
{
    int t0 = blockIdx.x * 4, b = blockIdx.y, ch = blockIdx.z;
    int f = threadIdx.x;
    __shared__ float ws[8*C1_*9];
    __shared__ float ys[4][116];
    for (int i = threadIdx.x; i < 8*C1_*9; i += 128) ws[i] = g_wf3[ch*8*C1_*9 + i];
    __syncthreads();

    float acc[8][4];
#pragma unroll
    for (int cc = 0; cc < 8; cc++) {
        float bv = g_bf3[ch*8 + cc];
#pragma unroll
        for (int tt = 0; tt < 4; tt++) acc[cc][tt] = bv;
    }
    if (f < FP1_) {
        for (int ci = 0; ci < C1_; ci++) {
            const float* base = g_conv2 + ((b*C1_ + ci)*T_)*FP1_;
            float xr[6][3];
#pragma unroll
            for (int j = 0; j < 6; j++) {
                int tt = t0 - 1 + j;
#pragma unroll
                for (int d = 0; d < 3; d++) {
                    int ff = f - 1 + d;
                    xr[j][d] = (tt >= 0 && tt < T_ && ff >= 0 && ff < FP1_)
                               ? base[tt*FP1_ + ff] : 0.f;
                }
            }
#pragma unroll
            for (int cc = 0; cc < 8; cc++) {
                const float* w = &ws[(cc*C1_ + ci)*9];
                float w0=w[0],w1=w[1],w2=w[2],w3=w[3],w4=w[4],w5=w[5],w6=w[6],w7=w[7],w8=w[8];
#pragma unroll
                for (int tt = 0; tt < 4; tt++) {
                    acc[cc][tt] += w0*xr[tt  ][0] + w1*xr[tt  ][1] + w2*xr[tt  ][2]
                                 + w3*xr[tt+1][0] + w4*xr[tt+1][1] + w5*xr[tt+1][2]
                                 + w6*xr[tt+2][0] + w7*xr[tt+2][1] + w8*xr[tt+2][2];
                }
            }
        }
    }
    for (int cc = 0; cc < 8; cc++) {
        __syncthreads();
        if (f < FP1_) {
#pragma unroll
            for (int tt = 0; tt < 4; tt++) ys[tt][f] = fmaxf(acc[cc][tt], 0.f);
        }
        __syncthreads();
        if (f < FP2_) {
            int c = ch*8 + cc;
#pragma unroll
            for (int tt = 0; tt < 4; tt++)
                g_Amat[(b*T_ + t0 + tt)*FCIN_ + c*FP2_ + f] =
                    fmaxf(ys[tt][2*f], ys[tt][2*f+1]);
        }
    }
}

// ---------------- GEMM: C[M,N] = A[M,K] * B[N,K]^T + bias[N] ----------------
// 128x128x16 tile, 256 threads, 8x8 micro-tile, double-buffered smem, f32x2 math.
#define BM_ 128
#define BN_ 128
#define BK_ 16

__global__ __launch_bounds__(256) void gemm_tn(
    const float* __restrict__ A, const float* __restrict__ Bm,
    const float* __restrict__ bias, float* __restrict__ C,
    int M, int N, int K)
{
    __shared__ float As[2][BK_][BM_];
    __shared__ float Bs[2][BK_][BN_];

    const int tid = threadIdx.x;
    const int m0 = blockIdx.y * BM_, n0 = blockIdx.x * BN_;

    const int lr = tid >> 2;
    const int lk = (tid & 3) * 4;
    const float* Ap = A + (size_t)(m0 + lr) * K + lk;
    const float* Bp = Bm + (size_t)(n0 + lr) * K + lk;
    const size_t rowK = (size_t)64 * K;

    const int warp = tid >> 5, lane = tid & 31;
    const int wm = warp & 3, wn = warp >> 2;
    const int lm = lane >> 3, ln = lane & 7;
    const int row0 = wm * 32 + lm * 8;
    const int col0 = wn * 64 + ln * 8;

    u64t acc2[8][4];
#pragma unroll
    for (int i = 0; i < 8; i++)
#pragma unroll
        for (int j = 0; j < 4; j++) acc2[i][j] = 0ull;

    {
        float4 a0 = *(const float4*)(Ap);
        float4 a1 = *(const float4*)(Ap + rowK);
        float4 b0 = *(const float4*)(Bp);
        float4 b1 = *(const float4*)(Bp + rowK);
        As[0][lk+0][lr] = a0.x; As[0][lk+1][lr] = a0.y; As[0][lk+2][lr] = a0.z; As[0][lk+3][lr] = a0.w;
        As[0][lk+0][lr+64] = a1.x; As[0][lk+1][lr+64] = a1.y; As[0][lk+2][lr+64] = a1.z; As[0][lk+3][lr+64] = a1.w;
        Bs[0][lk+0][lr] = b0.x; Bs[0][lk+1][lr] = b0.y; Bs[0][lk+2][lr] = b0.z; Bs[0][lk+3][lr] = b0.w;
        Bs[0][lk+0][lr+64] = b1.x; Bs[0][lk+1][lr+64] = b1.y; Bs[0][lk+2][lr+64] = b1.z; Bs[0][lk+3][lr+64] = b1.w;
    }
    __syncthreads();

    const int nkt = K >> 4;
    int cur = 0;
    for (int kt = 0; kt < nkt; kt++) {
        float4 pa0, pa1, pb0, pb1;
        const bool has = (kt + 1 < nkt);
        if (has) {
            int ko = (kt + 1) << 4;
            pa0 = *(const float4*)(Ap + ko);
            pa1 = *(const float4*)(Ap + rowK + ko);
            pb0 = *(const float4*)(Bp + ko);
            pb1 = *(const float4*)(Bp + rowK + ko);
        }
#pragma unroll
        for (int kk = 0; kk < BK_; kk++) {
            float4 av0 = *(const float4*)&As[cur][kk][row0];
            float4 av1 = *(const float4*)&As[cur][kk][row0 + 4];
            float4 bv0 = *(const float4*)&Bs[cur][kk][col0];
            float4 bv1 = *(const float4*)&Bs[cur][kk][col0 + 4];
            u64t b2[4];
            b2[0] = pk2(bv0.x, bv0.y); b2[1] = pk2(bv0.z, bv0.w);
            b2[2] = pk2(bv1.x, bv1.y); b2[3] = pk2(bv1.z, bv1.w);
            float a[8] = {av0.x, av0.y, av0.z, av0.w, av1.x, av1.y, av1.z, av1.w};
#pragma unroll
            for (int i = 0; i < 8; i++) {
                u64t ai = pk2(a[i], a[i]);
#pragma unroll
                for (int j = 0; j < 4; j++)
                    fma2(acc2[i][j], ai, b2[j]);
            }
        }
        if (has) {
            int nb = cur ^ 1;
            As[nb][lk+0][lr] = pa0.x; As[nb][lk+1][lr] = pa0.y; As[nb][lk+2][lr] = pa0.z; As[nb][lk+3][lr] = pa0.w;
            As[nb][lk+0][lr+64] = pa1.x; As[nb][lk+1][lr+64] = pa1.y; As[nb][lk+2][lr+64] = pa1.z; As[nb][lk+3][lr+64] = pa1.w;
            Bs[nb][lk+0][lr] = pb0.x; Bs[nb][lk+1][lr] = pb0.y; Bs[nb][lk+2][lr] = pb0.z; Bs[nb][lk+3][lr] = pb0.w;
            Bs[nb][lk+0][lr+64] = pb1.x; Bs[nb][lk+1][lr+64] = pb1.y; Bs[nb][lk+2][lr+64] = pb1.z; Bs[nb][lk+3][lr+64] = pb1.w;
        }
        __syncthreads();
        cur ^= 1;
    }

    float bv[8];
#pragma unroll
    for (int j = 0; j < 8; j++) bv[j] = bias[n0 + col0 + j];
#pragma unroll
    for (int i = 0; i < 8; i++) {
        float* Cp = C + (size_t)(m0 + row0 + i) * N + n0 + col0;
        float2 r0 = upk2(acc2[i][0]), r1 = upk2(acc2[i][1]);
        float2 r2 = upk2(acc2[i][2]), r3 = upk2(acc2[i][3]);
        float4 o0 = make_float4(r0.x+bv[0], r0.y+bv[1], r1.x+bv[2], r1.y+bv[3]);
        float4 o1 = make_float4(r2.x+bv[4], r2.y+bv[5], r3.x+bv[6], r3.y+bv[7]);
        *(float4*)(Cp)     = o0;
        *(float4*)(Cp + 4) = o1;
    }
}

// ---------------- AR persistent kernel ----------------
__device__ __forceinline__ float warp_sum(float s)
{
    s += __shfl_xor_sync(0xffffffffu, s, 16);
    s += __shfl_xor_sync(0xffffffffu, s, 8);
    s += __shfl_xor_sync(0xffffffffu, s, 4);
    s += __shfl_xor_sync(0xffffffffu, s, 2);
    s += __shfl_xor_sync(0xffffffffu, s, 1);
    return s;
}
__device__ __forceinline__ float sigm(float x) { return 1.f / (1.f + expf(-x)); }

__device__ __forceinline__ void grid_bar2(unsigned gen)
{
    __syncthreads();
    if (threadIdx.x == 0) {
        __threadfence();
        g_arr[blockIdx.x * 32] = gen;
    }
    if (blockIdx.x == 0) {
        if (threadIdx.x < NB_AR)
            while (g_arr[threadIdx.x * 32] != gen) { }
        __syncthreads();
        if (threadIdx.x == 0) { __threadfence(); g_rel = gen; }
    } else {
        if (threadIdx.x == 0)
            while (g_rel != gen) { }
    }
    __syncthreads();
}

// GEMV partial: warp = (cell_local, K-half). Results (after warp reduction)
// go to part[warp*32 + r*8+b].
template<int KP>
__device__ __forceinline__ void lstm_partial(
    const float* __restrict__ W, const float* xs,
    int warp, int lane, float* part)
{
    const int KH = KP / 2;
    const int cell = blockIdx.x * 6 + (warp >> 1);
    const int half = warp & 1;
    const float* Wb = W + (size_t)cell * 4 * KP + half * KH;
    const float* xb = xs + half * KH;

    u64t acc[4][8];
#pragma unroll
    for (int r = 0; r < 4; r++)
#pragma unroll
        for (int b = 0; b < 8; b++) acc[r][b] = 0ull;

#pragma unroll 2
    for (int kb = 0; kb < KH; kb += 128) {
        int off = kb + lane * 4;
        float4 w0 = *(const float4*)(Wb          + off);
        float4 w1 = *(const float4*)(Wb +   KP   + off);
        float4 w2 = *(const float4*)(Wb + 2*KP   + off);
        float4 w3 = *(const float4*)(Wb + 3*KP   + off);
        u64t wp[4][2];
        wp[0][0] = pk2(w0.x, w0.y); wp[0][1] = pk2(w0.z, w0.w);
        wp[1][0] = pk2(w1.x, w1.y); wp[1][1] = pk2(w1.z, w1.w);
        wp[2][0] = pk2(w2.x, w2.y); wp[2][1] = pk2(w2.z, w2.w);
        wp[3][0] = pk2(w3.x, w3.y); wp[3][1] = pk2(w3.z, w3.w);
#pragma unroll
        for (int b = 0; b < 8; b++) {
            float4 x = *(const float4*)(xb + b*K2_ + off);
            u64t x0 = pk2(x.x, x.y), x1 = pk2(x.z, x.w);
            fma2(acc[0][b], wp[0][0], x0); fma2(acc[0][b], wp[0][1], x1);
            fma2(acc[1][b], wp[1][0], x0); fma2(acc[1][b], wp[1][1], x1);
            fma2(acc[2][b], wp[2][0], x0); fma2(acc[2][b], wp[2][1], x1);
            fma2(acc[3][b], wp[3][0], x0); fma2(acc[3][b], wp[3][1], x1);
        }
    }
#pragma unroll
    for (int r = 0; r < 4; r++)
#pragma unroll
        for (int b = 0; b < 8; b++) {
            float s = warp_sum(psum(acc[r][b]));
            if (lane == r*8 + b) part[warp*32 + lane] = s;
        }
}

// combine two K-half partials, add bias, gate math, update c (smem) and h (global)
__device__ __forceinline__ void lstm_combine(
    const float* part, float* c_s, float* h_out,
    const float* __restrict__ bias1, bool per_sample, int t, int tid)
{
    if (tid < 48) {
        int cl = tid >> 3, b = tid & 7;
        int cell = blockIdx.x * 6 + cl;
        float z[4];
#pragma unroll
        for (int r = 0; r < 4; r++) {
            float zz = part[cl*64 + r*8 + b] + part[cl*64 + 32 + r*8 + b];
            zz += per_sample ? __ldg(&bias1[((size_t)(b*T_ + t))*G4_ + cell*4 + r])
                             : __ldg(&bias1[cell*4 + r]);
            z[r] = zz;
        }
        float co = c_s[tid];
        float ig = sigm(z[0]), fg = sigm(z[1]);
        float gg = tanhf(z[2]), og = sigm(z[3]);
        float cn = fg*co + ig*gg;
        c_s[tid] = cn;
        h_out[b*DC_ + cell] = og * tanhf(cn);
    }
}

__global__ __launch_bounds__(384, 1) void ar_kernel(
    const float* __restrict__ postw, const float* __restrict__ postb,
    const float* __restrict__ embw, float* __restrict__ out)
{
    extern __shared__ float sm[];
    float* xs   = sm;            // 12288 floats: x staged [b][K2_]
    float* part = sm + 12288;    // 12 warps * 32
    float* c1s  = sm + 12672;    // 48 (cell-local c state)
    float* c2s  = sm + 12720;    // 48
    const int tid = threadIdx.x, lane = tid & 31, warp = tid >> 5;

    if (tid < 48) { c1s[tid] = 0.f; c2s[tid] = 0.f; }
    __syncthreads();

    unsigned gen = 0;
    for (int t = 0; t < T_; t++) {
        int rd = t & 1, wr = rd ^ 1;

        // ---- fill xs for LSTM1: [emb(176) | h1_old(768) | 0-pad(80)] ----
        for (int i = tid; i < B_*K1P_; i += 384) {
            int b = i >> 10, k = i & (K1P_-1);
            float v = 0.f;
            if (k < 176)       v = embw[__ldcg((const int*)&g_prev[b][k >> 1]) * 2 + (k & 1)];
            else if (k < 944)  v = __ldcg(&g_h1[rd][b][k - 176]);
            xs[b*K2_ + k] = v;
        }
        __syncthreads();
        lstm_partial<K1P_>(g_W1r, xs, warp, lane, part);
        __syncthreads();
        lstm_combine(part, c1s, &g_h1[wr][0][0], g_pre, true, t, tid);
        grid_bar2(++gen);

        // ---- fill xs for LSTM2: [h1_new(768) | h2_old(768)] ----
        for (int i = tid; i < B_*K2_; i += 384) {
            int b = i / K2_, k = i - b*K2_;
            xs[i] = (k < DC_) ? __ldcg(&g_h1[wr][b][k]) : __ldcg(&g_h2[rd][b][k - DC_]);
        }
        __syncthreads();
        lstm_partial<K2_>(g_W2r, xs, warp, lane, part);
        __syncthreads();
        lstm_combine(part, c2s, &g_h2[wr][0][0], g_b2v, false, t, tid);
        grid_bar2(++gen);

        // ---- fill xs for post: h2_new(768) ----
        for (int i = tid; i < B_*DC_; i += 384) {
            int b = i / DC_, k = i - b*DC_;
            xs[b*K2_ + k] = __ldcg(&g_h2[wr][b][k]);
        }
        __syncthreads();

        // post GEMV + argmax; task = (pitch, batch-half)
        int task = warp * NB_AR + blockIdx.x;
        if (task < NP_*2) {
            int p = task >> 1, bh = (task & 1) * 4;
            const float* Wp = postw + (size_t)p*5*DC_;
            u64t acc[5][4];
#pragma unroll
            for (int s = 0; s < 5; s++)
#pragma unroll
                for (int b = 0; b < 4; b++) acc[s][b] = 0ull;
#pragma unroll 2
            for (int kb = 0; kb < DC_; kb += 128) {
                int off = kb + lane*4;
                u64t wp[5][2];
#pragma unroll
                for (int s = 0; s < 5; s++) {
                    float4 w = *(const float4*)(Wp + s*DC_ + off);
                    wp[s][0] = pk2(w.x, w.y); wp[s][1] = pk2(w.z, w.w);
                }
#pragma unroll
                for (int b = 0; b < 4; b++) {
                    float4 x = *(const float4*)(xs + (bh + b)*K2_ + off);
                    u64t x0 = pk2(x.x, x.y), x1 = pk2(x.z, x.w);
#pragma unroll
                    for (int s = 0; s < 5; s++) {
                        fma2(acc[s][b], wp[s][0], x0);
                        fma2(acc[s][b], wp[s][1], x1);
                    }
                }
            }
            float z[5][4];
#pragma unroll
            for (int s = 0; s < 5; s++)
#pragma unroll
                for (int b = 0; b < 4; b++)
                    z[s][b] = warp_sum(psum(acc[s][b]));
            if (lane < 4) {
                int b = bh + lane;
                float* o = out + (size_t)(b*T_ + t)*440 + p*5;
                float best = -1e30f; int bi = 0;
#pragma unroll
                for (int s = 0; s < 5; s++) {
                    float v0 = (lane & 1) ? z[s][1] : z[s][0];
                    float v1 = (lane & 1) ? z[s][3] : z[s][2];
                    float v  = ((lane & 2) ? v1 : v0) + postb[p*5 + s];
                    o[s] = v;
                    if (v > best) { best = v; bi = s; }
                }
                g_prev[b][p] = bi;
            }
        }
        grid_bar2(++gen);
    }
}

// ---------------- launch ----------------
extern "C" void kernel_launch(void* const* d_in, const int* in_sizes, int n_in,
                              void* d_out, int out_size)
{
    const float* mel    = (const float*)d_in[0];
    const float* c1w    = (const float*)d_in[1];
    const float* c1b    = (const float*)d_in[2];
    const float* b1g    = (const float*)d_in[3];
    const float* b1b    = (const float*)d_in[4];
    const float* b1m    = (const float*)d_in[5];
    const float* b1v    = (const float*)d_in[6];
    const float* c2w    = (const float*)d_in[7];
    const float* c2b    = (const float*)d_in[8];
    const float* b2g    = (const float*)d_in[9];
    const float* b2b    = (const float*)d_in[10];
    const float* b2m    = (const float*)d_in[11];
    const float* b2v    = (const float*)d_in[12];
    const float* c3w    = (const float*)d_in[13];
    const float* c3b    = (const float*)d_in[14];
    const float* b3g    = (const float*)d_in[15];
    const float* b3b    = (const float*)d_in[16];
    const float* b3m    = (const float*)d_in[17];
    const float* b3v    = (const float*)d_in[18];
    const float* fc_w   = (const float*)d_in[19];
    const float* fc_b   = (const float*)d_in[20];
    const float* wih1   = (const float*)d_in[21];
    const float* whh1   = (const float*)d_in[22];
    const float* bih1   = (const float*)d_in[23];
    const float* bhh1   = (const float*)d_in[24];
    const float* wih2   = (const float*)d_in[25];
    const float* whh2   = (const float*)d_in[26];
    const float* bih2   = (const float*)d_in[27];
    const float* bhh2   = (const float*)d_in[28];
    const float* post_w = (const float*)d_in[29];
    const float* post_b = (const float*)d_in[30];
    const float* emb_w  = (const float*)d_in[31];

    prep_kernel<<<2048, 256>>>(c1w, c1b, b1g, b1b, b1m, b1v,
                               c2w, c2b, b2g, b2b, b2m, b2v,
                               c3w, c3b, b3g, b3b, b3m, b3v,
                               wih1, whh1, bih1, bhh1,
                               wih2, whh2, bih2, bhh2);

    conv1_kernel<<<dim3(T_, B_), 256>>>(mel);
    conv2_kernel<<<dim3(T_/4, B_, C1_/8), 256>>>();
    conv3_kernel<<<dim3(T_/4, B_, C3_/8), 128>>>();

    float *pA, *pAc, *pPre, *pWpre, *pBpre;
    cudaGetSymbolAddress((void**)&pA,    g_Amat);
    cudaGetSymbolAddress((void**)&pAc,   g_ac);
    cudaGetSymbolAddress((void**)&pPre,  g_pre);
    cudaGetSymbolAddress((void**)&pWpre, g_Wpre);
    cudaGetSymbolAddress((void**)&pBpre, g_bpre);

    // acoustic = A * fc_w^T + fc_b              (4096 x 768, K=5472)
    gemm_tn<<<dim3(DC_/BN_, MALL_/BM_), 256>>>(pA, fc_w, fc_b, pAc, MALL_, DC_, FCIN_);
    // pre = acoustic * Wpre^T + (bih1+bhh1)     (4096 x 3072, K=768)
    gemm_tn<<<dim3(G4_/BN_, MALL_/BM_), 256>>>(pAc, pWpre, pBpre, pPre, MALL_, G4_, DC_);

    const int ar_smem = (12288 + 384 + 48 + 48) * (int)sizeof(float);  // 51072 B
    cudaFuncSetAttribute(ar_kernel, cudaFuncAttributeMaxDynamicSharedMemorySize, ar_smem);
    ar_kernel<<<NB_AR, 384, ar_smem>>>(post_w, post_b, emb_w, (float*)d_out);
}

// round 6
// speedup vs baseline: 1.6465x; 1.3755x over previous
#include <cuda_runtime.h>
#include <math.h>

#define B_    8
#define T_    512
#define F_    229
#define C1_   48
#define C3_   96
#define FP1_  114
#define FP2_  57
#define DC_   768
#define FCIN_ 5472
#define G4_   3072
#define K1P_  1024   /* [emb 176 + pad 80 -> 256 | h1 768] */
#define K2_   1536
#define NP_   88
#define MALL_ 4096
#define NB_AR 128

typedef unsigned long long u64t;

// ---------------- f32x2 helpers ----------------
__device__ __forceinline__ void fma2(u64t &acc, u64t a, u64t b) {
    asm("fma.rn.f32x2 %0, %1, %2, %0;" : "+l"(acc) : "l"(a), "l"(b));
}
__device__ __forceinline__ u64t pk2(float lo, float hi) {
    u64t r;
    asm("mov.b64 %0, {%1, %2};" : "=l"(r) : "r"(__float_as_uint(lo)), "r"(__float_as_uint(hi)));
    return r;
}
__device__ __forceinline__ float2 upk2(u64t v) {
    unsigned lo, hi;
    asm("mov.b64 {%0, %1}, %2;" : "=r"(lo), "=r"(hi) : "l"(v));
    return make_float2(__uint_as_float(lo), __uint_as_float(hi));
}
__device__ __forceinline__ float psum(u64t v) {
    float2 f = upk2(v);
    return f.x + f.y;
}

// ---------------- device scratch ----------------
__device__ float g_conv1[B_*C1_*T_*F_];
__device__ float g_conv2[B_*C1_*T_*FP1_];
__device__ float g_Amat[MALL_*FCIN_];
__device__ float g_ac[MALL_*DC_];
__device__ float g_pre[MALL_*G4_];
__device__ float g_W1r[G4_*K1P_];
__device__ float g_W2r[G4_*K2_];
__device__ float g_Wpre[G4_*DC_];
__device__ float g_bpre[G4_];
__device__ float g_b2v[G4_];
__device__ float g_wf1[C1_*9],      g_bf1[C1_];
__device__ float g_wf2[C1_*C1_*9],  g_bf2[C1_];
__device__ float g_wf3[C3_*C1_*9],  g_bf3[C3_];
__device__ float g_h1[2][B_][DC_], g_h2[2][B_][DC_];
__device__ int   g_prev[B_][NP_];
__device__ unsigned g_cnt2;
__device__ volatile unsigned g_rel2;

// ---------------- prep ----------------
__global__ void prep_kernel(
    const float* __restrict__ c1w, const float* __restrict__ c1b,
    const float* __restrict__ b1g, const float* __restrict__ b1b,
    const float* __restrict__ b1m, const float* __restrict__ b1v,
    const float* __restrict__ c2w, const float* __restrict__ c2b,
    const float* __restrict__ b2g, const float* __restrict__ b2b,
    const float* __restrict__ b2m, const float* __restrict__ b2v,
    const float* __restrict__ c3w, const float* __restrict__ c3b,
    const float* __restrict__ b3g, const float* __restrict__ b3b,
    const float* __restrict__ b3m, const float* __restrict__ b3v,
    const float* __restrict__ wih1, const float* __restrict__ whh1,
    const float* __restrict__ bih1, const float* __restrict__ bhh1,
    const float* __restrict__ wih2, const float* __restrict__ whh2,
    const float* __restrict__ bih2, const float* __restrict__ bhh2)
{
    const int st = gridDim.x * blockDim.x;
    const int t0 = blockIdx.x * blockDim.x + threadIdx.x;
    const float eps = 1e-5f;

    for (int i = t0; i < C1_*9; i += st) { int c = i/9;        g_wf1[i] = c1w[i] * (b1g[c]*rsqrtf(b1v[c]+eps)); }
    for (int i = t0; i < C1_;  i += st)  g_bf1[i] = (c1b[i]-b1m[i])*(b1g[i]*rsqrtf(b1v[i]+eps)) + b1b[i];
    for (int i = t0; i < C1_*C1_*9; i += st) { int c = i/(C1_*9); g_wf2[i] = c2w[i] * (b2g[c]*rsqrtf(b2v[c]+eps)); }
    for (int i = t0; i < C1_;  i += st)  g_bf2[i] = (c2b[i]-b2m[i])*(b2g[i]*rsqrtf(b2v[i]+eps)) + b2b[i];
    for (int i = t0; i < C3_*C1_*9; i += st) { int c = i/(C1_*9); g_wf3[i] = c3w[i] * (b3g[c]*rsqrtf(b3v[c]+eps)); }
    for (int i = t0; i < C3_;  i += st)  g_bf3[i] = (c3b[i]-b3m[i])*(b3g[i]*rsqrtf(b3v[i]+eps)) + b3b[i];

    // W1r layout: rows n = cell*4+g; cols [0,176)=wih1 emb part, [176,256)=0, [256,1024)=whh1
    for (int i = t0; i < G4_*K1P_; i += st) {
        int n = i >> 10, k = i & (K1P_-1);
        int m = n >> 2, g = n & 3, orig = g*DC_ + m;
        float v = 0.f;
        if (k < 176)       v = wih1[orig*944 + 768 + k];
        else if (k >= 256) v = whh1[orig*DC_ + (k - 256)];
        g_W1r[i] = v;
    }
    // W2r: cols [0,768)=wih2, [768,1536)=whh2
    for (int i = t0; i < G4_*K2_; i += st) {
        int n = i / K2_, k = i - n*K2_;
        int m = n >> 2, g = n & 3, orig = g*DC_ + m;
        g_W2r[i] = (k < DC_) ? wih2[orig*DC_ + k] : whh2[orig*DC_ + (k - DC_)];
    }
    // Wpre: acoustic part of wih1, reordered rows
    for (int i = t0; i < G4_*DC_; i += st) {
        int n = i / DC_, k = i - n*DC_;
        int m = n >> 2, g = n & 3, orig = g*DC_ + m;
        g_Wpre[i] = wih1[orig*944 + k];
    }
    for (int i = t0; i < G4_; i += st) {
        int m = i >> 2, g = i & 3, orig = g*DC_ + m;
        g_bpre[i] = bih1[orig] + bhh1[orig];
        g_b2v[i]  = bih2[orig] + bhh2[orig];
    }
    for (int i = t0; i < B_*DC_; i += st) {
        (&g_h1[0][0][0])[i] = 0.f;
        (&g_h2[0][0][0])[i] = 0.f;
    }
    for (int i = t0; i < B_*NP_; i += st) (&g_prev[0][0])[i] = 0;
    if (t0 == 0) { g_cnt2 = 0u; g_rel2 = 0u; }
}

// ---------------- conv1 ----------------
__global__ void conv1_kernel(const float* __restrict__ mel)
{
    int t = blockIdx.x, b = blockIdx.y, f = threadIdx.x;
    __shared__ float ws[C1_*9];
    __shared__ float bs[C1_];
    for (int i = threadIdx.x; i < C1_*9; i += 256) ws[i] = g_wf1[i];
    for (int i = threadIdx.x; i < C1_;  i += 256) bs[i] = g_bf1[i];
    __syncthreads();
    if (f >= F_) return;

    float x[9];
#pragma unroll
    for (int dt = 0; dt < 3; dt++)
#pragma unroll
        for (int df = 0; df < 3; df++) {
            int tt = t - 1 + dt, ff = f - 1 + df;
            x[dt*3+df] = (tt >= 0 && tt < T_ && ff >= 0 && ff < F_)
                         ? mel[(b*T_ + tt)*F_ + ff] : 0.f;
        }
    for (int c = 0; c < C1_; c++) {
        float a = bs[c];
#pragma unroll
        for (int k = 0; k < 9; k++) a += ws[c*9+k] * x[k];
        g_conv1[((b*C1_ + c)*T_ + t)*F_ + f] = fmaxf(a, 0.f);
    }
}

// ---------------- conv2 ----------------
__global__ __launch_bounds__(256) void conv2_kernel()
{
    int t0 = blockIdx.x * 4, b = blockIdx.y, ch = blockIdx.z;
    int f = threadIdx.x;
    __shared__ float ws[8*C1_*9];
    __shared__ float ys[4][232];
    for (int i = threadIdx.x; i < 8*C1_*9; i += 256) ws[i] = g_wf2[ch*8*C1_*9 + i];
    __syncthreads();

    float acc[8][4];
#pragma unroll
    for (int cc = 0; cc < 8; cc++) {
        float bv = g_bf2[ch*8 + cc];
#pragma unroll
        for (int tt = 0; tt < 4; tt++) acc[cc][tt] = bv;
    }
    if (f < F_) {
        for (int ci = 0; ci < C1_; ci++) {
            const float* base = g_conv1 + ((b*C1_ + ci)*T_)*F_;
            float xr[6][3];
#pragma unroll
            for (int j = 0; j < 6; j++) {
                int tt = t0 - 1 + j;
#pragma unroll
                for (int d = 0; d < 3; d++) {
                    int ff = f - 1 + d;
                    xr[j][d] = (tt >= 0 && tt < T_ && ff >= 0 && ff < F_)
                               ? base[tt*F_ + ff] : 0.f;
                }
            }
#pragma unroll
            for (int cc = 0; cc < 8; cc++) {
                const float* w = &ws[(cc*C1_ + ci)*9];
                float w0=w[0],w1=w[1],w2=w[2],w3=w[3],w4=w[4],w5=w[5],w6=w[6],w7=w[7],w8=w[8];
#pragma unroll
                for (int tt = 0; tt < 4; tt++) {
                    acc[cc][tt] += w0*xr[tt  ][0] + w1*xr[tt  ][1] + w2*xr[tt  ][2]
                                 + w3*xr[tt+1][0] + w4*xr[tt+1][1] + w5*xr[tt+1][2]
                                 + w6*xr[tt+2][0] + w7*xr[tt+2][1] + w8*xr[tt+2][2];
                }
            }
        }
    }
    for (int cc = 0; cc < 8; cc++) {
        __syncthreads();
        if (f < F_) {
#pragma unroll
            for (int tt = 0; tt < 4; tt++) ys[tt][f] = fmaxf(acc[cc][tt], 0.f);
        }
        __syncthreads();
        if (f < FP1_) {
            int c = ch*8 + cc;
#pragma unroll
            for (int tt = 0; tt < 4; tt++)
                g_conv2[((b*C1_ + c)*T_ + t0 + tt)*FP1_ + f] =
                    fmaxf(ys[tt][2*f], ys[tt][2*f+1]);
        }
    }
}

// ---------------- conv3 ----------------
__global__ __launch_bounds__(128) void conv3_kernel()
{
    int t0 = blockIdx.x * 4, b = blockIdx.y, ch = blockIdx.z;
    int f = threadIdx.x;
    __shared__ float ws[8*C1_*9];
    __shared__ float ys[4][116];
    for (int i = threadIdx.x; i < 8*C1_*9; i += 128) ws[i] = g_wf3[ch*8*C1_*9 + i];
    __syncthreads();

    float acc[8][4];
#pragma unroll
    for (int cc = 0; cc < 8; cc++) {
        float bv = g_bf3[ch*8 + cc];
#pragma unroll
        for (int tt = 0; tt < 4; tt++) acc[cc][tt] = bv;
    }
    if (f < FP1_) {
        for (int ci = 0; ci < C1_; ci++) {
            const float* base = g_conv2 + ((b*C1_ + ci)*T_)*FP1_;
            float xr[6][3];
#pragma unroll
            for (int j = 0; j < 6; j++) {
                int tt = t0 - 1 + j;
#pragma unroll
                for (int d = 0; d < 3; d++) {
                    int ff = f - 1 + d;
                    xr[j][d] = (tt >= 0 && tt < T_ && ff >= 0 && ff < FP1_)
                               ? base[tt*FP1_ + ff] : 0.f;
                }
            }
#pragma unroll
            for (int cc = 0; cc < 8; cc++) {
                const float* w = &ws[(cc*C1_ + ci)*9];
                float w0=w[0],w1=w[1],w2=w[2],w3=w[3],w4=w[4],w5=w[5],w6=w[6],w7=w[7],w8=w[8];
#pragma unroll
                for (int tt = 0; tt < 4; tt++) {
                    acc[cc][tt] += w0*xr[tt  ][0] + w1*xr[tt  ][1] + w2*xr[tt  ][2]
                                 + w3*xr[tt+1][0] + w4*xr[tt+1][1] + w5*xr[tt+1][2]
                                 + w6*xr[tt+2][0] + w7*xr[tt+2][1] + w8*xr[tt+2][2];
                }
            }
        }
    }
    for (int cc = 0; cc < 8; cc++) {
        __syncthreads();
        if (f < FP1_) {
#pragma unroll
            for (int tt = 0; tt < 4; tt++) ys[tt][f] = fmaxf(acc[cc][tt], 0.f);
        }
        __syncthreads();
        if (f < FP2_) {
            int c = ch*8 + cc;
#pragma unroll
            for (int tt = 0; tt < 4; tt++)
                g_Amat[(b*T_ + t0 + tt)*FCIN_ + c*FP2_ + f] =
                    fmaxf(ys[tt][2*f], ys[tt][2*f+1]);
        }
    }
}

// ---------------- GEMM (unchanged from R5) ----------------
#define BM_ 128
#define BN_ 128
#define BK_ 16

__global__ __launch_bounds__(256) void gemm_tn(
    const float* __restrict__ A, const float* __restrict__ Bm,
    const float* __restrict__ bias, float* __restrict__ C,
    int M, int N, int K)
{
    __shared__ float As[2][BK_][BM_];
    __shared__ float Bs[2][BK_][BN_];

    const int tid = threadIdx.x;
    const int m0 = blockIdx.y * BM_, n0 = blockIdx.x * BN_;

    const int lr = tid >> 2;
    const int lk = (tid & 3) * 4;
    const float* Ap = A + (size_t)(m0 + lr) * K + lk;
    const float* Bp = Bm + (size_t)(n0 + lr) * K + lk;
    const size_t rowK = (size_t)64 * K;

    const int warp = tid >> 5, lane = tid & 31;
    const int wm = warp & 3, wn = warp >> 2;
    const int lm = lane >> 3, ln = lane & 7;
    const int row0 = wm * 32 + lm * 8;
    const int col0 = wn * 64 + ln * 8;

    u64t acc2[8][4];
#pragma unroll
    for (int i = 0; i < 8; i++)
#pragma unroll
        for (int j = 0; j < 4; j++) acc2[i][j] = 0ull;

    {
        float4 a0 = *(const float4*)(Ap);
        float4 a1 = *(const float4*)(Ap + rowK);
        float4 b0 = *(const float4*)(Bp);
        float4 b1 = *(const float4*)(Bp + rowK);
        As[0][lk+0][lr] = a0.x; As[0][lk+1][lr] = a0.y; As[0][lk+2][lr] = a0.z; As[0][lk+3][lr] = a0.w;
        As[0][lk+0][lr+64] = a1.x; As[0][lk+1][lr+64] = a1.y; As[0][lk+2][lr+64] = a1.z; As[0][lk+3][lr+64] = a1.w;
        Bs[0][lk+0][lr] = b0.x; Bs[0][lk+1][lr] = b0.y; Bs[0][lk+2][lr] = b0.z; Bs[0][lk+3][lr] = b0.w;
        Bs[0][lk+0][lr+64] = b1.x; Bs[0][lk+1][lr+64] = b1.y; Bs[0][lk+2][lr+64] = b1.z; Bs[0][lk+3][lr+64] = b1.w;
    }
    __syncthreads();

    const int nkt = K >> 4;
    int cur = 0;
    for (int kt = 0; kt < nkt; kt++) {
        float4 pa0, pa1, pb0, pb1;
        const bool has = (kt + 1 < nkt);
        if (has) {
            int ko = (kt + 1) << 4;
            pa0 = *(const float4*)(Ap + ko);
            pa1 = *(const float4*)(Ap + rowK + ko);
            pb0 = *(const float4*)(Bp + ko);
            pb1 = *(const float4*)(Bp + rowK + ko);
        }
#pragma unroll
        for (int kk = 0; kk < BK_; kk++) {
            float4 av0 = *(const float4*)&As[cur][kk][row0];
            float4 av1 = *(const float4*)&As[cur][kk][row0 + 4];
            float4 bv0 = *(const float4*)&Bs[cur][kk][col0];
            float4 bv1 = *(const float4*)&Bs[cur][kk][col0 + 4];
            u64t b2[4];
            b2[0] = pk2(bv0.x, bv0.y); b2[1] = pk2(bv0.z, bv0.w);
            b2[2] = pk2(bv1.x, bv1.y); b2[3] = pk2(bv1.z, bv1.w);
            float a[8] = {av0.x, av0.y, av0.z, av0.w, av1.x, av1.y, av1.z, av1.w};
#pragma unroll
            for (int i = 0; i < 8; i++) {
                u64t ai = pk2(a[i], a[i]);
#pragma unroll
                for (int j = 0; j < 4; j++)
                    fma2(acc2[i][j], ai, b2[j]);
            }
        }
        if (has) {
            int nb = cur ^ 1;
            As[nb][lk+0][lr] = pa0.x; As[nb][lk+1][lr] = pa0.y; As[nb][lk+2][lr] = pa0.z; As[nb][lk+3][lr] = pa0.w;
            As[nb][lk+0][lr+64] = pa1.x; As[nb][lk+1][lr+64] = pa1.y; As[nb][lk+2][lr+64] = pa1.z; As[nb][lk+3][lr+64] = pa1.w;
            Bs[nb][lk+0][lr] = pb0.x; Bs[nb][lk+1][lr] = pb0.y; Bs[nb][lk+2][lr] = pb0.z; Bs[nb][lk+3][lr] = pb0.w;
            Bs[nb][lk+0][lr+64] = pb1.x; Bs[nb][lk+1][lr+64] = pb1.y; Bs[nb][lk+2][lr+64] = pb1.z; Bs[nb][lk+3][lr+64] = pb1.w;
        }
        __syncthreads();
        cur ^= 1;
    }

    float bv[8];
#pragma unroll
    for (int j = 0; j < 8; j++) bv[j] = bias[n0 + col0 + j];
#pragma unroll
    for (int i = 0; i < 8; i++) {
        float* Cp = C + (size_t)(m0 + row0 + i) * N + n0 + col0;
        float2 r0 = upk2(acc2[i][0]), r1 = upk2(acc2[i][1]);
        float2 r2 = upk2(acc2[i][2]), r3 = upk2(acc2[i][3]);
        float4 o0 = make_float4(r0.x+bv[0], r0.y+bv[1], r1.x+bv[2], r1.y+bv[3]);
        float4 o1 = make_float4(r2.x+bv[4], r2.y+bv[5], r3.x+bv[6], r3.y+bv[7]);
        *(float4*)(Cp)     = o0;
        *(float4*)(Cp + 4) = o1;
    }
}

// ---------------- AR persistent kernel ----------------
__device__ __forceinline__ float warp_sum(float s)
{
    s += __shfl_xor_sync(0xffffffffu, s, 16);
    s += __shfl_xor_sync(0xffffffffu, s, 8);
    s += __shfl_xor_sync(0xffffffffu, s, 4);
    s += __shfl_xor_sync(0xffffffffu, s, 2);
    s += __shfl_xor_sync(0xffffffffu, s, 1);
    return s;
}
__device__ __forceinline__ float sigm(float x) { return 1.f / (1.f + expf(-x)); }

// single-counter sense barrier: target = gen * NB_AR
__device__ __forceinline__ void gbar(unsigned gen)
{
    __syncthreads();
    if (threadIdx.x == 0) {
        __threadfence();
        unsigned a = atomicAdd(&g_cnt2, 1u) + 1u;
        if (a == gen * NB_AR) {
            g_rel2 = gen;
        } else {
            while (g_rel2 < gen) { }
        }
    }
    __syncthreads();
}

// staged pairwise reduction: 32 values across 32 lanes; result for index L lands on lane L in v[0]
__device__ __forceinline__ void reduce32(float* v, int lane)
{
#pragma unroll
    for (int o = 16; o > 0; o >>= 1) {
        bool hi = (lane & o) != 0;
#pragma unroll
        for (int i = 0; i < o; i++) {
            float a0 = v[i], a1 = v[i + o];
            float mine = hi ? a1 : a0;
            float send = hi ? a0 : a1;
            float other = __shfl_xor_sync(0xffffffffu, send, o);
            v[i] = mine + other;
        }
    }
}

// GEMV partial: 4 gate rows x 8 batches; K-range NITER*128 elements
template<int NITER>
__device__ __forceinline__ void gemv_part(
    const float* __restrict__ Wb, int wstride,
    const float* xb, int xstride, int lane, float* v)
{
    u64t acc[4][8];
#pragma unroll
    for (int r = 0; r < 4; r++)
#pragma unroll
        for (int b = 0; b < 8; b++) acc[r][b] = 0ull;

#pragma unroll
    for (int it = 0; it < NITER; it++) {
        int off = it * 128 + lane * 4;
        float4 w0 = *(const float4*)(Wb              + off);
        float4 w1 = *(const float4*)(Wb +   wstride  + off);
        float4 w2 = *(const float4*)(Wb + 2*wstride  + off);
        float4 w3 = *(const float4*)(Wb + 3*wstride  + off);
        u64t wp[4][2];
        wp[0][0] = pk2(w0.x, w0.y); wp[0][1] = pk2(w0.z, w0.w);
        wp[1][0] = pk2(w1.x, w1.y); wp[1][1] = pk2(w1.z, w1.w);
        wp[2][0] = pk2(w2.x, w2.y); wp[2][1] = pk2(w2.z, w2.w);
        wp[3][0] = pk2(w3.x, w3.y); wp[3][1] = pk2(w3.z, w3.w);
#pragma unroll
        for (int b = 0; b < 8; b++) {
            float4 x = *(const float4*)(xb + b*xstride + off);
            u64t x0 = pk2(x.x, x.y), x1 = pk2(x.z, x.w);
            fma2(acc[0][b], wp[0][0], x0); fma2(acc[0][b], wp[0][1], x1);
            fma2(acc[1][b], wp[1][0], x0); fma2(acc[1][b], wp[1][1], x1);
            fma2(acc[2][b], wp[2][0], x0); fma2(acc[2][b], wp[2][1], x1);
            fma2(acc[3][b], wp[3][0], x0); fma2(acc[3][b], wp[3][1], x1);
        }
    }
#pragma unroll
    for (int r = 0; r < 4; r++)
#pragma unroll
        for (int b = 0; b < 8; b++) v[r*8 + b] = psum(acc[r][b]);
}

// smem float offsets
#define SM_XS2  0        /* 8*1536 = 12288 : [h1_new | h2_old] */
#define SM_XH2  12288    /* 8*768  =  6144 : h2_new staged for post */
#define SM_X1E  18432    /* 8*256  =  2048 : emb input (pad zeros) */
#define SM_PE   20480    /* 12*32 */
#define SM_PH   20864    /* 12*32 */
#define SM_P2   21248    /* 12*32 */
#define SM_PRE  21632    /* 2*192 */
#define SM_C1   22016    /* 48 */
#define SM_C2   22064    /* 48 */
#define SM_TOT  22112

__global__ __launch_bounds__(384, 1) void ar_kernel(
    const float* __restrict__ postw, const float* __restrict__ postb,
    const float* __restrict__ embw, float* __restrict__ out)
{
    extern __shared__ float sm[];
    float* xs2  = sm + SM_XS2;
    float* xh2  = sm + SM_XH2;
    float* x1e  = sm + SM_X1E;
    float* pe   = sm + SM_PE;
    float* ph   = sm + SM_PH;
    float* p2   = sm + SM_P2;
    float* preS = sm + SM_PRE;
    float* c1s  = sm + SM_C1;
    float* c2s  = sm + SM_C2;

    const int tid = threadIdx.x, lane = tid & 31, warp = tid >> 5;
    const int cl = warp >> 1, half = warp & 1;
    const int cell = blockIdx.x * 6 + cl;

    // init: zero x1e (pad region stays 0), ph (h1(-1)=0), c-state; preload preS for t=0
    for (int i = tid; i < 2048; i += 384) x1e[i] = 0.f;
    for (int i = tid; i < 384;  i += 384) ph[i] = 0.f;
    if (tid < 384) { }  // (all ph entries covered above since 384 threads)
    if (tid < 48) { c1s[tid] = 0.f; c2s[tid] = 0.f; }
    if (tid < 192) {
        int b = tid / 24, j = tid - b*24;
        preS[tid] = __ldg(&g_pre[(size_t)(b*T_)*G4_ + blockIdx.x*24 + j]);
    }
    __syncthreads();

    float v[32];
    unsigned gen = 0;

    for (int t = 0; t < T_; t++) {
        const int rd = t & 1, wr = rd ^ 1, pbuf = t & 1;

        // ======== Phase A: emb-part GEMV + combine -> h1_new ========
        for (int i = tid; i < B_*176; i += 384) {
            int b = i / 176, k = i - b*176;
            x1e[b*256 + k] = embw[__ldcg((const int*)&g_prev[b][k >> 1]) * 2 + (k & 1)];
        }
        __syncthreads();
        gemv_part<1>(g_W1r + (size_t)cell*4*K1P_ + half*128, K1P_,
                     x1e + half*128, 256, lane, v);
        reduce32(v, lane);
        pe[warp*32 + lane] = v[0];
        __syncthreads();
        if (tid < 48) {
            int c = tid >> 3, b = tid & 7;
            int mycell = blockIdx.x*6 + c;
            float z[4];
#pragma unroll
            for (int r = 0; r < 4; r++) {
                int idx = r*8 + b;
                z[r] = pe[(c*2)*32 + idx] + pe[(c*2+1)*32 + idx]
                     + ph[(c*2)*32 + idx] + ph[(c*2+1)*32 + idx]
                     + preS[pbuf*192 + b*24 + c*4 + r];
            }
            float co = c1s[tid];
            float ig = sigm(z[0]), fg = sigm(z[1]);
            float gg = tanhf(z[2]), og = sigm(z[3]);
            float cn = fg*co + ig*gg;
            c1s[tid] = cn;
            g_h1[wr][b][mycell] = og * tanhf(cn);
        }
        gbar(++gen);

        // ======== Phase B: LSTM2 ========
        for (int i = tid; i < B_*DC_; i += 384) {
            int b = i / DC_, k = i - b*DC_;
            xs2[b*K2_ + k]       = __ldcg(&g_h1[wr][b][k]);
            xs2[b*K2_ + DC_ + k] = __ldcg(&g_h2[rd][b][k]);
        }
        __syncthreads();
        gemv_part<6>(g_W2r + (size_t)cell*4*K2_ + half*DC_, K2_,
                     xs2 + half*DC_, K2_, lane, v);
        reduce32(v, lane);
        p2[warp*32 + lane] = v[0];
        __syncthreads();
        if (tid < 48) {
            int c = tid >> 3, b = tid & 7;
            int mycell = blockIdx.x*6 + c;
            float z[4];
#pragma unroll
            for (int r = 0; r < 4; r++) {
                int idx = r*8 + b;
                z[r] = p2[(c*2)*32 + idx] + p2[(c*2+1)*32 + idx]
                     + __ldg(&g_b2v[mycell*4 + r]);
            }
            float co = c2s[tid];
            float ig = sigm(z[0]), fg = sigm(z[1]);
            float gg = tanhf(z[2]), og = sigm(z[3]);
            float cn = fg*co + ig*gg;
            c2s[tid] = cn;
            g_h2[wr][b][mycell] = og * tanhf(cn);
        }
        gbar(++gen);

        // ======== Phase C: stage h2_new; h1-part GEMV for t+1; post GEMV + argmax ========
        for (int i = tid; i < B_*DC_; i += 384) {
            int b = i / DC_, k = i - b*DC_;
            xh2[i] = __ldcg(&g_h2[wr][b][k]);
        }
        if (t + 1 < T_ && tid < 192) {
            int b = tid / 24, j = tid - b*24;
            preS[(pbuf^1)*192 + tid] = __ldg(&g_pre[(size_t)(b*T_ + t + 1)*G4_ + blockIdx.x*24 + j]);
        }
        __syncthreads();

        // h1-dependent 3/4 of LSTM1 for NEXT step (x = h1_new already staged in xs2[0:768))
        gemv_part<3>(g_W1r + (size_t)cell*4*K1P_ + 256 + half*384, K1P_,
                     xs2 + half*384, K2_, lane, v);
        reduce32(v, lane);
        ph[warp*32 + lane] = v[0];

        // post GEMV + argmax; task = (pitch, batch-half)
        {
            int task = warp * NB_AR + blockIdx.x;
            if (task < NP_*2) {
                int p = task >> 1, bh = (task & 1) * 4;
                const float* Wp = postw + (size_t)p*5*DC_;
                u64t acc[5][4];
#pragma unroll
                for (int s = 0; s < 5; s++)
#pragma unroll
                    for (int b = 0; b < 4; b++) acc[s][b] = 0ull;
#pragma unroll 2
                for (int kb = 0; kb < DC_; kb += 128) {
                    int off = kb + lane*4;
                    u64t wp[5][2];
#pragma unroll
                    for (int s = 0; s < 5; s++) {
                        float4 w = *(const float4*)(Wp + s*DC_ + off);
                        wp[s][0] = pk2(w.x, w.y); wp[s][1] = pk2(w.z, w.w);
                    }
#pragma unroll
                    for (int b = 0; b < 4; b++) {
                        float4 x = *(const float4*)(xh2 + (bh + b)*DC_ + off);
                        u64t x0 = pk2(x.x, x.y), x1 = pk2(x.z, x.w);
#pragma unroll
                        for (int s = 0; s < 5; s++) {
                            fma2(acc[s][b], wp[s][0], x0);
                            fma2(acc[s][b], wp[s][1], x1);
                        }
                    }
                }
                float z[5][4];
#pragma unroll
                for (int s = 0; s < 5; s++)
#pragma unroll
                    for (int b = 0; b < 4; b++)
                        z[s][b] = warp_sum(psum(acc[s][b]));
                if (lane < 4) {
                    int b = bh + lane;
                    float* o = out + (size_t)(b*T_ + t)*440 + p*5;
                    float best = -1e30f; int bi = 0;
#pragma unroll
                    for (int s = 0; s < 5; s++) {
                        float v0 = (lane & 1) ? z[s][1] : z[s][0];
                        float v1 = (lane & 1) ? z[s][3] : z[s][2];
                        float vv = ((lane & 2) ? v1 : v0) + postb[p*5 + s];
                        o[s] = vv;
                        if (vv > best) { best = vv; bi = s; }
                    }
                    g_prev[b][p] = bi;
                }
            }
        }
        gbar(++gen);
    }
}

// ---------------- launch ----------------
extern "C" void kernel_launch(void* const* d_in, const int* in_sizes, int n_in,
                              void* d_out, int out_size)
{
    const float* mel    = (const float*)d_in[0];
    const float* c1w    = (const float*)d_in[1];
    const float* c1b    = (const float*)d_in[2];
    const float* b1g    = (const float*)d_in[3];
    const float* b1b    = (const float*)d_in[4];
    const float* b1m    = (const float*)d_in[5];
    const float* b1v    = (const float*)d_in[6];
    const float* c2w    = (const float*)d_in[7];
    const float* c2b    = (const float*)d_in[8];
    const float* b2g    = (const float*)d_in[9];
    const float* b2b    = (const float*)d_in[10];
    const float* b2m    = (const float*)d_in[11];
    const float* b2v    = (const float*)d_in[12];
    const float* c3w    = (const float*)d_in[13];
    const float* c3b    = (const float*)d_in[14];
    const float* b3g    = (const float*)d_in[15];
    const float* b3b    = (const float*)d_in[16];
    const float* b3m    = (const float*)d_in[17];
    const float* b3v    = (const float*)d_in[18];
    const float* fc_w   = (const float*)d_in[19];
    const float* fc_b   = (const float*)d_in[20];
    const float* wih1   = (const float*)d_in[21];
    const float* whh1   = (const float*)d_in[22];
    const float* bih1   = (const float*)d_in[23];
    const float* bhh1   = (const float*)d_in[24];
    const float* wih2   = (const float*)d_in[25];
    const float* whh2   = (const float*)d_in[26];
    const float* bih2   = (const float*)d_in[27];
    const float* bhh2   = (const float*)d_in[28];
    const float* post_w = (const float*)d_in[29];
    const float* post_b = (const float*)d_in[30];
    const float* emb_w  = (const float*)d_in[31];

    prep_kernel<<<2048, 256>>>(c1w, c1b, b1g, b1b, b1m, b1v,
                               c2w, c2b, b2g, b2b, b2m, b2v,
                               c3w, c3b, b3g, b3b, b3m, b3v,
                               wih1, whh1, bih1, bhh1,
                               wih2, whh2, bih2, bhh2);

    conv1_kernel<<<dim3(T_, B_), 256>>>(mel);
    conv2_kernel<<<dim3(T_/4, B_, C1_/8), 256>>>();
    conv3_kernel<<<dim3(T_/4, B_, C3_/8), 128>>>();

    float *pA, *pAc, *pPre, *pWpre, *pBpre;
    cudaGetSymbolAddress((void**)&pA,    g_Amat);
    cudaGetSymbolAddress((void**)&pAc,   g_ac);
    cudaGetSymbolAddress((void**)&pPre,  g_pre);
    cudaGetSymbolAddress((void**)&pWpre, g_Wpre);
    cudaGetSymbolAddress((void**)&pBpre, g_bpre);

    gemm_tn<<<dim3(DC_/BN_, MALL_/BM_), 256>>>(pA, fc_w, fc_b, pAc, MALL_, DC_, FCIN_);
    gemm_tn<<<dim3(G4_/BN_, MALL_/BM_), 256>>>(pAc, pWpre, pBpre, pPre, MALL_, G4_, DC_);

    const int ar_smem = SM_TOT * (int)sizeof(float);  // 88448 B
    cudaFuncSetAttribute(ar_kernel, cudaFuncAttributeMaxDynamicSharedMemorySize, ar_smem);
    ar_kernel<<<NB_AR, 384, ar_smem>>>(post_w, post_b, emb_w, (float*)d_out);
}

// round 7
// speedup vs baseline: 1.7513x; 1.0636x over previous
#include <cuda_runtime.h>
#include <math.h>

#define B_    8
#define T_    512
#define F_    229
#define C1_   48
#define C3_   96
#define FP1_  114
#define FP2_  57
#define DC_   768
#define FCIN_ 5472
#define G4_   3072
#define K1P_  1024   /* [emb 176 + pad 80 -> 256 | h1 768] */
#define K2_   1536
#define NP_   88
#define MALL_ 4096
#define NB_AR 128

typedef unsigned long long u64t;

// ---------------- f32x2 helpers ----------------
__device__ __forceinline__ void fma2(u64t &acc, u64t a, u64t b) {
    asm("fma.rn.f32x2 %0, %1, %2, %0;" : "+l"(acc) : "l"(a), "l"(b));
}
__device__ __forceinline__ u64t pk2(float lo, float hi) {
    u64t r;
    asm("mov.b64 %0, {%1, %2};" : "=l"(r) : "r"(__float_as_uint(lo)), "r"(__float_as_uint(hi)));
    return r;
}
__device__ __forceinline__ float2 upk2(u64t v) {
    unsigned lo, hi;
    asm("mov.b64 {%0, %1}, %2;" : "=r"(lo), "=r"(hi) : "l"(v));
    return make_float2(__uint_as_float(lo), __uint_as_float(hi));
}
__device__ __forceinline__ float psum(u64t v) {
    float2 f = upk2(v);
    return f.x + f.y;
}

// ---------------- device scratch ----------------
__device__ float g_conv1[B_*C1_*T_*F_];
__device__ float g_conv2[B_*C1_*T_*FP1_];
__device__ float g_Amat[MALL_*FCIN_];
__device__ float g_ac[MALL_*DC_];
__device__ float g_pre[MALL_*G4_];
__device__ float g_W1r[G4_*K1P_];
__device__ float g_W2r[G4_*K2_];
__device__ float g_Wpre[G4_*DC_];
__device__ float g_bpre[G4_];
__device__ float g_b2v[G4_];
__device__ float g_wf1[C1_*9],      g_bf1[C1_];
__device__ float g_wf2[C1_*C1_*9],  g_bf2[C1_];
__device__ float g_wf3[C3_*C1_*9],  g_bf3[C3_];
__device__ float g_h1[2][B_][DC_], g_h2[2][B_][DC_];
__device__ int   g_prev[B_][NP_];
__device__ unsigned g_cnt2;
__device__ volatile unsigned g_rel2;

// ---------------- prep ----------------
__global__ void prep_kernel(
    const float* __restrict__ c1w, const float* __restrict__ c1b,
    const float* __restrict__ b1g, const float* __restrict__ b1b,
    const float* __restrict__ b1m, const float* __restrict__ b1v,
    const float* __restrict__ c2w, const float* __restrict__ c2b,
    const float* __restrict__ b2g, const float* __restrict__ b2b,
    const float* __restrict__ b2m, const float* __restrict__ b2v,
    const float* __restrict__ c3w, const float* __restrict__ c3b,
    const float* __restrict__ b3g, const float* __restrict__ b3b,
    const float* __restrict__ b3m, const float* __restrict__ b3v,
    const float* __restrict__ wih1, const float* __restrict__ whh1,
    const float* __restrict__ bih1, const float* __restrict__ bhh1,
    const float* __restrict__ wih2, const float* __restrict__ whh2,
    const float* __restrict__ bih2, const float* __restrict__ bhh2)
{
    const int st = gridDim.x * blockDim.x;
    const int t0 = blockIdx.x * blockDim.x + threadIdx.x;
    const float eps = 1e-5f;

    for (int i = t0; i < C1_*9; i += st) { int c = i/9;        g_wf1[i] = c1w[i] * (b1g[c]*rsqrtf(b1v[c]+eps)); }
    for (int i = t0; i < C1_;  i += st)  g_bf1[i] = (c1b[i]-b1m[i])*(b1g[i]*rsqrtf(b1v[i]+eps)) + b1b[i];
    for (int i = t0; i < C1_*C1_*9; i += st) { int c = i/(C1_*9); g_wf2[i] = c2w[i] * (b2g[c]*rsqrtf(b2v[c]+eps)); }
    for (int i = t0; i < C1_;  i += st)  g_bf2[i] = (c2b[i]-b2m[i])*(b2g[i]*rsqrtf(b2v[i]+eps)) + b2b[i];
    for (int i = t0; i < C3_*C1_*9; i += st) { int c = i/(C1_*9); g_wf3[i] = c3w[i] * (b3g[c]*rsqrtf(b3v[c]+eps)); }
    for (int i = t0; i < C3_;  i += st)  g_bf3[i] = (c3b[i]-b3m[i])*(b3g[i]*rsqrtf(b3v[i]+eps)) + b3b[i];

    // W1r layout: rows n = cell*4+g; cols [0,176)=wih1 emb part, [176,256)=0, [256,1024)=whh1
    for (int i = t0; i < G4_*K1P_; i += st) {
        int n = i >> 10, k = i & (K1P_-1);
        int m = n >> 2, g = n & 3, orig = g*DC_ + m;
        float v = 0.f;
        if (k < 176)       v = wih1[orig*944 + 768 + k];
        else if (k >= 256) v = whh1[orig*DC_ + (k - 256)];
        g_W1r[i] = v;
    }
    // W2r: cols [0,768)=wih2, [768,1536)=whh2
    for (int i = t0; i < G4_*K2_; i += st) {
        int n = i / K2_, k = i - n*K2_;
        int m = n >> 2, g = n & 3, orig = g*DC_ + m;
        g_W2r[i] = (k < DC_) ? wih2[orig*DC_ + k] : whh2[orig*DC_ + (k - DC_)];
    }
    // Wpre: acoustic part of wih1, reordered rows
    for (int i = t0; i < G4_*DC_; i += st) {
        int n = i / DC_, k = i - n*DC_;
        int m = n >> 2, g = n & 3, orig = g*DC_ + m;
        g_Wpre[i] = wih1[orig*944 + k];
    }
    for (int i = t0; i < G4_; i += st) {
        int m = i >> 2, g = i & 3, orig = g*DC_ + m;
        g_bpre[i] = bih1[orig] + bhh1[orig];
        g_b2v[i]  = bih2[orig] + bhh2[orig];
    }
    for (int i = t0; i < B_*DC_; i += st) {
        (&g_h1[0][0][0])[i] = 0.f;
        (&g_h2[0][0][0])[i] = 0.f;
    }
    for (int i = t0; i < B_*NP_; i += st) (&g_prev[0][0])[i] = 0;
    if (t0 == 0) { g_cnt2 = 0u; g_rel2 = 0u; }
}

// ---------------- conv1 ----------------
__global__ void conv1_kernel(const float* __restrict__ mel)
{
    int t = blockIdx.x, b = blockIdx.y, f = threadIdx.x;
    __shared__ float ws[C1_*9];
    __shared__ float bs[C1_];
    for (int i = threadIdx.x; i < C1_*9; i += 256) ws[i] = g_wf1[i];
    for (int i = threadIdx.x; i < C1_;  i += 256) bs[i] = g_bf1[i];
    __syncthreads();
    if (f >= F_) return;

    float x[9];
#pragma unroll
    for (int dt = 0; dt < 3; dt++)
#pragma unroll
        for (int df = 0; df < 3; df++) {
            int tt = t - 1 + dt, ff = f - 1 + df;
            x[dt*3+df] = (tt >= 0 && tt < T_ && ff >= 0 && ff < F_)
                         ? mel[(b*T_ + tt)*F_ + ff] : 0.f;
        }
    for (int c = 0; c < C1_; c++) {
        float a = bs[c];
#pragma unroll
        for (int k = 0; k < 9; k++) a += ws[c*9+k] * x[k];
        g_conv1[((b*C1_ + c)*T_ + t)*F_ + f] = fmaxf(a, 0.f);
    }
}

// ---------------- conv2 ----------------
__global__ __launch_bounds__(256) void conv2_kernel()
{
    int t0 = blockIdx.x * 4, b = blockIdx.y, ch = blockIdx.z;
    int f = threadIdx.x;
    __shared__ float ws[8*C1_*9];
    __shared__ float ys[4][232];
    for (int i = threadIdx.x; i < 8*C1_*9; i += 256) ws[i] = g_wf2[ch*8*C1_*9 + i];
    __syncthreads();

    float acc[8][4];
#pragma unroll
    for (int cc = 0; cc < 8; cc++) {
        float bv = g_bf2[ch*8 + cc];
#pragma unroll
        for (int tt = 0; tt < 4; tt++) acc[cc][tt] = bv;
    }
    if (f < F_) {
        for (int ci = 0; ci < C1_; ci++) {
            const float* base = g_conv1 + ((b*C1_ + ci)*T_)*F_;
            float xr[6][3];
#pragma unroll
            for (int j = 0; j < 6; j++) {
                int tt = t0 - 1 + j;
#pragma unroll
                for (int d = 0; d < 3; d++) {
                    int ff = f - 1 + d;
                    xr[j][d] = (tt >= 0 && tt < T_ && ff >= 0 && ff < F_)
                               ? base[tt*F_ + ff] : 0.f;
                }
            }
#pragma unroll
            for (int cc = 0; cc < 8; cc++) {
                const float* w = &ws[(cc*C1_ + ci)*9];
                float w0=w[0],w1=w[1],w2=w[2],w3=w[3],w4=w[4],w5=w[5],w6=w[6],w7=w[7],w8=w[8];
#pragma unroll
                for (int tt = 0; tt < 4; tt++) {
                    acc[cc][tt] += w0*xr[tt  ][0] + w1*xr[tt  ][1] + w2*xr[tt  ][2]
                                 + w3*xr[tt+1][0] + w4*xr[tt+1][1] + w5*xr[tt+1][2]
                                 + w6*xr[tt+2][0] + w7*xr[tt+2][1] + w8*xr[tt+2][2];
                }
            }
        }
    }
    for (int cc = 0; cc < 8; cc++) {
        __syncthreads();
        if (f < F_) {
#pragma unroll
            for (int tt = 0; tt < 4; tt++) ys[tt][f] = fmaxf(acc[cc][tt], 0.f);
        }
        __syncthreads();
        if (f < FP1_) {
            int c = ch*8 + cc;
#pragma unroll
            for (int tt = 0; tt < 4; tt++)
                g_conv2[((b*C1_ + c)*T_ + t0 + tt)*FP1_ + f] =
                    fmaxf(ys[tt][2*f], ys[tt][2*f+1]);
        }
    }
}

// ---------------- conv3 ----------------
__global__ __launch_bounds__(128) void conv3_kernel()
{
    int t0 = blockIdx.x * 4, b = blockIdx.y, ch = blockIdx.z;
    int f = threadIdx.x;
    __shared__ float ws[8*C1_*9];
    __shared__ float ys[4][116];
    for (int i = threadIdx.x; i < 8*C1_*9; i += 128) ws[i] = g_wf3[ch*8*C1_*9 + i];
    __syncthreads();

    float acc[8][4];
#pragma unroll
    for (int cc = 0; cc < 8; cc++) {
        float bv = g_bf3[ch*8 + cc];
#pragma unroll
        for (int tt = 0; tt < 4; tt++) acc[cc][tt] = bv;
    }
    if (f < FP1_) {
        for (int ci = 0; ci < C1_; ci++) {
            const float* base = g_conv2 + ((b*C1_ + ci)*T_)*FP1_;
            float xr[6][3];
#pragma unroll
            for (int j = 0; j < 6; j++) {
                int tt = t0 - 1 + j;
#pragma unroll
                for (int d = 0; d < 3; d++) {
                    int ff = f - 1 + d;
                    xr[j][d] = (tt >= 0 && tt < T_ && ff >= 0 && ff < FP1_)
                               ? base[tt*FP1_ + ff] : 0.f;
                }
            }
#pragma unroll
            for (int cc = 0; cc < 8; cc++) {
                const float* w = &ws[(cc*C1_ + ci)*9];
                float w0=w[0],w1=w[1],w2=w[2],w3=w[3],w4=w[4],w5=w[5],w6=w[6],w7=w[7],w8=w[8];
#pragma unroll
                for (int tt = 0; tt < 4; tt++) {
                    acc[cc][tt] += w0*xr[tt  ][0] + w1*xr[tt  ][1] + w2*xr[tt  ][2]
                                 + w3*xr[tt+1][0] + w4*xr[tt+1][1] + w5*xr[tt+1][2]
                                 + w6*xr[tt+2][0] + w7*xr[tt+2][1] + w8*xr[tt+2][2];
                }
            }
        }
    }
    for (int cc = 0; cc < 8; cc++) {
        __syncthreads();
        if (f < FP1_) {
#pragma unroll
            for (int tt = 0; tt < 4; tt++) ys[tt][f] = fmaxf(acc[cc][tt], 0.f);
        }
        __syncthreads();
        if (f < FP2_) {
            int c = ch*8 + cc;
#pragma unroll
            for (int tt = 0; tt < 4; tt++)
                g_Amat[(b*T_ + t0 + tt)*FCIN_ + c*FP2_ + f] =
                    fmaxf(ys[tt][2*f], ys[tt][2*f+1]);
        }
    }
}

// ---------------- GEMM (unchanged) ----------------
#define BM_ 128
#define BN_ 128
#define BK_ 16

__global__ __launch_bounds__(256) void gemm_tn(
    const float* __restrict__ A, const float* __restrict__ Bm,
    const float* __restrict__ bias, float* __restrict__ C,
    int M, int N, int K)
{
    __shared__ float As[2][BK_][BM_];
    __shared__ float Bs[2][BK_][BN_];

    const int tid = threadIdx.x;
    const int m0 = blockIdx.y * BM_, n0 = blockIdx.x * BN_;

    const int lr = tid >> 2;
    const int lk = (tid & 3) * 4;
    const float* Ap = A + (size_t)(m0 + lr) * K + lk;
    const float* Bp = Bm + (size_t)(n0 + lr) * K + lk;
    const size_t rowK = (size_t)64 * K;

    const int warp = tid >> 5, lane = tid & 31;
    const int wm = warp & 3, wn = warp >> 2;
    const int lm = lane >> 3, ln = lane & 7;
    const int row0 = wm * 32 + lm * 8;
    const int col0 = wn * 64 + ln * 8;

    u64t acc2[8][4];
#pragma unroll
    for (int i = 0; i < 8; i++)
#pragma unroll
        for (int j = 0; j < 4; j++) acc2[i][j] = 0ull;

    {
        float4 a0 = *(const float4*)(Ap);
        float4 a1 = *(const float4*)(Ap + rowK);
        float4 b0 = *(const float4*)(Bp);
        float4 b1 = *(const float4*)(Bp + rowK);
        As[0][lk+0][lr] = a0.x; As[0][lk+1][lr] = a0.y; As[0][lk+2][lr] = a0.z; As[0][lk+3][lr] = a0.w;
        As[0][lk+0][lr+64] = a1.x; As[0][lk+1][lr+64] = a1.y; As[0][lk+2][lr+64] = a1.z; As[0][lk+3][lr+64] = a1.w;
        Bs[0][lk+0][lr] = b0.x; Bs[0][lk+1][lr] = b0.y; Bs[0][lk+2][lr] = b0.z; Bs[0][lk+3][lr] = b0.w;
        Bs[0][lk+0][lr+64] = b1.x; Bs[0][lk+1][lr+64] = b1.y; Bs[0][lk+2][lr+64] = b1.z; Bs[0][lk+3][lr+64] = b1.w;
    }
    __syncthreads();

    const int nkt = K >> 4;
    int cur = 0;
    for (int kt = 0; kt < nkt; kt++) {
        float4 pa0, pa1, pb0, pb1;
        const bool has = (kt + 1 < nkt);
        if (has) {
            int ko = (kt + 1) << 4;
            pa0 = *(const float4*)(Ap + ko);
            pa1 = *(const float4*)(Ap + rowK + ko);
            pb0 = *(const float4*)(Bp + ko);
            pb1 = *(const float4*)(Bp + rowK + ko);
        }
#pragma unroll
        for (int kk = 0; kk < BK_; kk++) {
            float4 av0 = *(const float4*)&As[cur][kk][row0];
            float4 av1 = *(const float4*)&As[cur][kk][row0 + 4];
            float4 bv0 = *(const float4*)&Bs[cur][kk][col0];
            float4 bv1 = *(const float4*)&Bs[cur][kk][col0 + 4];
            u64t b2[4];
            b2[0] = pk2(bv0.x, bv0.y); b2[1] = pk2(bv0.z, bv0.w);
            b2[2] = pk2(bv1.x, bv1.y); b2[3] = pk2(bv1.z, bv1.w);
            float a[8] = {av0.x, av0.y, av0.z, av0.w, av1.x, av1.y, av1.z, av1.w};
#pragma unroll
            for (int i = 0; i < 8; i++) {
                u64t ai = pk2(a[i], a[i]);
#pragma unroll
                for (int j = 0; j < 4; j++)
                    fma2(acc2[i][j], ai, b2[j]);
            }
        }
        if (has) {
            int nb = cur ^ 1;
            As[nb][lk+0][lr] = pa0.x; As[nb][lk+1][lr] = pa0.y; As[nb][lk+2][lr] = pa0.z; As[nb][lk+3][lr] = pa0.w;
            As[nb][lk+0][lr+64] = pa1.x; As[nb][lk+1][lr+64] = pa1.y; As[nb][lk+2][lr+64] = pa1.z; As[nb][lk+3][lr+64] = pa1.w;
            Bs[nb][lk+0][lr] = pb0.x; Bs[nb][lk+1][lr] = pb0.y; Bs[nb][lk+2][lr] = pb0.z; Bs[nb][lk+3][lr] = pb0.w;
            Bs[nb][lk+0][lr+64] = pb1.x; Bs[nb][lk+1][lr+64] = pb1.y; Bs[nb][lk+2][lr+64] = pb1.z; Bs[nb][lk+3][lr+64] = pb1.w;
        }
        __syncthreads();
        cur ^= 1;
    }

    float bv[8];
#pragma unroll
    for (int j = 0; j < 8; j++) bv[j] = bias[n0 + col0 + j];
#pragma unroll
    for (int i = 0; i < 8; i++) {
        float* Cp = C + (size_t)(m0 + row0 + i) * N + n0 + col0;
        float2 r0 = upk2(acc2[i][0]), r1 = upk2(acc2[i][1]);
        float2 r2 = upk2(acc2[i][2]), r3 = upk2(acc2[i][3]);
        float4 o0 = make_float4(r0.x+bv[0], r0.y+bv[1], r1.x+bv[2], r1.y+bv[3]);
        float4 o1 = make_float4(r2.x+bv[4], r2.y+bv[5], r3.x+bv[6], r3.y+bv[7]);
        *(float4*)(Cp)     = o0;
        *(float4*)(Cp + 4) = o1;
    }
}

// ---------------- AR persistent kernel ----------------
__device__ __forceinline__ float warp_sum(float s)
{
    s += __shfl_xor_sync(0xffffffffu, s, 16);
    s += __shfl_xor_sync(0xffffffffu, s, 8);
    s += __shfl_xor_sync(0xffffffffu, s, 4);
    s += __shfl_xor_sync(0xffffffffu, s, 2);
    s += __shfl_xor_sync(0xffffffffu, s, 1);
    return s;
}
__device__ __forceinline__ float sigm(float x) { return 1.f / (1.f + expf(-x)); }

__device__ __forceinline__ void gbar(unsigned gen)
{
    __syncthreads();
    if (threadIdx.x == 0) {
        __threadfence();
        unsigned a = atomicAdd(&g_cnt2, 1u) + 1u;
        if (a == gen * NB_AR) {
            g_rel2 = gen;
        } else {
            while (g_rel2 < gen) { }
        }
    }
    __syncthreads();
}

// staged pairwise reduction: 32 values across 32 lanes; result for index L lands on lane L in v[0]
__device__ __forceinline__ void reduce32(float* v, int lane)
{
#pragma unroll
    for (int o = 16; o > 0; o >>= 1) {
        bool hi = (lane & o) != 0;
#pragma unroll
        for (int i = 0; i < o; i++) {
            float a0 = v[i], a1 = v[i + o];
            float mine = hi ? a1 : a0;
            float send = hi ? a0 : a1;
            float other = __shfl_xor_sync(0xffffffffu, send, o);
            v[i] = mine + other;
        }
    }
}

// GEMV partial: 4 gate rows x 8 batches; K-range NITER*128 elements
template<int NITER>
__device__ __forceinline__ void gemv_part(
    const float* __restrict__ Wb, int wstride,
    const float* xb, int xstride, int lane, float* v)
{
    u64t acc[4][8];
#pragma unroll
    for (int r = 0; r < 4; r++)
#pragma unroll
        for (int b = 0; b < 8; b++) acc[r][b] = 0ull;

#pragma unroll
    for (int it = 0; it < NITER; it++) {
        int off = it * 128 + lane * 4;
        float4 w0 = *(const float4*)(Wb              + off);
        float4 w1 = *(const float4*)(Wb +   wstride  + off);
        float4 w2 = *(const float4*)(Wb + 2*wstride  + off);
        float4 w3 = *(const float4*)(Wb + 3*wstride  + off);
        u64t wp[4][2];
        wp[0][0] = pk2(w0.x, w0.y); wp[0][1] = pk2(w0.z, w0.w);
        wp[1][0] = pk2(w1.x, w1.y); wp[1][1] = pk2(w1.z, w1.w);
        wp[2][0] = pk2(w2.x, w2.y); wp[2][1] = pk2(w2.z, w2.w);
        wp[3][0] = pk2(w3.x, w3.y); wp[3][1] = pk2(w3.z, w3.w);
#pragma unroll
        for (int b = 0; b < 8; b++) {
            float4 x = *(const float4*)(xb + b*xstride + off);
            u64t x0 = pk2(x.x, x.y), x1 = pk2(x.z, x.w);
            fma2(acc[0][b], wp[0][0], x0); fma2(acc[0][b], wp[0][1], x1);
            fma2(acc[1][b], wp[1][0], x0); fma2(acc[1][b], wp[1][1], x1);
            fma2(acc[2][b], wp[2][0], x0); fma2(acc[2][b], wp[2][1], x1);
            fma2(acc[3][b], wp[3][0], x0); fma2(acc[3][b], wp[3][1], x1);
        }
    }
#pragma unroll
    for (int r = 0; r < 4; r++)
#pragma unroll
        for (int b = 0; b < 8; b++) v[r*8 + b] = psum(acc[r][b]);
}

// smem float offsets (total 58080 floats = 232320 B <= 232448 B limit)
#define SW2   0        /* 6*4*1536 = 36864 : LSTM2 weights (block's 6 cells) */
#define SWP   36864    /* 2*5*768  =  7680 : post weights (block's 2 tasks) */
#define SXS   44544    /* 8*1536   = 12288 : [emb/h1 | h2] staging */
#define SP2   56832    /* 12*32 = 384 : partials (phase A reuses as pe) */
#define SPH   57216    /* 384 : deferred h1 partials */
#define SPRE  57600    /* 2*192 : g_pre prefetch double-buffer */
#define SC1   57984    /* 48 */
#define SC2   58032    /* 48 */
#define STOT  58080

__global__ __launch_bounds__(384, 1) void ar_kernel(
    const float* __restrict__ postw, const float* __restrict__ postb,
    const float* __restrict__ embw, float* __restrict__ out)
{
    extern __shared__ float sm[];
    float* w2s  = sm + SW2;
    float* wps  = sm + SWP;
    float* xs2  = sm + SXS;
    float* p2   = sm + SP2;
    float* ph   = sm + SPH;
    float* preS = sm + SPRE;
    float* c1s  = sm + SC1;
    float* c2s  = sm + SC2;

    const int tid = threadIdx.x, lane = tid & 31, warp = tid >> 5;
    const int cl = warp >> 1, half = warp & 1;
    const int cell = blockIdx.x * 6 + cl;

    // ---- one-time loads: LSTM2 weight slice + post weight slices ----
    {
        const float4* src = (const float4*)(g_W2r + (size_t)blockIdx.x * 6 * 4 * K2_);
        float4* dst = (float4*)w2s;
        for (int i = tid; i < 6*4*K2_/4; i += 384) dst[i] = src[i];
    }
    {
        const float4* s0 = (const float4*)(postw + (size_t)(blockIdx.x >> 1) * 5 * DC_);
        float4* d0 = (float4*)wps;
        for (int i = tid; i < 5*DC_/4; i += 384) d0[i] = s0[i];
        if (blockIdx.x < 48) {
            const float4* s1 = (const float4*)(postw + (size_t)((NB_AR + blockIdx.x) >> 1) * 5 * DC_);
            float4* d1 = (float4*)(wps + 5*DC_);
            for (int i = tid; i < 5*DC_/4; i += 384) d1[i] = s1[i];
        }
    }
    // init state
    for (int i = tid; i < 12288; i += 384) xs2[i] = 0.f;
    for (int i = tid; i < 384;   i += 384) ph[i] = 0.f;
    if (tid < 48) { c1s[tid] = 0.f; c2s[tid] = 0.f; }
    if (tid < 192) {
        int b = tid / 24, j = tid - b*24;
        preS[tid] = __ldg(&g_pre[(size_t)(b*T_)*G4_ + blockIdx.x*24 + j]);
    }
    __syncthreads();

    float v[32];
    unsigned gen = 0;

    for (int t = 0; t < T_; t++) {
        const int wr = (t & 1) ^ 1, pbuf = t & 1;

        // ======== Phase A: emb-part GEMV + combine -> h1_new ========
        for (int i = tid; i < B_*176; i += 384) {
            int b = i / 176, k = i - b*176;
            xs2[b*K2_ + k] = embw[__ldcg((const int*)&g_prev[b][k >> 1]) * 2 + (k & 1)];
        }
        __syncthreads();
        gemv_part<1>(g_W1r + (size_t)cell*4*K1P_ + half*128, K1P_,
                     xs2 + half*128, K2_, lane, v);
        reduce32(v, lane);
        p2[warp*32 + lane] = v[0];
        __syncthreads();
        if (tid < 48) {
            int c = tid >> 3, b = tid & 7;
            int mycell = blockIdx.x*6 + c;
            float z[4];
#pragma unroll
            for (int r = 0; r < 4; r++) {
                int idx = r*8 + b;
                z[r] = p2[(c*2)*32 + idx] + p2[(c*2+1)*32 + idx]
                     + ph[(c*2)*32 + idx] + ph[(c*2+1)*32 + idx]
                     + preS[pbuf*192 + b*24 + c*4 + r];
            }
            float co = c1s[tid];
            float ig = sigm(z[0]), fg = sigm(z[1]);
            float gg = tanhf(z[2]), og = sigm(z[3]);
            float cn = fg*co + ig*gg;
            c1s[tid] = cn;
            g_h1[wr][b][mycell] = og * tanhf(cn);
        }
        gbar(++gen);

        // ======== Phase B: LSTM2 (weights in smem; h2_old already staged) ========
        for (int i = tid; i < B_*(DC_/4); i += 384) {
            int b = i / (DC_/4), j = i - b*(DC_/4);
            ((float4*)(xs2 + b*K2_))[j] = __ldcg((const float4*)&g_h1[wr][b][0] + j);
        }
        __syncthreads();
        gemv_part<6>(w2s + cl*4*K2_ + half*DC_, K2_,
                     xs2 + half*DC_, K2_, lane, v);
        reduce32(v, lane);
        p2[warp*32 + lane] = v[0];
        __syncthreads();
        if (tid < 48) {
            int c = tid >> 3, b = tid & 7;
            int mycell = blockIdx.x*6 + c;
            float z[4];
#pragma unroll
            for (int r = 0; r < 4; r++) {
                int idx = r*8 + b;
                z[r] = p2[(c*2)*32 + idx] + p2[(c*2+1)*32 + idx]
                     + __ldg(&g_b2v[mycell*4 + r]);
            }
            float co = c2s[tid];
            float ig = sigm(z[0]), fg = sigm(z[1]);
            float gg = tanhf(z[2]), og = sigm(z[3]);
            float cn = fg*co + ig*gg;
            c2s[tid] = cn;
            g_h2[wr][b][mycell] = og * tanhf(cn);
        }
        gbar(++gen);

        // ======== Phase C: stage h2_new (doubles as next h2_old); deferred h1 GEMV; post ========
        for (int i = tid; i < B_*(DC_/4); i += 384) {
            int b = i / (DC_/4), j = i - b*(DC_/4);
            ((float4*)(xs2 + b*K2_ + DC_))[j] = __ldcg((const float4*)&g_h2[wr][b][0] + j);
        }
        if (t + 1 < T_ && tid < 192) {
            int b = tid / 24, j = tid - b*24;
            preS[(pbuf^1)*192 + tid] = __ldg(&g_pre[(size_t)(b*T_ + t + 1)*G4_ + blockIdx.x*24 + j]);
        }
        __syncthreads();

        // deferred h1-part of LSTM1 for next step (x = h1_new in xs2[0:768))
        gemv_part<3>(g_W1r + (size_t)cell*4*K1P_ + 256 + half*384, K1P_,
                     xs2 + half*384, K2_, lane, v);
        reduce32(v, lane);
        ph[warp*32 + lane] = v[0];

        // post GEMV + argmax (weights in smem); task = warp*128 + blockIdx
        if (warp < 2 && (warp == 0 || blockIdx.x < 48)) {
            int task = warp * NB_AR + blockIdx.x;
            int p = task >> 1, bh = (task & 1) * 4;
            const float* Wp = wps + warp * 5 * DC_;
            u64t acc[5][4];
#pragma unroll
            for (int s = 0; s < 5; s++)
#pragma unroll
                for (int b = 0; b < 4; b++) acc[s][b] = 0ull;
#pragma unroll 2
            for (int kb = 0; kb < DC_; kb += 128) {
                int off = kb + lane*4;
                u64t wp[5][2];
#pragma unroll
                for (int s = 0; s < 5; s++) {
                    float4 w = *(const float4*)(Wp + s*DC_ + off);
                    wp[s][0] = pk2(w.x, w.y); wp[s][1] = pk2(w.z, w.w);
                }
#pragma unroll
                for (int b = 0; b < 4; b++) {
                    float4 x = *(const float4*)(xs2 + (bh + b)*K2_ + DC_ + off);
                    u64t x0 = pk2(x.x, x.y), x1 = pk2(x.z, x.w);
#pragma unroll
                    for (int s = 0; s < 5; s++) {
                        fma2(acc[s][b], wp[s][0], x0);
                        fma2(acc[s][b], wp[s][1], x1);
                    }
                }
            }
            float z[5][4];
#pragma unroll
            for (int s = 0; s < 5; s++)
#pragma unroll
                for (int b = 0; b < 4; b++)
                    z[s][b] = warp_sum(psum(acc[s][b]));
            if (lane < 4) {
                int b = bh + lane;
                float* o = out + (size_t)(b*T_ + t)*440 + p*5;
                float best = -1e30f; int bi = 0;
#pragma unroll
                for (int s = 0; s < 5; s++) {
                    float v0 = (lane & 1) ? z[s][1] : z[s][0];
                    float v1 = (lane & 1) ? z[s][3] : z[s][2];
                    float vv = ((lane & 2) ? v1 : v0) + __ldg(&postb[p*5 + s]);
                    o[s] = vv;
                    if (vv > best) { best = vv; bi = s; }
                }
                g_prev[b][p] = bi;
            }
        }
        gbar(++gen);
    }
}

// ---------------- launch ----------------
extern "C" void kernel_launch(void* const* d_in, const int* in_sizes, int n_in,
                              void* d_out, int out_size)
{
    const float* mel    = (const float*)d_in[0];
    const float* c1w    = (const float*)d_in[1];
    const float* c1b    = (const float*)d_in[2];
    const float* b1g    = (const float*)d_in[3];
    const float* b1b    = (const float*)d_in[4];
    const float* b1m    = (const float*)d_in[5];
    const float* b1v    = (const float*)d_in[6];
    const float* c2w    = (const float*)d_in[7];
    const float* c2b    = (const float*)d_in[8];
    const float* b2g    = (const float*)d_in[9];
    const float* b2b    = (const float*)d_in[10];
    const float* b2m    = (const float*)d_in[11];
    const float* b2v    = (const float*)d_in[12];
    const float* c3w    = (const float*)d_in[13];
    const float* c3b    = (const float*)d_in[14];
    const float* b3g    = (const float*)d_in[15];
    const float* b3b    = (const float*)d_in[16];
    const float* b3m    = (const float*)d_in[17];
    const float* b3v    = (const float*)d_in[18];
    const float* fc_w   = (const float*)d_in[19];
    const float* fc_b   = (const float*)d_in[20];
    const float* wih1   = (const float*)d_in[21];
    const float* whh1   = (const float*)d_in[22];
    const float* bih1   = (const float*)d_in[23];
    const float* bhh1   = (const float*)d_in[24];
    const float* wih2   = (const float*)d_in[25];
    const float* whh2   = (const float*)d_in[26];
    const float* bih2   = (const float*)d_in[27];
    const float* bhh2   = (const float*)d_in[28];
    const float* post_w = (const float*)d_in[29];
    const float* post_b = (const float*)d_in[30];
    const float* emb_w  = (const float*)d_in[31];

    prep_kernel<<<2048, 256>>>(c1w, c1b, b1g, b1b, b1m, b1v,
                               c2w, c2b, b2g, b2b, b2m, b2v,
                               c3w, c3b, b3g, b3b, b3m, b3v,
                               wih1, whh1, bih1, bhh1,
                               wih2, whh2, bih2, bhh2);

    conv1_kernel<<<dim3(T_, B_), 256>>>(mel);
    conv2_kernel<<<dim3(T_/4, B_, C1_/8), 256>>>();
    conv3_kernel<<<dim3(T_/4, B_, C3_/8), 128>>>();

    float *pA, *pAc, *pPre, *pWpre, *pBpre;
    cudaGetSymbolAddress((void**)&pA,    g_Amat);
    cudaGetSymbolAddress((void**)&pAc,   g_ac);
    cudaGetSymbolAddress((void**)&pPre,  g_pre);
    cudaGetSymbolAddress((void**)&pWpre, g_Wpre);
    cudaGetSymbolAddress((void**)&pBpre, g_bpre);

    gemm_tn<<<dim3(DC_/BN_, MALL_/BM_), 256>>>(pA, fc_w, fc_b, pAc, MALL_, DC_, FCIN_);
    gemm_tn<<<dim3(G4_/BN_, MALL_/BM_), 256>>>(pAc, pWpre, pBpre, pPre, MALL_, G4_, DC_);

    const int ar_smem = STOT * (int)sizeof(float);  // 232320 B
    cudaFuncSetAttribute(ar_kernel, cudaFuncAttributeMaxDynamicSharedMemorySize, ar_smem);
    ar_kernel<<<NB_AR, 384, ar_smem>>>(post_w, post_b, emb_w, (float*)d_out);
}

// round 8
// speedup vs baseline: 1.9956x; 1.1395x over previous
#include <cuda_runtime.h>
#include <math.h>

#define B_    8
#define T_    512
#define F_    229
#define C1_   48
#define C3_   96
#define FP1_  114
#define FP2_  57
#define DC_   768
#define FCIN_ 5472
#define G4_   3072
#define K1P_  1024   /* [emb 176 + pad 80 -> 256 | h1 768] */
#define K2_   1536
#define NP_   88
#define MALL_ 4096
#define NB_AR 128

typedef unsigned long long u64t;

// ---------------- f32x2 helpers ----------------
__device__ __forceinline__ void fma2(u64t &acc, u64t a, u64t b) {
    asm("fma.rn.f32x2 %0, %1, %2, %0;" : "+l"(acc) : "l"(a), "l"(b));
}
__device__ __forceinline__ u64t pk2(float lo, float hi) {
    u64t r;
    asm("mov.b64 %0, {%1, %2};" : "=l"(r) : "r"(__float_as_uint(lo)), "r"(__float_as_uint(hi)));
    return r;
}
__device__ __forceinline__ float2 upk2(u64t v) {
    unsigned lo, hi;
    asm("mov.b64 {%0, %1}, %2;" : "=r"(lo), "=r"(hi) : "l"(v));
    return make_float2(__uint_as_float(lo), __uint_as_float(hi));
}
__device__ __forceinline__ float psum(u64t v) {
    float2 f = upk2(v);
    return f.x + f.y;
}

// ---------------- device scratch ----------------
__device__ float g_conv1[B_*C1_*T_*F_];
__device__ float g_conv2[B_*C1_*T_*FP1_];
__device__ float g_Amat[MALL_*FCIN_];
__device__ float g_ac[MALL_*DC_];
__device__ float g_pre[MALL_*G4_];
__device__ float g_W1r[G4_*K1P_];
__device__ float g_W2r[G4_*K2_];
__device__ float g_Wpre[G4_*DC_];
__device__ float g_bpre[G4_];
__device__ float g_b2v[G4_];
__device__ float g_wf1[C1_*9],      g_bf1[C1_];
__device__ float g_wf2[C1_*C1_*9],  g_bf2[C1_];
__device__ float g_wf3[C3_*C1_*9],  g_bf3[C3_];
__device__ float g_h1[2][B_][DC_], g_h2[2][B_][DC_];
__device__ float g_xemb[B_][176];
__device__ unsigned g_cnt2;
__device__ volatile unsigned g_rel2;

// ---------------- prep ----------------
__global__ void prep_kernel(
    const float* __restrict__ c1w, const float* __restrict__ c1b,
    const float* __restrict__ b1g, const float* __restrict__ b1b,
    const float* __restrict__ b1m, const float* __restrict__ b1v,
    const float* __restrict__ c2w, const float* __restrict__ c2b,
    const float* __restrict__ b2g, const float* __restrict__ b2b,
    const float* __restrict__ b2m, const float* __restrict__ b2v,
    const float* __restrict__ c3w, const float* __restrict__ c3b,
    const float* __restrict__ b3g, const float* __restrict__ b3b,
    const float* __restrict__ b3m, const float* __restrict__ b3v,
    const float* __restrict__ wih1, const float* __restrict__ whh1,
    const float* __restrict__ bih1, const float* __restrict__ bhh1,
    const float* __restrict__ wih2, const float* __restrict__ whh2,
    const float* __restrict__ bih2, const float* __restrict__ bhh2,
    const float* __restrict__ embw)
{
    const int st = gridDim.x * blockDim.x;
    const int t0 = blockIdx.x * blockDim.x + threadIdx.x;
    const float eps = 1e-5f;

    for (int i = t0; i < C1_*9; i += st) { int c = i/9;        g_wf1[i] = c1w[i] * (b1g[c]*rsqrtf(b1v[c]+eps)); }
    for (int i = t0; i < C1_;  i += st)  g_bf1[i] = (c1b[i]-b1m[i])*(b1g[i]*rsqrtf(b1v[i]+eps)) + b1b[i];
    for (int i = t0; i < C1_*C1_*9; i += st) { int c = i/(C1_*9); g_wf2[i] = c2w[i] * (b2g[c]*rsqrtf(b2v[c]+eps)); }
    for (int i = t0; i < C1_;  i += st)  g_bf2[i] = (c2b[i]-b2m[i])*(b2g[i]*rsqrtf(b2v[i]+eps)) + b2b[i];
    for (int i = t0; i < C3_*C1_*9; i += st) { int c = i/(C1_*9); g_wf3[i] = c3w[i] * (b3g[c]*rsqrtf(b3v[c]+eps)); }
    for (int i = t0; i < C3_;  i += st)  g_bf3[i] = (c3b[i]-b3m[i])*(b3g[i]*rsqrtf(b3v[i]+eps)) + b3b[i];

    // W1r layout: rows n = cell*4+g; cols [0,176)=wih1 emb part, [176,256)=0, [256,1024)=whh1
    for (int i = t0; i < G4_*K1P_; i += st) {
        int n = i >> 10, k = i & (K1P_-1);
        int m = n >> 2, g = n & 3, orig = g*DC_ + m;
        float v = 0.f;
        if (k < 176)       v = wih1[orig*944 + 768 + k];
        else if (k >= 256) v = whh1[orig*DC_ + (k - 256)];
        g_W1r[i] = v;
    }
    // W2r: cols [0,768)=wih2, [768,1536)=whh2
    for (int i = t0; i < G4_*K2_; i += st) {
        int n = i / K2_, k = i - n*K2_;
        int m = n >> 2, g = n & 3, orig = g*DC_ + m;
        g_W2r[i] = (k < DC_) ? wih2[orig*DC_ + k] : whh2[orig*DC_ + (k - DC_)];
    }
    // Wpre: acoustic part of wih1, reordered rows
    for (int i = t0; i < G4_*DC_; i += st) {
        int n = i / DC_, k = i - n*DC_;
        int m = n >> 2, g = n & 3, orig = g*DC_ + m;
        g_Wpre[i] = wih1[orig*944 + k];
    }
    for (int i = t0; i < G4_; i += st) {
        int m = i >> 2, g = i & 3, orig = g*DC_ + m;
        g_bpre[i] = bih1[orig] + bhh1[orig];
        g_b2v[i]  = bih2[orig] + bhh2[orig];
    }
    for (int i = t0; i < B_*DC_; i += st) {
        (&g_h1[0][0][0])[i] = 0.f;
        (&g_h2[0][0][0])[i] = 0.f;
    }
    // prev state = 0 -> emb row 0
    for (int i = t0; i < B_*176; i += st)
        (&g_xemb[0][0])[i] = embw[i & 1];
    if (t0 == 0) { g_cnt2 = 0u; g_rel2 = 0u; }
}

// ---------------- conv1 ----------------
__global__ void conv1_kernel(const float* __restrict__ mel)
{
    int t = blockIdx.x, b = blockIdx.y, f = threadIdx.x;
    __shared__ float ws[C1_*9];
    __shared__ float bs[C1_];
    for (int i = threadIdx.x; i < C1_*9; i += 256) ws[i] = g_wf1[i];
    for (int i = threadIdx.x; i < C1_;  i += 256) bs[i] = g_bf1[i];
    __syncthreads();
    if (f >= F_) return;

    float x[9];
#pragma unroll
    for (int dt = 0; dt < 3; dt++)
#pragma unroll
        for (int df = 0; df < 3; df++) {
            int tt = t - 1 + dt, ff = f - 1 + df;
            x[dt*3+df] = (tt >= 0 && tt < T_ && ff >= 0 && ff < F_)
                         ? mel[(b*T_ + tt)*F_ + ff] : 0.f;
        }
    for (int c = 0; c < C1_; c++) {
        float a = bs[c];
#pragma unroll
        for (int k = 0; k < 9; k++) a += ws[c*9+k] * x[k];
        g_conv1[((b*C1_ + c)*T_ + t)*F_ + f] = fmaxf(a, 0.f);
    }
}

// ---------------- conv2: f32x2, weights pair-packed in smem ----------------
__global__ __launch_bounds__(256) void conv2_kernel()
{
    int t0 = blockIdx.x * 4, b = blockIdx.y, ch = blockIdx.z;
    int f = threadIdx.x;
    __shared__ u64t ws2[4*C1_*9];
    __shared__ float ys[4][232];
    for (int i = threadIdx.x; i < 4*C1_*9; i += 256) {
        int p = i / (C1_*9), r = i - p*(C1_*9);
        ws2[i] = pk2(g_wf2[(ch*8 + 2*p)*C1_*9 + r],
                     g_wf2[(ch*8 + 2*p + 1)*C1_*9 + r]);
    }
    __syncthreads();

    u64t acc2[4][4];
#pragma unroll
    for (int p = 0; p < 4; p++) {
        u64t bp = pk2(g_bf2[ch*8 + 2*p], g_bf2[ch*8 + 2*p + 1]);
#pragma unroll
        for (int tt = 0; tt < 4; tt++) acc2[p][tt] = bp;
    }

    if (f < F_) {
        for (int ci = 0; ci < C1_; ci++) {
            const float* base = g_conv1 + ((b*C1_ + ci)*T_)*F_;
            float xr[6][3];
#pragma unroll
            for (int j = 0; j < 6; j++) {
                int tt = t0 - 1 + j;
#pragma unroll
                for (int d = 0; d < 3; d++) {
                    int ff = f - 1 + d;
                    xr[j][d] = (tt >= 0 && tt < T_ && ff >= 0 && ff < F_)
                               ? base[tt*F_ + ff] : 0.f;
                }
            }
#pragma unroll
            for (int k = 0; k < 9; k++) {
                const int dt = k / 3, df = k % 3;
                u64t xk0 = pk2(xr[dt  ][df], xr[dt  ][df]);
                u64t xk1 = pk2(xr[dt+1][df], xr[dt+1][df]);
                u64t xk2 = pk2(xr[dt+2][df], xr[dt+2][df]);
                u64t xk3 = pk2(xr[dt+3][df], xr[dt+3][df]);
#pragma unroll
                for (int p = 0; p < 4; p++) {
                    u64t wv = ws2[(p*C1_ + ci)*9 + k];
                    fma2(acc2[p][0], wv, xk0);
                    fma2(acc2[p][1], wv, xk1);
                    fma2(acc2[p][2], wv, xk2);
                    fma2(acc2[p][3], wv, xk3);
                }
            }
        }
    }
    float acc[8][4];
#pragma unroll
    for (int p = 0; p < 4; p++)
#pragma unroll
        for (int tt = 0; tt < 4; tt++) {
            float2 u = upk2(acc2[p][tt]);
            acc[2*p][tt] = u.x; acc[2*p+1][tt] = u.y;
        }

    for (int cc = 0; cc < 8; cc++) {
        __syncthreads();
        if (f < F_) {
#pragma unroll
            for (int tt = 0; tt < 4; tt++) ys[tt][f] = fmaxf(acc[cc][tt], 0.f);
        }
        __syncthreads();
        if (f < FP1_) {
            int c = ch*8 + cc;
#pragma unroll
            for (int tt = 0; tt < 4; tt++)
                g_conv2[((b*C1_ + c)*T_ + t0 + tt)*FP1_ + f] =
                    fmaxf(ys[tt][2*f], ys[tt][2*f+1]);
        }
    }
}

// ---------------- conv3: f32x2, weights pair-packed in smem ----------------
__global__ __launch_bounds__(128) void conv3_kernel()
{
    int t0 = blockIdx.x * 4, b = blockIdx.y, ch = blockIdx.z;
    int f = threadIdx.x;
    __shared__ u64t ws2[4*C1_*9];
    __shared__ float ys[4][116];
    for (int i = threadIdx.x; i < 4*C1_*9; i += 128) {
        int p = i / (C1_*9), r = i - p*(C1_*9);
        ws2[i] = pk2(g_wf3[(ch*8 + 2*p)*C1_*9 + r],
                     g_wf3[(ch*8 + 2*p + 1)*C1_*9 + r]);
    }
    __syncthreads();

    u64t acc2[4][4];
#pragma unroll
    for (int p = 0; p < 4; p++) {
        u64t bp = pk2(g_bf3[ch*8 + 2*p], g_bf3[ch*8 + 2*p + 1]);
#pragma unroll
        for (int tt = 0; tt < 4; tt++) acc2[p][tt] = bp;
    }

    if (f < FP1_) {
        for (int ci = 0; ci < C1_; ci++) {
            const float* base = g_conv2 + ((b*C1_ + ci)*T_)*FP1_;
            float xr[6][3];
#pragma unroll
            for (int j = 0; j < 6; j++) {
                int tt = t0 - 1 + j;
#pragma unroll
                for (int d = 0; d < 3; d++) {
                    int ff = f - 1 + d;
                    xr[j][d] = (tt >= 0 && tt < T_ && ff >= 0 && ff < FP1_)
                               ? base[tt*FP1_ + ff] : 0.f;
                }
            }
#pragma unroll
            for (int k = 0; k < 9; k++) {
                const int dt = k / 3, df = k % 3;
                u64t xk0 = pk2(xr[dt  ][df], xr[dt  ][df]);
                u64t xk1 = pk2(xr[dt+1][df], xr[dt+1][df]);
                u64t xk2 = pk2(xr[dt+2][df], xr[dt+2][df]);
                u64t xk3 = pk2(xr[dt+3][df], xr[dt+3][df]);
#pragma unroll
                for (int p = 0; p < 4; p++) {
                    u64t wv = ws2[(p*C1_ + ci)*9 + k];
                    fma2(acc2[p][0], wv, xk0);
                    fma2(acc2[p][1], wv, xk1);
                    fma2(acc2[p][2], wv, xk2);
                    fma2(acc2[p][3], wv, xk3);
                }
            }
        }
    }
    float acc[8][4];
#pragma unroll
    for (int p = 0; p < 4; p++)
#pragma unroll
        for (int tt = 0; tt < 4; tt++) {
            float2 u = upk2(acc2[p][tt]);
            acc[2*p][tt] = u.x; acc[2*p+1][tt] = u.y;
        }

    for (int cc = 0; cc < 8; cc++) {
        __syncthreads();
        if (f < FP1_) {
#pragma unroll
            for (int tt = 0; tt < 4; tt++) ys[tt][f] = fmaxf(acc[cc][tt], 0.f);
        }
        __syncthreads();
        if (f < FP2_) {
            int c = ch*8 + cc;
#pragma unroll
            for (int tt = 0; tt < 4; tt++)
                g_Amat[(b*T_ + t0 + tt)*FCIN_ + c*FP2_ + f] =
                    fmaxf(ys[tt][2*f], ys[tt][2*f+1]);
        }
    }
}

// ---------------- GEMM (unchanged) ----------------
#define BM_ 128
#define BN_ 128
#define BK_ 16

__global__ __launch_bounds__(256) void gemm_tn(
    const float* __restrict__ A, const float* __restrict__ Bm,
    const float* __restrict__ bias, float* __restrict__ C,
    int M, int N, int K)
{
    __shared__ float As[2][BK_][BM_];
    __shared__ float Bs[2][BK_][BN_];

    const int tid = threadIdx.x;
    const int m0 = blockIdx.y * BM_, n0 = blockIdx.x * BN_;

    const int lr = tid >> 2;
    const int lk = (tid & 3) * 4;
    const float* Ap = A + (size_t)(m0 + lr) * K + lk;
    const float* Bp = Bm + (size_t)(n0 + lr) * K + lk;
    const size_t rowK = (size_t)64 * K;

    const int warp = tid >> 5, lane = tid & 31;
    const int wm = warp & 3, wn = warp >> 2;
    const int lm = lane >> 3, ln = lane & 7;
    const int row0 = wm * 32 + lm * 8;
    const int col0 = wn * 64 + ln * 8;

    u64t acc2[8][4];
#pragma unroll
    for (int i = 0; i < 8; i++)
#pragma unroll
        for (int j = 0; j < 4; j++) acc2[i][j] = 0ull;

    {
        float4 a0 = *(const float4*)(Ap);
        float4 a1 = *(const float4*)(Ap + rowK);
        float4 b0 = *(const float4*)(Bp);
        float4 b1 = *(const float4*)(Bp + rowK);
        As[0][lk+0][lr] = a0.x; As[0][lk+1][lr] = a0.y; As[0][lk+2][lr] = a0.z; As[0][lk+3][lr] = a0.w;
        As[0][lk+0][lr+64] = a1.x; As[0][lk+1][lr+64] = a1.y; As[0][lk+2][lr+64] = a1.z; As[0][lk+3][lr+64] = a1.w;
        Bs[0][lk+0][lr] = b0.x; Bs[0][lk+1][lr] = b0.y; Bs[0][lk+2][lr] = b0.z; Bs[0][lk+3][lr] = b0.w;
        Bs[0][lk+0][lr+64] = b1.x; Bs[0][lk+1][lr+64] = b1.y; Bs[0][lk+2][lr+64] = b1.z; Bs[0][lk+3][lr+64] = b1.w;
    }
    __syncthreads();

    const int nkt = K >> 4;
    int cur = 0;
    for (int kt = 0; kt < nkt; kt++) {
        float4 pa0, pa1, pb0, pb1;
        const bool has = (kt + 1 < nkt);
        if (has) {
            int ko = (kt + 1) << 4;
            pa0 = *(const float4*)(Ap + ko);
            pa1 = *(const float4*)(Ap + rowK + ko);
            pb0 = *(const float4*)(Bp + ko);
            pb1 = *(const float4*)(Bp + rowK + ko);
        }
#pragma unroll
        for (int kk = 0; kk < BK_; kk++) {
            float4 av0 = *(const float4*)&As[cur][kk][row0];
            float4 av1 = *(const float4*)&As[cur][kk][row0 + 4];
            float4 bv0 = *(const float4*)&Bs[cur][kk][col0];
            float4 bv1 = *(const float4*)&Bs[cur][kk][col0 + 4];
            u64t b2[4];
            b2[0] = pk2(bv0.x, bv0.y); b2[1] = pk2(bv0.z, bv0.w);
            b2[2] = pk2(bv1.x, bv1.y); b2[3] = pk2(bv1.z, bv1.w);
            float a[8] = {av0.x, av0.y, av0.z, av0.w, av1.x, av1.y, av1.z, av1.w};
#pragma unroll
            for (int i = 0; i < 8; i++) {
                u64t ai = pk2(a[i], a[i]);
#pragma unroll
                for (int j = 0; j < 4; j++)
                    fma2(acc2[i][j], ai, b2[j]);
            }
        }
        if (has) {
            int nb = cur ^ 1;
            As[nb][lk+0][lr] = pa0.x; As[nb][lk+1][lr] = pa0.y; As[nb][lk+2][lr] = pa0.z; As[nb][lk+3][lr] = pa0.w;
            As[nb][lk+0][lr+64] = pa1.x; As[nb][lk+1][lr+64] = pa1.y; As[nb][lk+2][lr+64] = pa1.z; As[nb][lk+3][lr+64] = pa1.w;
            Bs[nb][lk+0][lr] = pb0.x; Bs[nb][lk+1][lr] = pb0.y; Bs[nb][lk+2][lr] = pb0.z; Bs[nb][lk+3][lr] = pb0.w;
            Bs[nb][lk+0][lr+64] = pb1.x; Bs[nb][lk+1][lr+64] = pb1.y; Bs[nb][lk+2][lr+64] = pb1.z; Bs[nb][lk+3][lr+64] = pb1.w;
        }
        __syncthreads();
        cur ^= 1;
    }

    float bv[8];
#pragma unroll
    for (int j = 0; j < 8; j++) bv[j] = bias[n0 + col0 + j];
#pragma unroll
    for (int i = 0; i < 8; i++) {
        float* Cp = C + (size_t)(m0 + row0 + i) * N + n0 + col0;
        float2 r0 = upk2(acc2[i][0]), r1 = upk2(acc2[i][1]);
        float2 r2 = upk2(acc2[i][2]), r3 = upk2(acc2[i][3]);
        float4 o0 = make_float4(r0.x+bv[0], r0.y+bv[1], r1.x+bv[2], r1.y+bv[3]);
        float4 o1 = make_float4(r2.x+bv[4], r2.y+bv[5], r3.x+bv[6], r3.y+bv[7]);
        *(float4*)(Cp)     = o0;
        *(float4*)(Cp + 4) = o1;
    }
}

// ---------------- AR persistent kernel ----------------
__device__ __forceinline__ float warp_sum(float s)
{
    s += __shfl_xor_sync(0xffffffffu, s, 16);
    s += __shfl_xor_sync(0xffffffffu, s, 8);
    s += __shfl_xor_sync(0xffffffffu, s, 4);
    s += __shfl_xor_sync(0xffffffffu, s, 2);
    s += __shfl_xor_sync(0xffffffffu, s, 1);
    return s;
}
__device__ __forceinline__ float sigm(float x) { return 1.f / (1.f + expf(-x)); }

__device__ __forceinline__ void gbar(unsigned gen)
{
    __syncthreads();
    if (threadIdx.x == 0) {
        __threadfence();
        unsigned a = atomicAdd(&g_cnt2, 1u) + 1u;
        if (a == gen * NB_AR) {
            g_rel2 = gen;
        } else {
            while (g_rel2 < gen) { }
        }
    }
    __syncthreads();
}

// staged pairwise reduction
__device__ __forceinline__ void reduce32(float* v, int lane)
{
#pragma unroll
    for (int o = 16; o > 0; o >>= 1) {
        bool hi = (lane & o) != 0;
#pragma unroll
        for (int i = 0; i < o; i++) {
            float a0 = v[i], a1 = v[i + o];
            float mine = hi ? a1 : a0;
            float send = hi ? a0 : a1;
            float other = __shfl_xor_sync(0xffffffffu, send, o);
            v[i] = mine + other;
        }
    }
}

template<int NITER>
__device__ __forceinline__ void gemv_part(
    const float* __restrict__ Wb, int wstride,
    const float* xb, int xstride, int lane, float* v)
{
    u64t acc[4][8];
#pragma unroll
    for (int r = 0; r < 4; r++)
#pragma unroll
        for (int b = 0; b < 8; b++) acc[r][b] = 0ull;

#pragma unroll
    for (int it = 0; it < NITER; it++) {
        int off = it * 128 + lane * 4;
        float4 w0 = *(const float4*)(Wb              + off);
        float4 w1 = *(const float4*)(Wb +   wstride  + off);
        float4 w2 = *(const float4*)(Wb + 2*wstride  + off);
        float4 w3 = *(const float4*)(Wb + 3*wstride  + off);
        u64t wp[4][2];
        wp[0][0] = pk2(w0.x, w0.y); wp[0][1] = pk2(w0.z, w0.w);
        wp[1][0] = pk2(w1.x, w1.y); wp[1][1] = pk2(w1.z, w1.w);
        wp[2][0] = pk2(w2.x, w2.y); wp[2][1] = pk2(w2.z, w2.w);
        wp[3][0] = pk2(w3.x, w3.y); wp[3][1] = pk2(w3.z, w3.w);
#pragma unroll
        for (int b = 0; b < 8; b++) {
            float4 x = *(const float4*)(xb + b*xstride + off);
            u64t x0 = pk2(x.x, x.y), x1 = pk2(x.z, x.w);
            fma2(acc[0][b], wp[0][0], x0); fma2(acc[0][b], wp[0][1], x1);
            fma2(acc[1][b], wp[1][0], x0); fma2(acc[1][b], wp[1][1], x1);
            fma2(acc[2][b], wp[2][0], x0); fma2(acc[2][b], wp[2][1], x1);
            fma2(acc[3][b], wp[3][0], x0); fma2(acc[3][b], wp[3][1], x1);
        }
    }
#pragma unroll
    for (int r = 0; r < 4; r++)
#pragma unroll
        for (int b = 0; b < 8; b++) v[r*8 + b] = psum(acc[r][b]);
}

// smem float offsets (58096 floats = 232384 B <= 232448 B limit)
#define SW2   0        /* 6*4*1536 = 36864 */
#define SWP   36864    /* 2*5*768  =  7680 */
#define SXS   44544    /* 8*1536   = 12288 */
#define SP2   56832    /* 384 */
#define SPH   57216    /* 384 */
#define SPRE  57600    /* 384 */
#define SC1   57984    /* 48 */
#define SC2   58032    /* 48 */
#define SEMB  58080    /* 16 (10 used) */
#define STOT  58096

__global__ __launch_bounds__(384, 1) void ar_kernel(
    const float* __restrict__ postw, const float* __restrict__ postb,
    const float* __restrict__ embw, float* __restrict__ out)
{
    extern __shared__ float sm[];
    float* w2s  = sm + SW2;
    float* wps  = sm + SWP;
    float* xs2  = sm + SXS;
    float* p2   = sm + SP2;
    float* ph   = sm + SPH;
    float* preS = sm + SPRE;
    float* c1s  = sm + SC1;
    float* c2s  = sm + SC2;
    float* embS = sm + SEMB;

    const int tid = threadIdx.x, lane = tid & 31, warp = tid >> 5;
    const int cl = warp >> 1, half = warp & 1;
    const int cell = blockIdx.x * 6 + cl;

    // ---- one-time loads ----
    {
        const float4* src = (const float4*)(g_W2r + (size_t)blockIdx.x * 6 * 4 * K2_);
        float4* dst = (float4*)w2s;
        for (int i = tid; i < 6*4*K2_/4; i += 384) dst[i] = src[i];
    }
    {
        const float4* s0 = (const float4*)(postw + (size_t)(blockIdx.x >> 1) * 5 * DC_);
        float4* d0 = (float4*)wps;
        for (int i = tid; i < 5*DC_/4; i += 384) d0[i] = s0[i];
        if (blockIdx.x < 48) {
            const float4* s1 = (const float4*)(postw + (size_t)((NB_AR + blockIdx.x) >> 1) * 5 * DC_);
            float4* d1 = (float4*)(wps + 5*DC_);
            for (int i = tid; i < 5*DC_/4; i += 384) d1[i] = s1[i];
        }
    }
    for (int i = tid; i < 12288; i += 384) xs2[i] = 0.f;
    for (int i = tid; i < 384;   i += 384) ph[i] = 0.f;
    if (tid < 48) { c1s[tid] = 0.f; c2s[tid] = 0.f; }
    if (tid < 10) embS[tid] = embw[tid];
    if (tid < 192) {
        int b = tid / 24, j = tid - b*24;
        preS[tid] = __ldg(&g_pre[(size_t)(b*T_)*G4_ + blockIdx.x*24 + j]);
    }
    __syncthreads();

    float v[32];
    unsigned gen = 0;

    for (int t = 0; t < T_; t++) {
        const int wr = (t & 1) ^ 1, pbuf = t & 1;

        // ======== Phase A: emb-part GEMV + combine -> h1_new ========
        for (int i = tid; i < B_*44; i += 384) {
            int b = i / 44, j = i - b*44;
            ((float4*)(xs2 + b*K2_))[j] = __ldcg((const float4*)&g_xemb[b][0] + j);
        }
        __syncthreads();
        gemv_part<1>(g_W1r + (size_t)cell*4*K1P_ + half*128, K1P_,
                     xs2 + half*128, K2_, lane, v);
        reduce32(v, lane);
        p2[warp*32 + lane] = v[0];
        __syncthreads();
        if (tid < 48) {
            int c = tid >> 3, b = tid & 7;
            int mycell = blockIdx.x*6 + c;
            float z[4];
#pragma unroll
            for (int r = 0; r < 4; r++) {
                int idx = r*8 + b;
                z[r] = p2[(c*2)*32 + idx] + p2[(c*2+1)*32 + idx]
                     + ph[(c*2)*32 + idx] + ph[(c*2+1)*32 + idx]
                     + preS[pbuf*192 + b*24 + c*4 + r];
            }
            float co = c1s[tid];
            float ig = sigm(z[0]), fg = sigm(z[1]);
            float gg = tanhf(z[2]), og = sigm(z[3]);
            float cn = fg*co + ig*gg;
            c1s[tid] = cn;
            g_h1[wr][b][mycell] = og * tanhf(cn);
        }
        gbar(++gen);

        // ======== Phase B: LSTM2 ========
        for (int i = tid; i < B_*(DC_/4); i += 384) {
            int b = i / (DC_/4), j = i - b*(DC_/4);
            ((float4*)(xs2 + b*K2_))[j] = __ldcg((const float4*)&g_h1[wr][b][0] + j);
        }
        __syncthreads();
        gemv_part<6>(w2s + cl*4*K2_ + half*DC_, K2_,
                     xs2 + half*DC_, K2_, lane, v);
        reduce32(v, lane);
        p2[warp*32 + lane] = v[0];
        __syncthreads();
        if (tid < 48) {
            int c = tid >> 3, b = tid & 7;
            int mycell = blockIdx.x*6 + c;
            float z[4];
#pragma unroll
            for (int r = 0; r < 4; r++) {
                int idx = r*8 + b;
                z[r] = p2[(c*2)*32 + idx] + p2[(c*2+1)*32 + idx]
                     + __ldg(&g_b2v[mycell*4 + r]);
            }
            float co = c2s[tid];
            float ig = sigm(z[0]), fg = sigm(z[1]);
            float gg = tanhf(z[2]), og = sigm(z[3]);
            float cn = fg*co + ig*gg;
            c2s[tid] = cn;
            g_h2[wr][b][mycell] = og * tanhf(cn);
        }
        gbar(++gen);

        // ======== Phase C: stage h2_new; deferred h1 GEMV; post + argmax ========
        for (int i = tid; i < B_*(DC_/4); i += 384) {
            int b = i / (DC_/4), j = i - b*(DC_/4);
            ((float4*)(xs2 + b*K2_ + DC_))[j] = __ldcg((const float4*)&g_h2[wr][b][0] + j);
        }
        if (t + 1 < T_ && tid < 192) {
            int b = tid / 24, j = tid - b*24;
            preS[(pbuf^1)*192 + tid] = __ldg(&g_pre[(size_t)(b*T_ + t + 1)*G4_ + blockIdx.x*24 + j]);
        }
        __syncthreads();

        gemv_part<3>(g_W1r + (size_t)cell*4*K1P_ + 256 + half*384, K1P_,
                     xs2 + half*384, K2_, lane, v);
        reduce32(v, lane);
        ph[warp*32 + lane] = v[0];

        if (warp < 2 && (warp == 0 || blockIdx.x < 48)) {
            int task = warp * NB_AR + blockIdx.x;
            int p = task >> 1, bh = (task & 1) * 4;
            const float* Wp = wps + warp * 5 * DC_;
            u64t acc[5][4];
#pragma unroll
            for (int s = 0; s < 5; s++)
#pragma unroll
                for (int b = 0; b < 4; b++) acc[s][b] = 0ull;
#pragma unroll 2
            for (int kb = 0; kb < DC_; kb += 128) {
                int off = kb + lane*4;
                u64t wp[5][2];
#pragma unroll
                for (int s = 0; s < 5; s++) {
                    float4 w = *(const float4*)(Wp + s*DC_ + off);
                    wp[s][0] = pk2(w.x, w.y); wp[s][1] = pk2(w.z, w.w);
                }
#pragma unroll
                for (int b = 0; b < 4; b++) {
                    float4 x = *(const float4*)(xs2 + (bh + b)*K2_ + DC_ + off);
                    u64t x0 = pk2(x.x, x.y), x1 = pk2(x.z, x.w);
#pragma unroll
                    for (int s = 0; s < 5; s++) {
                        fma2(acc[s][b], wp[s][0], x0);
                        fma2(acc[s][b], wp[s][1], x1);
                    }
                }
            }
            float z[5][4];
#pragma unroll
            for (int s = 0; s < 5; s++)
#pragma unroll
                for (int b = 0; b < 4; b++)
                    z[s][b] = warp_sum(psum(acc[s][b]));
            if (lane < 4) {
                int b = bh + lane;
                float* o = out + (size_t)(b*T_ + t)*440 + p*5;
                float best = -1e30f; int bi = 0;
#pragma unroll
                for (int s = 0; s < 5; s++) {
                    float v0 = (lane & 1) ? z[s][1] : z[s][0];
                    float v1 = (lane & 1) ? z[s][3] : z[s][2];
                    float vv = ((lane & 2) ? v1 : v0) + __ldg(&postb[p*5 + s]);
                    o[s] = vv;
                    if (vv > best) { best = vv; bi = s; }
                }
                // write emb slice for next step directly (removes gather from phase A)
                g_xemb[b][p*2]     = embS[bi*2];
                g_xemb[b][p*2 + 1] = embS[bi*2 + 1];
            }
        }
        gbar(++gen);
    }
}

// ---------------- launch ----------------
extern "C" void kernel_launch(void* const* d_in, const int* in_sizes, int n_in,
                              void* d_out, int out_size)
{
    const float* mel    = (const float*)d_in[0];
    const float* c1w    = (const float*)d_in[1];
    const float* c1b    = (const float*)d_in[2];
    const float* b1g    = (const float*)d_in[3];
    const float* b1b    = (const float*)d_in[4];
    const float* b1m    = (const float*)d_in[5];
    const float* b1v    = (const float*)d_in[6];
    const float* c2w    = (const float*)d_in[7];
    const float* c2b    = (const float*)d_in[8];
    const float* b2g    = (const float*)d_in[9];
    const float* b2b    = (const float*)d_in[10];
    const float* b2m    = (const float*)d_in[11];
    const float* b2v    = (const float*)d_in[12];
    const float* c3w    = (const float*)d_in[13];
    const float* c3b    = (const float*)d_in[14];
    const float* b3g    = (const float*)d_in[15];
    const float* b3b    = (const float*)d_in[16];
    const float* b3m    = (const float*)d_in[17];
    const float* b3v    = (const float*)d_in[18];
    const float* fc_w   = (const float*)d_in[19];
    const float* fc_b   = (const float*)d_in[20];
    const float* wih1   = (const float*)d_in[21];
    const float* whh1   = (const float*)d_in[22];
    const float* bih1   = (const float*)d_in[23];
    const float* bhh1   = (const float*)d_in[24];
    const float* wih2   = (const float*)d_in[25];
    const float* whh2   = (const float*)d_in[26];
    const float* bih2   = (const float*)d_in[27];
    const float* bhh2   = (const float*)d_in[28];
    const float* post_w = (const float*)d_in[29];
    const float* post_b = (const float*)d_in[30];
    const float* emb_w  = (const float*)d_in[31];

    prep_kernel<<<2048, 256>>>(c1w, c1b, b1g, b1b, b1m, b1v,
                               c2w, c2b, b2g, b2b, b2m, b2v,
                               c3w, c3b, b3g, b3b, b3m, b3v,
                               wih1, whh1, bih1, bhh1,
                               wih2, whh2, bih2, bhh2, emb_w);

    conv1_kernel<<<dim3(T_, B_), 256>>>(mel);
    conv2_kernel<<<dim3(T_/4, B_, C1_/8), 256>>>();
    conv3_kernel<<<dim3(T_/4, B_, C3_/8), 128>>>();

    float *pA, *pAc, *pPre, *pWpre, *pBpre;
    cudaGetSymbolAddress((void**)&pA,    g_Amat);
    cudaGetSymbolAddress((void**)&pAc,   g_ac);
    cudaGetSymbolAddress((void**)&pPre,  g_pre);
    cudaGetSymbolAddress((void**)&pWpre, g_Wpre);
    cudaGetSymbolAddress((void**)&pBpre, g_bpre);

    gemm_tn<<<dim3(DC_/BN_, MALL_/BM_), 256>>>(pA, fc_w, fc_b, pAc, MALL_, DC_, FCIN_);
    gemm_tn<<<dim3(G4_/BN_, MALL_/BM_), 256>>>(pAc, pWpre, pBpre, pPre, MALL_, G4_, DC_);

    const int ar_smem = STOT * (int)sizeof(float);  // 232384 B
    cudaFuncSetAttribute(ar_kernel, cudaFuncAttributeMaxDynamicSharedMemorySize, ar_smem);
    ar_kernel<<<NB_AR, 384, ar_smem>>>(post_w, post_b, emb_w, (float*)d_out);
}

// round 11
// speedup vs baseline: 2.0038x; 1.0041x over previous
#include <cuda_runtime.h>
#include <math.h>

#define B_    8
#define T_    512
#define F_    229
#define C1_   48
#define C3_   96
#define FP1_  114
#define FP2_  57
#define DC_   768
#define FCIN_ 5472
#define G4_   3072
#define K1P_  1024   /* [emb 176 + pad 80 -> 256 | h1 768] */
#define K2_   1536
#define NP_   88
#define MALL_ 4096
#define NB_AR 128

// padded conv buffers
#define TP_   514            /* T + 2 */
#define C1S_  232            /* F + 3 (cols: f+1, f in -1..230) */
#define C2S_  116            /* FP1 + 2 */

typedef unsigned long long u64t;

// ---------------- f32x2 helpers ----------------
__device__ __forceinline__ void fma2(u64t &acc, u64t a, u64t b) {
    asm("fma.rn.f32x2 %0, %1, %2, %0;" : "+l"(acc) : "l"(a), "l"(b));
}
__device__ __forceinline__ u64t pk2(float lo, float hi) {
    u64t r;
    asm("mov.b64 %0, {%1, %2};" : "=l"(r) : "r"(__float_as_uint(lo)), "r"(__float_as_uint(hi)));
    return r;
}
__device__ __forceinline__ float2 upk2(u64t v) {
    unsigned lo, hi;
    asm("mov.b64 {%0, %1}, %2;" : "=r"(lo), "=r"(hi) : "l"(v));
    return make_float2(__uint_as_float(lo), __uint_as_float(hi));
}
__device__ __forceinline__ float psum(u64t v) {
    float2 f = upk2(v);
    return f.x + f.y;
}
// reinterpret consecutive float pairs of a float4 as f32x2 operands (no movs)
__device__ __forceinline__ u64t lo2(const float4& v) { return *reinterpret_cast<const u64t*>(&v.x); }
__device__ __forceinline__ u64t hi2(const float4& v) { return *reinterpret_cast<const u64t*>(&v.z); }

// ---------------- device scratch ----------------
__device__ float g_conv1p[B_*C1_*TP_*C1S_];   /* padded conv1 out */
__device__ float g_conv2p[B_*C1_*TP_*C2S_];   /* padded conv2+pool out */
__device__ float g_Amat[MALL_*FCIN_];
__device__ float g_ac[MALL_*DC_];
__device__ float g_pre[MALL_*G4_];
__device__ float g_W1r[G4_*K1P_];
__device__ float g_W2r[G4_*K2_];
__device__ float g_Wpre[G4_*DC_];
__device__ float g_bpre[G4_];
__device__ float g_b2v[G4_];
__device__ float g_wf1[C1_*9],      g_bf1[C1_];
__device__ float g_wf2[C1_*C1_*9],  g_bf2[C1_];
__device__ float g_wf3[C3_*C1_*9],  g_bf3[C3_];
__device__ float g_h1[2][B_][DC_], g_h2[2][B_][DC_];
__device__ float g_xemb[B_][176];
__device__ unsigned g_cnt2;
__device__ volatile unsigned g_rel2;

// ---------------- prep ----------------
__global__ void prep_kernel(
    const float* __restrict__ c1w, const float* __restrict__ c1b,
    const float* __restrict__ b1g, const float* __restrict__ b1b,
    const float* __restrict__ b1m, const float* __restrict__ b1v,
    const float* __restrict__ c2w, const float* __restrict__ c2b,
    const float* __restrict__ b2g, const float* __restrict__ b2b,
    const float* __restrict__ b2m, const float* __restrict__ b2v,
    const float* __restrict__ c3w, const float* __restrict__ c3b,
    const float* __restrict__ b3g, const float* __restrict__ b3b,
    const float* __restrict__ b3m, const float* __restrict__ b3v,
    const float* __restrict__ wih1, const float* __restrict__ whh1,
    const float* __restrict__ bih1, const float* __restrict__ bhh1,
    const float* __restrict__ wih2, const float* __restrict__ whh2,
    const float* __restrict__ bih2, const float* __restrict__ bhh2,
    const float* __restrict__ embw)
{
    const int st = gridDim.x * blockDim.x;
    const int t0 = blockIdx.x * blockDim.x + threadIdx.x;
    const float eps = 1e-5f;

    // zero padded conv buffers (borders must be 0; interiors overwritten)
    {
        float4 z4 = make_float4(0.f, 0.f, 0.f, 0.f);
        float4* p1 = (float4*)g_conv1p;
        const int n1 = B_*C1_*TP_*C1S_/4;
        for (int i = t0; i < n1; i += st) p1[i] = z4;
        float4* p2 = (float4*)g_conv2p;
        const int n2 = B_*C1_*TP_*C2S_/4;
        for (int i = t0; i < n2; i += st) p2[i] = z4;
    }

    for (int i = t0; i < C1_*9; i += st) { int c = i/9;        g_wf1[i] = c1w[i] * (b1g[c]*rsqrtf(b1v[c]+eps)); }
    for (int i = t0; i < C1_;  i += st)  g_bf1[i] = (c1b[i]-b1m[i])*(b1g[i]*rsqrtf(b1v[i]+eps)) + b1b[i];
    for (int i = t0; i < C1_*C1_*9; i += st) { int c = i/(C1_*9); g_wf2[i] = c2w[i] * (b2g[c]*rsqrtf(b2v[c]+eps)); }
    for (int i = t0; i < C1_;  i += st)  g_bf2[i] = (c2b[i]-b2m[i])*(b2g[i]*rsqrtf(b2v[i]+eps)) + b2b[i];
    for (int i = t0; i < C3_*C1_*9; i += st) { int c = i/(C1_*9); g_wf3[i] = c3w[i] * (b3g[c]*rsqrtf(b3v[c]+eps)); }
    for (int i = t0; i < C3_;  i += st)  g_bf3[i] = (c3b[i]-b3m[i])*(b3g[i]*rsqrtf(b3v[i]+eps)) + b3b[i];

    // W1r layout: rows n = cell*4+g; cols [0,176)=wih1 emb part, [176,256)=0, [256,1024)=whh1
    for (int i = t0; i < G4_*K1P_; i += st) {
        int n = i >> 10, k = i & (K1P_-1);
        int m = n >> 2, g = n & 3, orig = g*DC_ + m;
        float v = 0.f;
        if (k < 176)       v = wih1[orig*944 + 768 + k];
        else if (k >= 256) v = whh1[orig*DC_ + (k - 256)];
        g_W1r[i] = v;
    }
    // W2r: cols [0,768)=wih2, [768,1536)=whh2
    for (int i = t0; i < G4_*K2_; i += st) {
        int n = i / K2_, k = i - n*K2_;
        int m = n >> 2, g = n & 3, orig = g*DC_ + m;
        g_W2r[i] = (k < DC_) ? wih2[orig*DC_ + k] : whh2[orig*DC_ + (k - DC_)];
    }
    // Wpre: acoustic part of wih1, reordered rows
    for (int i = t0; i < G4_*DC_; i += st) {
        int n = i / DC_, k = i - n*DC_;
        int m = n >> 2, g = n & 3, orig = g*DC_ + m;
        g_Wpre[i] = wih1[orig*944 + k];
    }
    for (int i = t0; i < G4_; i += st) {
        int m = i >> 2, g = i & 3, orig = g*DC_ + m;
        g_bpre[i] = bih1[orig] + bhh1[orig];
        g_b2v[i]  = bih2[orig] + bhh2[orig];
    }
    for (int i = t0; i < B_*DC_; i += st) {
        (&g_h1[0][0][0])[i] = 0.f;
        (&g_h2[0][0][0])[i] = 0.f;
    }
    // prev state = 0 -> emb row 0
    for (int i = t0; i < B_*176; i += st)
        (&g_xemb[0][0])[i] = embw[i & 1];
    if (t0 == 0) { g_cnt2 = 0u; g_rel2 = 0u; }
}

// ---------------- conv1 (writes padded layout) ----------------
__global__ void conv1_kernel(const float* __restrict__ mel)
{
    int t = blockIdx.x, b = blockIdx.y, f = threadIdx.x;
    __shared__ float ws[C1_*9];
    __shared__ float bs[C1_];
    for (int i = threadIdx.x; i < C1_*9; i += 256) ws[i] = g_wf1[i];
    for (int i = threadIdx.x; i < C1_;  i += 256) bs[i] = g_bf1[i];
    __syncthreads();
    if (f >= F_) return;

    float x[9];
#pragma unroll
    for (int dt = 0; dt < 3; dt++)
#pragma unroll
        for (int df = 0; df < 3; df++) {
            int tt = t - 1 + dt, ff = f - 1 + df;
            x[dt*3+df] = (tt >= 0 && tt < T_ && ff >= 0 && ff < F_)
                         ? mel[(b*T_ + tt)*F_ + ff] : 0.f;
        }
    for (int c = 0; c < C1_; c++) {
        float a = bs[c];
#pragma unroll
        for (int k = 0; k < 9; k++) a += ws[c*9+k] * x[k];
        g_conv1p[((b*C1_ + c)*TP_ + t + 1)*C1S_ + f + 1] = fmaxf(a, 0.f);
    }
}

// ---------------- conv2: f32x2, predicate-free padded input ----------------
__global__ __launch_bounds__(256) void conv2_kernel()
{
    int t0 = blockIdx.x * 4, b = blockIdx.y, ch = blockIdx.z;
    int f = threadIdx.x;
    __shared__ u64t ws2[4*C1_*9];
    __shared__ float ys[4][232];
    for (int i = threadIdx.x; i < 4*C1_*9; i += 256) {
        int p = i / (C1_*9), r = i - p*(C1_*9);
        ws2[i] = pk2(g_wf2[(ch*8 + 2*p)*C1_*9 + r],
                     g_wf2[(ch*8 + 2*p + 1)*C1_*9 + r]);
    }
    __syncthreads();

    u64t acc2[4][4];
#pragma unroll
    for (int p = 0; p < 4; p++) {
        u64t bp = pk2(g_bf2[ch*8 + 2*p], g_bf2[ch*8 + 2*p + 1]);
#pragma unroll
        for (int tt = 0; tt < 4; tt++) acc2[p][tt] = bp;
    }

    if (f < F_) {
        for (int ci = 0; ci < C1_; ci++) {
            const float* base = g_conv1p + ((b*C1_ + ci)*TP_ + t0)*C1S_ + f;
            float xr[6][3];
#pragma unroll
            for (int j = 0; j < 6; j++)
#pragma unroll
                for (int d = 0; d < 3; d++)
                    xr[j][d] = base[j*C1S_ + d];
#pragma unroll
            for (int k = 0; k < 9; k++) {
                const int dt = k / 3, df = k % 3;
                u64t xk0 = pk2(xr[dt  ][df], xr[dt  ][df]);
                u64t xk1 = pk2(xr[dt+1][df], xr[dt+1][df]);
                u64t xk2 = pk2(xr[dt+2][df], xr[dt+2][df]);
                u64t xk3 = pk2(xr[dt+3][df], xr[dt+3][df]);
#pragma unroll
                for (int p = 0; p < 4; p++) {
                    u64t wv = ws2[(p*C1_ + ci)*9 + k];
                    fma2(acc2[p][0], wv, xk0);
                    fma2(acc2[p][1], wv, xk1);
                    fma2(acc2[p][2], wv, xk2);
                    fma2(acc2[p][3], wv, xk3);
                }
            }
        }
    }
    float acc[8][4];
#pragma unroll
    for (int p = 0; p < 4; p++)
#pragma unroll
        for (int tt = 0; tt < 4; tt++) {
            float2 u = upk2(acc2[p][tt]);
            acc[2*p][tt] = u.x; acc[2*p+1][tt] = u.y;
        }

    for (int cc = 0; cc < 8; cc++) {
        __syncthreads();
        if (f < F_) {
#pragma unroll
            for (int tt = 0; tt < 4; tt++) ys[tt][f] = fmaxf(acc[cc][tt], 0.f);
        }
        __syncthreads();
        if (f < FP1_) {
            int c = ch*8 + cc;
#pragma unroll
            for (int tt = 0; tt < 4; tt++)
                g_conv2p[((b*C1_ + c)*TP_ + t0 + tt + 1)*C2S_ + f + 1] =
                    fmaxf(ys[tt][2*f], ys[tt][2*f+1]);
        }
    }
}

// ---------------- conv3: f32x2, predicate-free padded input ----------------
__global__ __launch_bounds__(128) void conv3_kernel()
{
    int t0 = blockIdx.x * 4, b = blockIdx.y, ch = blockIdx.z;
    int f = threadIdx.x;
    __shared__ u64t ws2[4*C1_*9];
    __shared__ float ys[4][116];
    for (int i = threadIdx.x; i < 4*C1_*9; i += 128) {
        int p = i / (C1_*9), r = i - p*(C1_*9);
        ws2[i] = pk2(g_wf3[(ch*8 + 2*p)*C1_*9 + r],
                     g_wf3[(ch*8 + 2*p + 1)*C1_*9 + r]);
    }
    __syncthreads();

    u64t acc2[4][4];
#pragma unroll
    for (int p = 0; p < 4; p++) {
        u64t bp = pk2(g_bf3[ch*8 + 2*p], g_bf3[ch*8 + 2*p + 1]);
#pragma unroll
        for (int tt = 0; tt < 4; tt++) acc2[p][tt] = bp;
    }

    if (f < FP1_) {
        for (int ci = 0; ci < C1_; ci++) {
            const float* base = g_conv2p + ((b*C1_ + ci)*TP_ + t0)*C2S_ + f;
            float xr[6][3];
#pragma unroll
            for (int j = 0; j < 6; j++)
#pragma unroll
                for (int d = 0; d < 3; d++)
                    xr[j][d] = base[j*C2S_ + d];
#pragma unroll
            for (int k = 0; k < 9; k++) {
                const int dt = k / 3, df = k % 3;
                u64t xk0 = pk2(xr[dt  ][df], xr[dt  ][df]);
                u64t xk1 = pk2(xr[dt+1][df], xr[dt+1][df]);
                u64t xk2 = pk2(xr[dt+2][df], xr[dt+2][df]);
                u64t xk3 = pk2(xr[dt+3][df], xr[dt+3][df]);
#pragma unroll
                for (int p = 0; p < 4; p++) {
                    u64t wv = ws2[(p*C1_ + ci)*9 + k];
                    fma2(acc2[p][0], wv, xk0);
                    fma2(acc2[p][1], wv, xk1);
                    fma2(acc2[p][2], wv, xk2);
                    fma2(acc2[p][3], wv, xk3);
                }
            }
        }
    }
    float acc[8][4];
#pragma unroll
    for (int p = 0; p < 4; p++)
#pragma unroll
        for (int tt = 0; tt < 4; tt++) {
            float2 u = upk2(acc2[p][tt]);
            acc[2*p][tt] = u.x; acc[2*p+1][tt] = u.y;
        }

    for (int cc = 0; cc < 8; cc++) {
        __syncthreads();
        if (f < FP1_) {
#pragma unroll
            for (int tt = 0; tt < 4; tt++) ys[tt][f] = fmaxf(acc[cc][tt], 0.f);
        }
        __syncthreads();
        if (f < FP2_) {
            int c = ch*8 + cc;
#pragma unroll
            for (int tt = 0; tt < 4; tt++)
                g_Amat[(b*T_ + t0 + tt)*FCIN_ + c*FP2_ + f] =
                    fmaxf(ys[tt][2*f], ys[tt][2*f+1]);
        }
    }
}

// ---------------- GEMM: duplicated-A smem, zero-mov f32x2 inner loop ----------------
#define BM_ 128
#define BN_ 128
#define BK_ 16
#define ASTR 260     /* 2*BM_ + 4 pad */
#define BSTR 132     /* BN_ + 4 pad */
#define GSMEM ((2*BK_*ASTR + 2*BK_*BSTR) * 4)   /* 50176 bytes */

__global__ __launch_bounds__(256) void gemm_tn(
    const float* __restrict__ A, const float* __restrict__ Bm,
    const float* __restrict__ bias, float* __restrict__ C,
    int M, int N, int K)
{
    extern __shared__ float gsm[];
    float* As = gsm;                     // [2][BK_][ASTR], A duplicated
    float* Bs = gsm + 2*BK_*ASTR;        // [2][BK_][BSTR]

    const int tid = threadIdx.x;
    const int m0 = blockIdx.y * BM_, n0 = blockIdx.x * BN_;

    const int lr = tid >> 2;
    const int lk = (tid & 3) * 4;
    const float* Ap = A + (size_t)(m0 + lr) * K + lk;
    const float* Bp = Bm + (size_t)(n0 + lr) * K + lk;
    const size_t rowK = (size_t)64 * K;

    const int warp = tid >> 5, lane = tid & 31;
    const int wm = warp & 3, wn = warp >> 2;
    const int lm = lane >> 3, ln = lane & 7;
    const int row0 = wm * 32 + lm * 8;
    const int col0 = wn * 64 + ln * 8;

    u64t acc2[8][4];
#pragma unroll
    for (int i = 0; i < 8; i++)
#pragma unroll
        for (int j = 0; j < 4; j++) acc2[i][j] = 0ull;

    // store helpers
    auto storeA = [&](int buf, const float4& a, int r) {
        float* p = As + (buf*BK_)*ASTR;
        *(float2*)&p[(lk+0)*ASTR + 2*r] = make_float2(a.x, a.x);
        *(float2*)&p[(lk+1)*ASTR + 2*r] = make_float2(a.y, a.y);
        *(float2*)&p[(lk+2)*ASTR + 2*r] = make_float2(a.z, a.z);
        *(float2*)&p[(lk+3)*ASTR + 2*r] = make_float2(a.w, a.w);
    };
    auto storeB = [&](int buf, const float4& b, int r) {
        float* p = Bs + (buf*BK_)*BSTR;
        p[(lk+0)*BSTR + r] = b.x;
        p[(lk+1)*BSTR + r] = b.y;
        p[(lk+2)*BSTR + r] = b.z;
        p[(lk+3)*BSTR + r] = b.w;
    };

    {
        float4 a0 = *(const float4*)(Ap);
        float4 a1 = *(const float4*)(Ap + rowK);
        float4 b0 = *(const float4*)(Bp);
        float4 b1 = *(const float4*)(Bp + rowK);
        storeA(0, a0, lr); storeA(0, a1, lr+64);
        storeB(0, b0, lr); storeB(0, b1, lr+64);
    }
    __syncthreads();

    const int nkt = K >> 4;
    int cur = 0;
    for (int kt = 0; kt < nkt; kt++) {
        float4 pa0, pa1, pb0, pb1;
        const bool has = (kt + 1 < nkt);
        if (has) {
            int ko = (kt + 1) << 4;
            pa0 = *(const float4*)(Ap + ko);
            pa1 = *(const float4*)(Ap + rowK + ko);
            pb0 = *(const float4*)(Bp + ko);
            pb1 = *(const float4*)(Bp + rowK + ko);
        }
#pragma unroll
        for (int kk = 0; kk < BK_; kk++) {
            const float* Ak = As + (cur*BK_ + kk)*ASTR + 2*row0;
            const float* Bk = Bs + (cur*BK_ + kk)*BSTR + col0;
            float4 ad0 = *(const float4*)(Ak);
            float4 ad1 = *(const float4*)(Ak + 4);
            float4 ad2 = *(const float4*)(Ak + 8);
            float4 ad3 = *(const float4*)(Ak + 12);
            float4 bv0 = *(const float4*)(Bk);
            float4 bv1 = *(const float4*)(Bk + 4);
            u64t ai[8] = {lo2(ad0), hi2(ad0), lo2(ad1), hi2(ad1),
                          lo2(ad2), hi2(ad2), lo2(ad3), hi2(ad3)};
            u64t bj[4] = {lo2(bv0), hi2(bv0), lo2(bv1), hi2(bv1)};
#pragma unroll
            for (int i = 0; i < 8; i++)
#pragma unroll
                for (int j = 0; j < 4; j++)
                    fma2(acc2[i][j], ai[i], bj[j]);
        }
        if (has) {
            int nb = cur ^ 1;
            storeA(nb, pa0, lr); storeA(nb, pa1, lr+64);
            storeB(nb, pb0, lr); storeB(nb, pb1, lr+64);
        }
        __syncthreads();
        cur ^= 1;
    }

    float bv[8];
#pragma unroll
    for (int j = 0; j < 8; j++) bv[j] = bias[n0 + col0 + j];
#pragma unroll
    for (int i = 0; i < 8; i++) {
        float* Cp = C + (size_t)(m0 + row0 + i) * N + n0 + col0;
        float2 r0 = upk2(acc2[i][0]), r1 = upk2(acc2[i][1]);
        float2 r2 = upk2(acc2[i][2]), r3 = upk2(acc2[i][3]);
        float4 o0 = make_float4(r0.x+bv[0], r0.y+bv[1], r1.x+bv[2], r1.y+bv[3]);
        float4 o1 = make_float4(r2.x+bv[4], r2.y+bv[5], r3.x+bv[6], r3.y+bv[7]);
        *(float4*)(Cp)     = o0;
        *(float4*)(Cp + 4) = o1;
    }
}

// ---------------- AR persistent kernel ----------------
__device__ __forceinline__ float warp_sum(float s)
{
    s += __shfl_xor_sync(0xffffffffu, s, 16);
    s += __shfl_xor_sync(0xffffffffu, s, 8);
    s += __shfl_xor_sync(0xffffffffu, s, 4);
    s += __shfl_xor_sync(0xffffffffu, s, 2);
    s += __shfl_xor_sync(0xffffffffu, s, 1);
    return s;
}
__device__ __forceinline__ float sigm(float x) { return 1.f / (1.f + expf(-x)); }

__device__ __forceinline__ void gbar(unsigned gen)
{
    __syncthreads();
    if (threadIdx.x == 0) {
        __threadfence();
        unsigned a = atomicAdd(&g_cnt2, 1u) + 1u;
        if (a == gen * NB_AR) {
            g_rel2 = gen;
        } else {
            while (g_rel2 < gen) { }
        }
    }
    __syncthreads();
}

// staged pairwise reduction
__device__ __forceinline__ void reduce32(float* v, int lane)
{
#pragma unroll
    for (int o = 16; o > 0; o >>= 1) {
        bool hi = (lane & o) != 0;
#pragma unroll
        for (int i = 0; i < o; i++) {
            float a0 = v[i], a1 = v[i + o];
            float mine = hi ? a1 : a0;
            float send = hi ? a0 : a1;
            float other = __shfl_xor_sync(0xffffffffu, send, o);
            v[i] = mine + other;
        }
    }
}

template<int NITER>
__device__ __forceinline__ void gemv_part(
    const float* __restrict__ Wb, int wstride,
    const float* xb, int xstride, int lane, float* v)
{
    u64t acc[4][8];
#pragma unroll
    for (int r = 0; r < 4; r++)
#pragma unroll
        for (int b = 0; b < 8; b++) acc[r][b] = 0ull;

#pragma unroll
    for (int it = 0; it < NITER; it++) {
        int off = it * 128 + lane * 4;
        float4 w0 = *(const float4*)(Wb              + off);
        float4 w1 = *(const float4*)(Wb +   wstride  + off);
        float4 w2 = *(const float4*)(Wb + 2*wstride  + off);
        float4 w3 = *(const float4*)(Wb + 3*wstride  + off);
#pragma unroll
        for (int b = 0; b < 8; b++) {
            float4 x = *(const float4*)(xb + b*xstride + off);
            u64t x0 = lo2(x), x1 = hi2(x);
            fma2(acc[0][b], lo2(w0), x0); fma2(acc[0][b], hi2(w0), x1);
            fma2(acc[1][b], lo2(w1), x0); fma2(acc[1][b], hi2(w1), x1);
            fma2(acc[2][b], lo2(w2), x0); fma2(acc[2][b], hi2(w2), x1);
            fma2(acc[3][b], lo2(w3), x0); fma2(acc[3][b], hi2(w3), x1);
        }
    }
#pragma unroll
    for (int r = 0; r < 4; r++)
#pragma unroll
        for (int b = 0; b < 8; b++) v[r*8 + b] = psum(acc[r][b]);
}

// smem float offsets (58096 floats = 232384 B <= 232448 B limit)
#define SW2   0        /* 6*4*1536 = 36864 */
#define SWP   36864    /* 2*5*768  =  7680 */
#define SXS   44544    /* 8*1536   = 12288 */
#define SP2   56832    /* 384 */
#define SPH   57216    /* 384 */
#define SPRE  57600    /* 384 */
#define SC1   57984    /* 48 */
#define SC2   58032    /* 48 */
#define SEMB  58080    /* 16 (10 used) */
#define STOT  58096

__global__ __launch_bounds__(384, 1) void ar_kernel(
    const float* __restrict__ postw, const float* __restrict__ postb,
    const float* __restrict__ embw, float* __restrict__ out)
{
    extern __shared__ float sm[];
    float* w2s  = sm + SW2;
    float* wps  = sm + SWP;
    float* xs2  = sm + SXS;
    float* p2   = sm + SP2;
    float* ph   = sm + SPH;
    float* preS = sm + SPRE;
    float* c1s  = sm + SC1;
    float* c2s  = sm + SC2;
    float* embS = sm + SEMB;

    const int tid = threadIdx.x, lane = tid & 31, warp = tid >> 5;
    const int cl = warp >> 1, half = warp & 1;
    const int cell = blockIdx.x * 6 + cl;

    // ---- one-time loads ----
    {
        const float4* src = (const float4*)(g_W2r + (size_t)blockIdx.x * 6 * 4 * K2_);
        float4* dst = (float4*)w2s;
        for (int i = tid; i < 6*4*K2_/4; i += 384) dst[i] = src[i];
    }
    {
        const float4* s0 = (const float4*)(postw + (size_t)(blockIdx.x >> 1) * 5 * DC_);
        float4* d0 = (float4*)wps;
        for (int i = tid; i < 5*DC_/4; i += 384) d0[i] = s0[i];
        if (blockIdx.x < 48) {
            const float4* s1 = (const float4*)(postw + (size_t)((NB_AR + blockIdx.x) >> 1) * 5 * DC_);
            float4* d1 = (float4*)(wps + 5*DC_);
            for (int i = tid; i < 5*DC_/4; i += 384) d1[i] = s1[i];
        }
    }
    for (int i = tid; i < 12288; i += 384) xs2[i] = 0.f;
    for (int i = tid; i < 384;   i += 384) ph[i] = 0.f;
    if (tid < 48) { c1s[tid] = 0.f; c2s[tid] = 0.f; }
    if (tid < 10) embS[tid] = embw[tid];
    if (tid < 192) {
        int b = tid / 24, j = tid - b*24;
        preS[tid] = __ldg(&g_pre[(size_t)(b*T_)*G4_ + blockIdx.x*24 + j]);
    }
    __syncthreads();

    float v[32];
    unsigned gen = 0;

    for (int t = 0; t < T_; t++) {
        const int wr = (t & 1) ^ 1, pbuf = t & 1;

        // ======== Phase A: emb-part GEMV + combine -> h1_new ========
        for (int i = tid; i < B_*44; i += 384) {
            int b = i / 44, j = i - b*44;
            ((float4*)(xs2 + b*K2_))[j] = __ldcg((const float4*)&g_xemb[b][0] + j);
        }
        __syncthreads();
        gemv_part<1>(g_W1r + (size_t)cell*4*K1P_ + half*128, K1P_,
                     xs2 + half*128, K2_, lane, v);
        reduce32(v, lane);
        p2[warp*32 + lane] = v[0];
        __syncthreads();
        if (tid < 48) {
            int c = tid >> 3, b = tid & 7;
            int mycell = blockIdx.x*6 + c;
            float z[4];
#pragma unroll
            for (int r = 0; r < 4; r++) {
                int idx = r*8 + b;
                z[r] = p2[(c*2)*32 + idx] + p2[(c*2+1)*32 + idx]
                     + ph[(c*2)*32 + idx] + ph[(c*2+1)*32 + idx]
                     + preS[pbuf*192 + b*24 + c*4 + r];
            }
            float co = c1s[tid];
            float ig = sigm(z[0]), fg = sigm(z[1]);
            float gg = tanhf(z[2]), og = sigm(z[3]);
            float cn = fg*co + ig*gg;
            c1s[tid] = cn;
            g_h1[wr][b][mycell] = og * tanhf(cn);
        }
        gbar(++gen);

        // ======== Phase B: LSTM2 ========
        for (int i = tid; i < B_*(DC_/4); i += 384) {
            int b = i / (DC_/4), j = i - b*(DC_/4);
            ((float4*)(xs2 + b*K2_))[j] = __ldcg((const float4*)&g_h1[wr][b][0] + j);
        }
        __syncthreads();
        gemv_part<6>(w2s + cl*4*K2_ + half*DC_, K2_,
                     xs2 + half*DC_, K2_, lane, v);
        reduce32(v, lane);
        p2[warp*32 + lane] = v[0];
        __syncthreads();
        if (tid < 48) {
            int c = tid >> 3, b = tid & 7;
            int mycell = blockIdx.x*6 + c;
            float z[4];
#pragma unroll
            for (int r = 0; r < 4; r++) {
                int idx = r*8 + b;
                z[r] = p2[(c*2)*32 + idx] + p2[(c*2+1)*32 + idx]
                     + __ldg(&g_b2v[mycell*4 + r]);
            }
            float co = c2s[tid];
            float ig = sigm(z[0]), fg = sigm(z[1]);
            float gg = tanhf(z[2]), og = sigm(z[3]);
            float cn = fg*co + ig*gg;
            c2s[tid] = cn;
            g_h2[wr][b][mycell] = og * tanhf(cn);
        }
        gbar(++gen);

        // ======== Phase C: stage h2_new; deferred h1 GEMV; post + argmax ========
        for (int i = tid; i < B_*(DC_/4); i += 384) {
            int b = i / (DC_/4), j = i - b*(DC_/4);
            ((float4*)(xs2 + b*K2_ + DC_))[j] = __ldcg((const float4*)&g_h2[wr][b][0] + j);
        }
        if (t + 1 < T_ && tid < 192) {
            int b = tid / 24, j = tid - b*24;
            preS[(pbuf^1)*192 + tid] = __ldg(&g_pre[(size_t)(b*T_ + t + 1)*G4_ + blockIdx.x*24 + j]);
        }
        __syncthreads();

        gemv_part<3>(g_W1r + (size_t)cell*4*K1P_ + 256 + half*384, K1P_,
                     xs2 + half*384, K2_, lane, v);
        reduce32(v, lane);
        ph[warp*32 + lane] = v[0];

        if (warp < 2 && (warp == 0 || blockIdx.x < 48)) {
            int task = warp * NB_AR + blockIdx.x;
            int p = task >> 1, bh = (task & 1) * 4;
            const float* Wp = wps + warp * 5 * DC_;
            u64t acc[5][4];
#pragma unroll
            for (int s = 0; s < 5; s++)
#pragma unroll
                for (int b = 0; b < 4; b++) acc[s][b] = 0ull;
#pragma unroll 2
            for (int kb = 0; kb < DC_; kb += 128) {
                int off = kb + lane*4;
                float4 w[5];
#pragma unroll
                for (int s = 0; s < 5; s++)
                    w[s] = *(const float4*)(Wp + s*DC_ + off);
#pragma unroll
                for (int b = 0; b < 4; b++) {
                    float4 x = *(const float4*)(xs2 + (bh + b)*K2_ + DC_ + off);
                    u64t x0 = lo2(x), x1 = hi2(x);
#pragma unroll
                    for (int s = 0; s < 5; s++) {
                        fma2(acc[s][b], lo2(w[s]), x0);
                        fma2(acc[s][b], hi2(w[s]), x1);
                    }
                }
            }
            float z[5][4];
#pragma unroll
            for (int s = 0; s < 5; s++)
#pragma unroll
                for (int b = 0; b < 4; b++)
                    z[s][b] = warp_sum(psum(acc[s][b]));
            if (lane < 4) {
                int b = bh + lane;
                float* o = out + (size_t)(b*T_ + t)*440 + p*5;
                float best = -1e30f; int bi = 0;
#pragma unroll
                for (int s = 0; s < 5; s++) {
                    float v0 = (lane & 1) ? z[s][1] : z[s][0];
                    float v1 = (lane & 1) ? z[s][3] : z[s][2];
                    float vv = ((lane & 2) ? v1 : v0) + __ldg(&postb[p*5 + s]);
                    o[s] = vv;
                    if (vv > best) { best = vv; bi = s; }
                }
                g_xemb[b][p*2]     = embS[bi*2];
                g_xemb[b][p*2 + 1] = embS[bi*2 + 1];
            }
        }
        gbar(++gen);
    }
}

// ---------------- launch ----------------
extern "C" void kernel_launch(void* const* d_in, const int* in_sizes, int n_in,
                              void* d_out, int out_size)
{
    const float* mel    = (const float*)d_in[0];
    const float* c1w    = (const float*)d_in[1];
    const float* c1b    = (const float*)d_in[2];
    const float* b1g    = (const float*)d_in[3];
    const float* b1b    = (const float*)d_in[4];
    const float* b1m    = (const float*)d_in[5];
    const float* b1v    = (const float*)d_in[6];
    const float* c2w    = (const float*)d_in[7];
    const float* c2b    = (const float*)d_in[8];
    const float* b2g    = (const float*)d_in[9];
    const float* b2b    = (const float*)d_in[10];
    const float* b2m    = (const float*)d_in[11];
    const float* b2v    = (const float*)d_in[12];
    const float* c3w    = (const float*)d_in[13];
    const float* c3b    = (const float*)d_in[14];
    const float* b3g    = (const float*)d_in[15];
    const float* b3b    = (const float*)d_in[16];
    const float* b3m    = (const float*)d_in[17];
    const float* b3v    = (const float*)d_in[18];
    const float* fc_w   = (const float*)d_in[19];
    const float* fc_b   = (const float*)d_in[20];
    const float* wih1   = (const float*)d_in[21];
    const float* whh1   = (const float*)d_in[22];
    const float* bih1   = (const float*)d_in[23];
    const float* bhh1   = (const float*)d_in[24];
    const float* wih2   = (const float*)d_in[25];
    const float* whh2   = (const float*)d_in[26];
    const float* bih2   = (const float*)d_in[27];
    const float* bhh2   = (const float*)d_in[28];
    const float* post_w = (const float*)d_in[29];
    const float* post_b = (const float*)d_in[30];
    const float* emb_w  = (const float*)d_in[31];

    prep_kernel<<<2048, 256>>>(c1w, c1b, b1g, b1b, b1m, b1v,
                               c2w, c2b, b2g, b2b, b2m, b2v,
                               c3w, c3b, b3g, b3b, b3m, b3v,
                               wih1, whh1, bih1, bhh1,
                               wih2, whh2, bih2, bhh2, emb_w);

    conv1_kernel<<<dim3(T_, B_), 256>>>(mel);
    conv2_kernel<<<dim3(T_/4, B_, C1_/8), 256>>>();
    conv3_kernel<<<dim3(T_/4, B_, C3_/8), 128>>>();

    float *pA, *pAc, *pPre, *pWpre, *pBpre;
    cudaGetSymbolAddress((void**)&pA,    g_Amat);
    cudaGetSymbolAddress((void**)&pAc,   g_ac);
    cudaGetSymbolAddress((void**)&pPre,  g_pre);
    cudaGetSymbolAddress((void**)&pWpre, g_Wpre);
    cudaGetSymbolAddress((void**)&pBpre, g_bpre);

    cudaFuncSetAttribute(gemm_tn, cudaFuncAttributeMaxDynamicSharedMemorySize, GSMEM);
    gemm_tn<<<dim3(DC_/BN_, MALL_/BM_), 256, GSMEM>>>(pA, fc_w, fc_b, pAc, MALL_, DC_, FCIN_);
    gemm_tn<<<dim3(G4_/BN_, MALL_/BM_), 256, GSMEM>>>(pAc, pWpre, pBpre, pPre, MALL_, G4_, DC_);

    const int ar_smem = STOT * (int)sizeof(float);  // 232384 B
    cudaFuncSetAttribute(ar_kernel, cudaFuncAttributeMaxDynamicSharedMemorySize, ar_smem);
    ar_kernel<<<NB_AR, 384, ar_smem>>>(post_w, post_b, emb_w, (float*)d_out);
}